// round 4
// baseline (speedup 1.0000x reference)
#include <cuda_runtime.h>
#include <cstdint>

// ---------------------------------------------------------------------------
// Problem constants
// ---------------------------------------------------------------------------
#define BATCH 8
#define CDIM  256
#define NPOS  1024          // H*W
#define NH    16
#define KDIM  16
#define DV    64
#define DH    (NH*DV)       // 1024
#define HID   1024
#define QKV_M 1536          // 256 Q + 256 K + 1024 V rows

// ---------------------------------------------------------------------------
// Scratch (device global). Offsets in floats.
// ---------------------------------------------------------------------------
#define OFF_Y     0u                        // [8,256,1024]
#define OFF_QKV   (OFF_Y    + 2097152u)     // [8,1536,1024]
#define OFF_O     (OFF_QKV  + 12582912u)    // [8,1024,1024]
#define OFF_X2    (OFF_O    + 8388608u)     // [8,256,1024]
#define OFF_Y2    (OFF_X2   + 2097152u)     // [8,256,1024]
#define OFF_H     (OFF_Y2   + 2097152u)     // [8,1024,1024]
#define OFF_VT    (OFF_H    + 8388608u)     // [8,16,1024,64]
#define OFF_WQKV  (OFF_VT   + 8388608u)     // [1536,256]
#define OFF_BQKV  (OFF_WQKV + 393216u)      // [1536]
#define SCRATCH_FLOATS (OFF_BQKV + 1536u)

__device__ float g_buf[SCRATCH_FLOATS];

// ---------------------------------------------------------------------------
// f32x2 helpers
// ---------------------------------------------------------------------------
__device__ __forceinline__ unsigned long long pack2(float x, float y) {
    unsigned long long r;
    asm("mov.b64 %0, {%1, %2};" : "=l"(r) : "f"(x), "f"(y));
    return r;
}
__device__ __forceinline__ void ffma2(unsigned long long &c,
                                      unsigned long long a, unsigned long long b) {
    asm("fma.rn.f32x2 %0, %1, %2, %0;" : "+l"(c) : "l"(a), "l"(b));
}
__device__ __forceinline__ float2 unpack2(unsigned long long v) {
    float2 f;
    asm("mov.b64 {%0, %1}, %2;" : "=f"(f.x), "=f"(f.y) : "l"(v));
    return f;
}

// ---------------------------------------------------------------------------
// Concatenate wq/wk/wv and biases into one [1536,256] weight (once per call)
// ---------------------------------------------------------------------------
__global__ void __launch_bounds__(256) pack_qkv_kernel(
    const float* __restrict__ wq, const float* __restrict__ wk,
    const float* __restrict__ wv, const float* __restrict__ bq,
    const float* __restrict__ bk, const float* __restrict__ bv,
    float* __restrict__ w, float* __restrict__ b)
{
    int row = blockIdx.x, c = threadIdx.x;
    const float* src; const float* bsrc; int r2;
    if (row < 256)      { src = wq; bsrc = bq; r2 = row; }
    else if (row < 512) { src = wk; bsrc = bk; r2 = row - 256; }
    else                { src = wv; bsrc = bv; r2 = row - 512; }
    w[(size_t)row * 256 + c] = src[(size_t)r2 * 256 + c];
    if (c == 0) b[row] = bsrc[r2];
}

// ---------------------------------------------------------------------------
// BatchNorm1d (train stats over (B,N)) + affine, float4-vectorized
// ---------------------------------------------------------------------------
__global__ void __launch_bounds__(256) bn_kernel(
    const float* __restrict__ x, float* __restrict__ y,
    const float* __restrict__ gamma, const float* __restrict__ beta)
{
    const int c = blockIdx.x, tid = threadIdx.x;
    __shared__ float sh[512];

    float s = 0.f, s2 = 0.f;
    for (int idx = tid; idx < BATCH * NPOS / 4; idx += 256) {
        int bb = idx >> 8, n4 = idx & 255;
        float4 v = *(const float4*)&x[((size_t)bb * CDIM + c) * NPOS + n4 * 4];
        s  += v.x + v.y + v.z + v.w;
        s2 += v.x*v.x + v.y*v.y + v.z*v.z + v.w*v.w;
    }
    sh[tid] = s; sh[256 + tid] = s2;
    __syncthreads();
    for (int off = 128; off; off >>= 1) {
        if (tid < off) { sh[tid] += sh[tid+off]; sh[256+tid] += sh[256+tid+off]; }
        __syncthreads();
    }
    const float inv_n = 1.0f / (float)(BATCH * NPOS);
    float mean = sh[0] * inv_n;
    float var  = sh[256] * inv_n - mean * mean;
    float scale = gamma[c] * rsqrtf(var + 1e-5f);
    float shift = beta[c] - mean * scale;

    for (int idx = tid; idx < BATCH * NPOS / 4; idx += 256) {
        int bb = idx >> 8, n4 = idx & 255;
        size_t o = ((size_t)bb * CDIM + c) * NPOS + n4 * 4;
        float4 v = *(const float4*)&x[o];
        v.x = v.x*scale+shift; v.y = v.y*scale+shift;
        v.z = v.z*scale+shift; v.w = v.w*scale+shift;
        *(float4*)&y[o] = v;
    }
}

// ---------------------------------------------------------------------------
// Batched SGEMM with f32x2: out[z] = act(W @ Y[z] + bias) (+ R[z])
// 128x128x8 tiles, 256 threads, 8x8 microtile, double-buffered smem.
// W smem stored value-duplicated so LDS.128 yields {a,a} pairs directly.
// grid = (NN/128, M/128, BATCH)
// ---------------------------------------------------------------------------
template<int RELU6, int ADDRES>
__global__ void __launch_bounds__(256, 2) gemm2_kernel(
    const float* __restrict__ W, const float* __restrict__ Y,
    const float* __restrict__ bias, const float* __restrict__ R,
    float* __restrict__ out, int M, int K, int NN)
{
    __shared__ float Wd[2][8][268];   // [buf][k][2*m dup], 268 pad (16B-aligned rows)
    __shared__ float Ys[2][8][128];   // [buf][k][n]

    const int tid = threadIdx.x;
    const int tx = tid & 15, ty = tid >> 4;
    const int n0 = blockIdx.x * 128, m0 = blockIdx.y * 128;
    const float* Yb = Y + (size_t)blockIdx.z * K * NN;
    const size_t zO = (size_t)blockIdx.z * M * NN;

    const int wm = tid >> 1;            // 0..127 (m within tile)
    const int wk = (tid & 1) * 4;       // 0 or 4 (k offset)
    const int yk = tid >> 5;            // 0..7
    const int yn = (tid & 31) * 4;      // 0..124

    const float* wp = W  + (size_t)(m0 + wm) * K + wk;
    const float* yp = Yb + (size_t)yk * NN + n0 + yn;

    unsigned long long acc[8][4];
    #pragma unroll
    for (int i = 0; i < 8; ++i)
        #pragma unroll
        for (int j = 0; j < 4; ++j) acc[i][j] = 0ull;

    // prologue: tile 0 into buf 0
    {
        float4 wr = *(const float4*)wp;
        float4 yr = *(const float4*)yp;
        *(float2*)&Wd[0][wk+0][2*wm] = make_float2(wr.x, wr.x);
        *(float2*)&Wd[0][wk+1][2*wm] = make_float2(wr.y, wr.y);
        *(float2*)&Wd[0][wk+2][2*wm] = make_float2(wr.z, wr.z);
        *(float2*)&Wd[0][wk+3][2*wm] = make_float2(wr.w, wr.w);
        *(float4*)&Ys[0][yk][yn] = yr;
    }
    __syncthreads();

    const int ntiles = K >> 3;
    int buf = 0;
    for (int t = 0; t < ntiles; ++t) {
        float4 wr, yr;
        const bool more = (t + 1 < ntiles);
        if (more) {
            wr = *(const float4*)(wp + (t + 1) * 8);
            yr = *(const float4*)(yp + (size_t)(t + 1) * 8 * NN);
        }
        #pragma unroll
        for (int kk = 0; kk < 8; ++kk) {
            ulonglong2 a01 = *(const ulonglong2*)&Wd[buf][kk][ty*16];
            ulonglong2 a23 = *(const ulonglong2*)&Wd[buf][kk][ty*16+4];
            ulonglong2 a45 = *(const ulonglong2*)&Wd[buf][kk][ty*16+8];
            ulonglong2 a67 = *(const ulonglong2*)&Wd[buf][kk][ty*16+12];
            ulonglong2 b01 = *(const ulonglong2*)&Ys[buf][kk][tx*8];
            ulonglong2 b23 = *(const ulonglong2*)&Ys[buf][kk][tx*8+4];
            unsigned long long av[8] = {a01.x, a01.y, a23.x, a23.y,
                                        a45.x, a45.y, a67.x, a67.y};
            #pragma unroll
            for (int i = 0; i < 8; ++i) {
                ffma2(acc[i][0], av[i], b01.x);
                ffma2(acc[i][1], av[i], b01.y);
                ffma2(acc[i][2], av[i], b23.x);
                ffma2(acc[i][3], av[i], b23.y);
            }
        }
        if (more) {
            int nb = buf ^ 1;
            *(float2*)&Wd[nb][wk+0][2*wm] = make_float2(wr.x, wr.x);
            *(float2*)&Wd[nb][wk+1][2*wm] = make_float2(wr.y, wr.y);
            *(float2*)&Wd[nb][wk+2][2*wm] = make_float2(wr.z, wr.z);
            *(float2*)&Wd[nb][wk+3][2*wm] = make_float2(wr.w, wr.w);
            *(float4*)&Ys[nb][yk][yn] = yr;
        }
        __syncthreads();
        buf ^= 1;
    }

    // epilogue
    #pragma unroll
    for (int i = 0; i < 8; ++i) {
        int m = m0 + ty * 8 + i;
        float bv = bias[m];
        float o[8];
        float2 u;
        u = unpack2(acc[i][0]); o[0] = u.x + bv; o[1] = u.y + bv;
        u = unpack2(acc[i][1]); o[2] = u.x + bv; o[3] = u.y + bv;
        u = unpack2(acc[i][2]); o[4] = u.x + bv; o[5] = u.y + bv;
        u = unpack2(acc[i][3]); o[6] = u.x + bv; o[7] = u.y + bv;
        if (RELU6) {
            #pragma unroll
            for (int j = 0; j < 8; ++j) o[j] = fminf(fmaxf(o[j], 0.f), 6.f);
        }
        size_t orow = zO + (size_t)m * NN + n0 + tx * 8;
        if (ADDRES) {
            float4 r0 = *(const float4*)&R[orow];
            float4 r1 = *(const float4*)&R[orow + 4];
            o[0]+=r0.x; o[1]+=r0.y; o[2]+=r0.z; o[3]+=r0.w;
            o[4]+=r1.x; o[5]+=r1.y; o[6]+=r1.z; o[7]+=r1.w;
        }
        *(float4*)&out[orow]     = make_float4(o[0], o[1], o[2], o[3]);
        *(float4*)&out[orow + 4] = make_float4(o[4], o[5], o[6], o[7]);
    }
}

// ---------------------------------------------------------------------------
// Transpose V slice of QKV: [b][h*64+d][m] -> Vt[b][h][m][d]  (coalesced both ways)
// grid = (NPOS/32, DV/32, BATCH*NH), 256 threads
// ---------------------------------------------------------------------------
__global__ void __launch_bounds__(256) transpose_v_kernel(
    const float* __restrict__ qkv, float* __restrict__ vt)
{
    __shared__ float tile[32][33];
    const int bh = blockIdx.z;
    const int b = bh >> 4, h = bh & 15;
    const float* src = qkv + ((size_t)b * QKV_M + 512 + h * DV) * NPOS;
    float* dst = vt + (size_t)bh * NPOS * DV;
    const int m0 = blockIdx.x * 32, d0 = blockIdx.y * 32;
    const int tx = threadIdx.x & 31, ty0 = threadIdx.x >> 5;

    #pragma unroll
    for (int ty = ty0; ty < 32; ty += 8)
        tile[ty][tx] = src[(size_t)(d0 + ty) * NPOS + m0 + tx];
    __syncthreads();
    #pragma unroll
    for (int ty = ty0; ty < 32; ty += 8)
        dst[(size_t)(m0 + ty) * DV + d0 + tx] = tile[tx][ty];
}

// ---------------------------------------------------------------------------
// Fused attention with f32x2.
// Block: one (b, h, 64-row tile); thread (r = tid>>2, dg = tid&3).
// QK: q pre-packed {q,q}; PV: transposed V tiles [m][d], thread owns 16
// contiguous d (8 f32x2 accumulators), V LDS.128 4-way broadcast across rows.
// ---------------------------------------------------------------------------
#define ATT_SMEM_FLOATS (16*132 + 64*132 + 128*68)   // Ks + Ss + Vs = 19264

__global__ void __launch_bounds__(256) attn2_kernel(
    const float* __restrict__ qkv, const float* __restrict__ vt,
    float* __restrict__ ob)
{
    extern __shared__ float sm[];
    float* Ks = sm;                   // [16][132]
    float* Ss = Ks + 16 * 132;        // [64][132]
    float* Vs = Ss + 64 * 132;        // [128][68]  (m-major, d cols)

    const int tid = threadIdx.x;
    const int r  = tid >> 2;          // 0..63
    const int dg = tid & 3;           // 0..3
    const int h  = blockIdx.y;
    const int r0 = blockIdx.x * 64;
    const int bz = blockIdx.z;

    const float* bbase = qkv + (size_t)bz * QKV_M * NPOS;
    const float* qh = bbase + (size_t)(h * KDIM) * NPOS;
    const float* kh = bbase + (size_t)(256 + h * KDIM) * NPOS;
    const float* vth = vt + (size_t)(bz * NH + h) * NPOS * DV;
    const size_t baseO = (size_t)(bz * DH + h * DV) * NPOS;

    // q row, scale sqrt(kd)=4 folded, packed {q,q}
    unsigned long long qq[16];
    #pragma unroll
    for (int kd = 0; kd < 16; ++kd) {
        float q = qh[(size_t)kd * NPOS + r0 + r] * 4.0f;
        qq[kd] = pack2(q, q);
    }

    unsigned long long facc[8];
    #pragma unroll
    for (int j = 0; j < 8; ++j) facc[j] = 0ull;
    float ssum = 0.f;
    const int dlo = dg * 16;

    for (int t = 0; t < 8; ++t) {
        const int m0 = t * 128;
        __syncthreads();
        // K tile: [16][128] float4 loads
        for (int idx = tid; idx < 16 * 32; idx += 256) {
            int kd = idx >> 5, mq = idx & 31;
            float4 v = *(const float4*)&kh[(size_t)kd * NPOS + m0 + mq * 4];
            *(float4*)&Ks[kd * 132 + mq * 4] = v;
        }
        // V tile (pre-transposed): [128][64] float4 loads
        for (int idx = tid; idx < 128 * 16; idx += 256) {
            int mm = idx >> 4, dq = idx & 15;
            float4 v = *(const float4*)&vth[(size_t)(m0 + mm) * DV + dq * 4];
            *(float4*)&Vs[mm * 68 + dq * 4] = v;
        }
        __syncthreads();

        // QK + exp: thread's 32 columns (mm4 = i*4 + dg), f32x2 over col pairs
        #pragma unroll
        for (int i = 0; i < 8; ++i) {
            int mm4 = i * 4 + dg;
            unsigned long long s01 = 0ull, s23 = 0ull;
            #pragma unroll
            for (int kd = 0; kd < 16; ++kd) {
                ulonglong2 kp = *(const ulonglong2*)&Ks[kd * 132 + mm4 * 4];
                ffma2(s01, qq[kd], kp.x);
                ffma2(s23, qq[kd], kp.y);
            }
            float2 e0 = unpack2(s01), e1 = unpack2(s23);
            float4 p;
            p.x = __expf(e0.x); p.y = __expf(e0.y);
            p.z = __expf(e1.x); p.w = __expf(e1.y);
            ssum += p.x + p.y + p.z + p.w;
            *(float4*)&Ss[r * 132 + mm4 * 4] = p;
        }
        __syncthreads();

        // PV: loop all 128 m, 8 f32x2 accumulators over d pairs
        #pragma unroll 2
        for (int mm0 = 0; mm0 < 128; mm0 += 4) {
            float4 p4 = *(const float4*)&Ss[r * 132 + mm0];
            float pv[4] = {p4.x, p4.y, p4.z, p4.w};
            #pragma unroll
            for (int j = 0; j < 4; ++j) {
                unsigned long long pp = pack2(pv[j], pv[j]);
                const float* vrow = &Vs[(mm0 + j) * 68 + dlo];
                ulonglong2 v01 = *(const ulonglong2*)(vrow);
                ulonglong2 v23 = *(const ulonglong2*)(vrow + 4);
                ulonglong2 v45 = *(const ulonglong2*)(vrow + 8);
                ulonglong2 v67 = *(const ulonglong2*)(vrow + 12);
                ffma2(facc[0], pp, v01.x); ffma2(facc[1], pp, v01.y);
                ffma2(facc[2], pp, v23.x); ffma2(facc[3], pp, v23.y);
                ffma2(facc[4], pp, v45.x); ffma2(facc[5], pp, v45.y);
                ffma2(facc[6], pp, v67.x); ffma2(facc[7], pp, v67.y);
            }
        }
    }

    // row softmax sum across the quad owning row r
    ssum += __shfl_xor_sync(0xffffffffu, ssum, 1);
    ssum += __shfl_xor_sync(0xffffffffu, ssum, 2);
    float inv = 1.0f / ssum;

    #pragma unroll
    for (int j = 0; j < 8; ++j) {
        float2 f = unpack2(facc[j]);
        int d = dlo + 2 * j;
        ob[baseO + (size_t)d * NPOS + r0 + r]       = f.x * inv;
        ob[baseO + (size_t)(d + 1) * NPOS + r0 + r] = f.y * inv;
    }
}

// ---------------------------------------------------------------------------
// Launch
// ---------------------------------------------------------------------------
extern "C" void kernel_launch(void* const* d_in, const int* in_sizes, int n_in,
                              void* d_out, int out_size)
{
    (void)in_sizes; (void)n_in; (void)out_size;
    const float* x   = (const float*)d_in[0];
    const float* g1  = (const float*)d_in[1];
    const float* b1  = (const float*)d_in[2];
    const float* wq  = (const float*)d_in[3];
    const float* bq  = (const float*)d_in[4];
    const float* wk  = (const float*)d_in[5];
    const float* bk  = (const float*)d_in[6];
    const float* wv  = (const float*)d_in[7];
    const float* bv  = (const float*)d_in[8];
    const float* wp  = (const float*)d_in[9];
    const float* bp  = (const float*)d_in[10];
    const float* g2  = (const float*)d_in[11];
    const float* b2  = (const float*)d_in[12];
    const float* w1  = (const float*)d_in[13];
    const float* bb1 = (const float*)d_in[14];
    const float* w2  = (const float*)d_in[15];
    const float* bb2 = (const float*)d_in[16];
    float* out = (float*)d_out;

    float* base = nullptr;
    cudaGetSymbolAddress((void**)&base, g_buf);
    float* Yb   = base + OFF_Y;
    float* QKVb = base + OFF_QKV;
    float* Ob   = base + OFF_O;
    float* X2b  = base + OFF_X2;
    float* Y2b  = base + OFF_Y2;
    float* Hb   = base + OFF_H;
    float* VTb  = base + OFF_VT;
    float* Wqkv = base + OFF_WQKV;
    float* Bqkv = base + OFF_BQKV;

    cudaFuncSetAttribute(attn2_kernel, cudaFuncAttributeMaxDynamicSharedMemorySize,
                         ATT_SMEM_FLOATS * (int)sizeof(float));

    // 0) weight concat (cheap, deterministic)
    pack_qkv_kernel<<<QKV_M, 256>>>(wq, wk, wv, bq, bk, bv, Wqkv, Bqkv);

    // 1) BN1
    bn_kernel<<<CDIM, 256>>>(x, Yb, g1, b1);

    // 2) fused QKV projection: [1536,256] @ [256,1024]
    gemm2_kernel<0,0><<<dim3(NPOS/128, QKV_M/128, BATCH), 256>>>(
        Wqkv, Yb, Bqkv, nullptr, QKVb, QKV_M, CDIM, NPOS);

    // 3) transpose V for the PV stage
    transpose_v_kernel<<<dim3(NPOS/32, DV/32, BATCH*NH), 256>>>(QKVb, VTb);

    // 4) attention
    attn2_kernel<<<dim3(NPOS/64, NH, BATCH), 256, ATT_SMEM_FLOATS * sizeof(float)>>>(
        QKVb, VTb, Ob);

    // 5) projection + residual(x)
    gemm2_kernel<0,1><<<dim3(NPOS/128, CDIM/128, BATCH), 256>>>(
        wp, Ob, bp, x, X2b, CDIM, DH, NPOS);

    // 6) BN2
    bn_kernel<<<CDIM, 256>>>(X2b, Y2b, g2, b2);

    // 7) MLP
    gemm2_kernel<1,0><<<dim3(NPOS/128, HID/128, BATCH), 256>>>(
        w1, Y2b, bb1, nullptr, Hb, HID, CDIM, NPOS);
    gemm2_kernel<0,1><<<dim3(NPOS/128, CDIM/128, BATCH), 256>>>(
        w2, Hb, bb2, X2b, out, CDIM, HID, NPOS);
}

// round 5
// speedup vs baseline: 1.5226x; 1.5226x over previous
#include <cuda_runtime.h>
#include <cstdint>

// ---------------------------------------------------------------------------
// Problem constants
// ---------------------------------------------------------------------------
#define BATCH 8
#define CDIM  256
#define NPOS  1024
#define NH    16
#define KDIM  16
#define DV    64
#define DH    (NH*DV)       // 1024
#define HID   1024
#define QKV_M 1536

// ---------------------------------------------------------------------------
// Scratch (device global). Offsets in floats.
// ---------------------------------------------------------------------------
#define OFF_Y     0u                        // [8,256,1024]
#define OFF_QKV   (OFF_Y    + 2097152u)     // [8,1536,1024]
#define OFF_O     (OFF_QKV  + 12582912u)    // [8,1024,1024]
#define OFF_X2    (OFF_O    + 8388608u)     // [8,256,1024]
#define OFF_Y2    (OFF_X2   + 2097152u)     // [8,256,1024]
#define OFF_H     (OFF_Y2   + 2097152u)     // [8,1024,1024]
#define OFF_WQKV  (OFF_H    + 8388608u)     // [1536,256]
#define OFF_BQKV  (OFF_WQKV + 393216u)      // [1536]
#define SCRATCH_FLOATS (OFF_BQKV + 1536u)

__device__ float g_buf[SCRATCH_FLOATS];

// ---------------------------------------------------------------------------
// Concatenate wq/wk/wv (+biases) into one [1536,256] weight
// ---------------------------------------------------------------------------
__global__ void __launch_bounds__(256) pack_qkv_kernel(
    const float* __restrict__ wq, const float* __restrict__ wk,
    const float* __restrict__ wv, const float* __restrict__ bq,
    const float* __restrict__ bk, const float* __restrict__ bv,
    float* __restrict__ w, float* __restrict__ b)
{
    int row = blockIdx.x, c = threadIdx.x;
    const float* src; const float* bsrc; int r2;
    if (row < 256)      { src = wq; bsrc = bq; r2 = row; }
    else if (row < 512) { src = wk; bsrc = bk; r2 = row - 256; }
    else                { src = wv; bsrc = bv; r2 = row - 512; }
    w[(size_t)row * 256 + c] = src[(size_t)r2 * 256 + c];
    if (c == 0) b[row] = bsrc[r2];
}

// ---------------------------------------------------------------------------
// BatchNorm1d (train stats over (B,N)) + affine, float4-vectorized
// ---------------------------------------------------------------------------
__global__ void __launch_bounds__(256) bn_kernel(
    const float* __restrict__ x, float* __restrict__ y,
    const float* __restrict__ gamma, const float* __restrict__ beta)
{
    const int c = blockIdx.x, tid = threadIdx.x;
    __shared__ float sh[512];

    float s = 0.f, s2 = 0.f;
    for (int idx = tid; idx < BATCH * NPOS / 4; idx += 256) {
        int bb = idx >> 8, n4 = idx & 255;
        float4 v = *(const float4*)&x[((size_t)bb * CDIM + c) * NPOS + n4 * 4];
        s  += v.x + v.y + v.z + v.w;
        s2 += v.x*v.x + v.y*v.y + v.z*v.z + v.w*v.w;
    }
    sh[tid] = s; sh[256 + tid] = s2;
    __syncthreads();
    for (int off = 128; off; off >>= 1) {
        if (tid < off) { sh[tid] += sh[tid+off]; sh[256+tid] += sh[256+tid+off]; }
        __syncthreads();
    }
    const float inv_n = 1.0f / (float)(BATCH * NPOS);
    float mean = sh[0] * inv_n;
    float var  = sh[256] * inv_n - mean * mean;
    float scale = gamma[c] * rsqrtf(var + 1e-5f);
    float shift = beta[c] - mean * scale;

    for (int idx = tid; idx < BATCH * NPOS / 4; idx += 256) {
        int bb = idx >> 8, n4 = idx & 255;
        size_t o = ((size_t)bb * CDIM + c) * NPOS + n4 * 4;
        float4 v = *(const float4*)&x[o];
        v.x = v.x*scale+shift; v.y = v.y*scale+shift;
        v.z = v.z*scale+shift; v.w = v.w*scale+shift;
        *(float4*)&y[o] = v;
    }
}

// ---------------------------------------------------------------------------
// gemmL: 128x128x16 tiles, 256 threads, 8x8 scalar microtile, double-buffered.
// out[z][m][n] = act(sum_k W[m][k]*Y[z][k][n] + bias[m]) (+R)
// grid = (NN/128, M/128, BATCH)
// ---------------------------------------------------------------------------
template<int RELU6, int ADDRES>
__global__ void __launch_bounds__(256) gemmL_kernel(
    const float* __restrict__ W, const float* __restrict__ Y,
    const float* __restrict__ bias, const float* __restrict__ R,
    float* __restrict__ out, int M, int K, int NN)
{
    __shared__ float Ws[2][16][132];
    __shared__ float Ys[2][16][132];

    const int tid = threadIdx.x;
    const int tx = tid & 15, ty = tid >> 4;
    const int n0 = blockIdx.x * 128, m0 = blockIdx.y * 128;
    const float* Yb = Y + (size_t)blockIdx.z * K * NN;
    const size_t zO = (size_t)blockIdx.z * M * NN;

    const int wm = tid >> 1, wk = (tid & 1) * 8;       // W: row wm, k-chunk of 8
    const int yk = tid >> 4, yn = (tid & 15) * 8;      // Y: row yk, n-chunk of 8

    const float* wp = W  + (size_t)(m0 + wm) * K + wk;
    const float* yp = Yb + (size_t)yk * NN + n0 + yn;

    float acc[8][8];
    #pragma unroll
    for (int i = 0; i < 8; ++i)
        #pragma unroll
        for (int j = 0; j < 8; ++j) acc[i][j] = 0.f;

    // prologue
    {
        float4 w0 = *(const float4*)wp;
        float4 w1 = *(const float4*)(wp + 4);
        float4 y0 = *(const float4*)yp;
        float4 y1 = *(const float4*)(yp + 4);
        Ws[0][wk+0][wm] = w0.x; Ws[0][wk+1][wm] = w0.y;
        Ws[0][wk+2][wm] = w0.z; Ws[0][wk+3][wm] = w0.w;
        Ws[0][wk+4][wm] = w1.x; Ws[0][wk+5][wm] = w1.y;
        Ws[0][wk+6][wm] = w1.z; Ws[0][wk+7][wm] = w1.w;
        *(float4*)&Ys[0][yk][yn]     = y0;
        *(float4*)&Ys[0][yk][yn + 4] = y1;
    }
    __syncthreads();

    const int ntiles = K >> 4;
    int buf = 0;
    for (int t = 0; t < ntiles; ++t) {
        float4 w0, w1, y0, y1;
        const bool more = (t + 1 < ntiles);
        if (more) {
            w0 = *(const float4*)(wp + (t + 1) * 16);
            w1 = *(const float4*)(wp + (t + 1) * 16 + 4);
            y0 = *(const float4*)(yp + (size_t)(t + 1) * 16 * NN);
            y1 = *(const float4*)(yp + (size_t)(t + 1) * 16 * NN + 4);
        }
        #pragma unroll
        for (int kk = 0; kk < 16; ++kk) {
            float4 a0 = *(const float4*)&Ws[buf][kk][ty * 8];
            float4 a1 = *(const float4*)&Ws[buf][kk][ty * 8 + 4];
            float4 b0 = *(const float4*)&Ys[buf][kk][tx * 8];
            float4 b1 = *(const float4*)&Ys[buf][kk][tx * 8 + 4];
            float a[8] = {a0.x,a0.y,a0.z,a0.w,a1.x,a1.y,a1.z,a1.w};
            float b[8] = {b0.x,b0.y,b0.z,b0.w,b1.x,b1.y,b1.z,b1.w};
            #pragma unroll
            for (int i = 0; i < 8; ++i)
                #pragma unroll
                for (int j = 0; j < 8; ++j)
                    acc[i][j] += a[i] * b[j];
        }
        if (more) {
            int nb = buf ^ 1;
            Ws[nb][wk+0][wm] = w0.x; Ws[nb][wk+1][wm] = w0.y;
            Ws[nb][wk+2][wm] = w0.z; Ws[nb][wk+3][wm] = w0.w;
            Ws[nb][wk+4][wm] = w1.x; Ws[nb][wk+5][wm] = w1.y;
            Ws[nb][wk+6][wm] = w1.z; Ws[nb][wk+7][wm] = w1.w;
            *(float4*)&Ys[nb][yk][yn]     = y0;
            *(float4*)&Ys[nb][yk][yn + 4] = y1;
        }
        __syncthreads();
        buf ^= 1;
    }

    #pragma unroll
    for (int i = 0; i < 8; ++i) {
        int m = m0 + ty * 8 + i;
        float bv = bias[m];
        float o[8];
        #pragma unroll
        for (int j = 0; j < 8; ++j) o[j] = acc[i][j] + bv;
        if (RELU6) {
            #pragma unroll
            for (int j = 0; j < 8; ++j) o[j] = fminf(fmaxf(o[j], 0.f), 6.f);
        }
        size_t orow = zO + (size_t)m * NN + n0 + tx * 8;
        if (ADDRES) {
            float4 r0 = *(const float4*)&R[orow];
            float4 r1 = *(const float4*)&R[orow + 4];
            o[0]+=r0.x; o[1]+=r0.y; o[2]+=r0.z; o[3]+=r0.w;
            o[4]+=r1.x; o[5]+=r1.y; o[6]+=r1.z; o[7]+=r1.w;
        }
        *(float4*)&out[orow]     = make_float4(o[0],o[1],o[2],o[3]);
        *(float4*)&out[orow + 4] = make_float4(o[4],o[5],o[6],o[7]);
    }
}

// ---------------------------------------------------------------------------
// gemmS: 64x128x16 tiles, 256 threads, 4x8 microtile, double-buffered.
// For M=256 GEMMs (proj, mlp2): 256 blocks -> better wave balance.
// grid = (NN/128, M/64, BATCH)
// ---------------------------------------------------------------------------
template<int RELU6, int ADDRES>
__global__ void __launch_bounds__(256) gemmS_kernel(
    const float* __restrict__ W, const float* __restrict__ Y,
    const float* __restrict__ bias, const float* __restrict__ R,
    float* __restrict__ out, int M, int K, int NN)
{
    __shared__ float Ws[2][16][68];
    __shared__ float Ys[2][16][132];

    const int tid = threadIdx.x;
    const int tx = tid & 15, ty = tid >> 4;
    const int n0 = blockIdx.x * 128, m0 = blockIdx.y * 64;
    const float* Yb = Y + (size_t)blockIdx.z * K * NN;
    const size_t zO = (size_t)blockIdx.z * M * NN;

    const int wm = tid & 63, wk = (tid >> 6) * 4;      // W: row wm, k-chunk of 4
    const int yk = tid >> 4, yn = (tid & 15) * 8;

    const float* wp = W  + (size_t)(m0 + wm) * K + wk;
    const float* yp = Yb + (size_t)yk * NN + n0 + yn;

    float acc[4][8];
    #pragma unroll
    for (int i = 0; i < 4; ++i)
        #pragma unroll
        for (int j = 0; j < 8; ++j) acc[i][j] = 0.f;

    {
        float4 w0 = *(const float4*)wp;
        float4 y0 = *(const float4*)yp;
        float4 y1 = *(const float4*)(yp + 4);
        Ws[0][wk+0][wm] = w0.x; Ws[0][wk+1][wm] = w0.y;
        Ws[0][wk+2][wm] = w0.z; Ws[0][wk+3][wm] = w0.w;
        *(float4*)&Ys[0][yk][yn]     = y0;
        *(float4*)&Ys[0][yk][yn + 4] = y1;
    }
    __syncthreads();

    const int ntiles = K >> 4;
    int buf = 0;
    for (int t = 0; t < ntiles; ++t) {
        float4 w0, y0, y1;
        const bool more = (t + 1 < ntiles);
        if (more) {
            w0 = *(const float4*)(wp + (t + 1) * 16);
            y0 = *(const float4*)(yp + (size_t)(t + 1) * 16 * NN);
            y1 = *(const float4*)(yp + (size_t)(t + 1) * 16 * NN + 4);
        }
        #pragma unroll
        for (int kk = 0; kk < 16; ++kk) {
            float4 a0 = *(const float4*)&Ws[buf][kk][ty * 4];
            float4 b0 = *(const float4*)&Ys[buf][kk][tx * 8];
            float4 b1 = *(const float4*)&Ys[buf][kk][tx * 8 + 4];
            float a[4] = {a0.x,a0.y,a0.z,a0.w};
            float b[8] = {b0.x,b0.y,b0.z,b0.w,b1.x,b1.y,b1.z,b1.w};
            #pragma unroll
            for (int i = 0; i < 4; ++i)
                #pragma unroll
                for (int j = 0; j < 8; ++j)
                    acc[i][j] += a[i] * b[j];
        }
        if (more) {
            int nb = buf ^ 1;
            Ws[nb][wk+0][wm] = w0.x; Ws[nb][wk+1][wm] = w0.y;
            Ws[nb][wk+2][wm] = w0.z; Ws[nb][wk+3][wm] = w0.w;
            *(float4*)&Ys[nb][yk][yn]     = y0;
            *(float4*)&Ys[nb][yk][yn + 4] = y1;
        }
        __syncthreads();
        buf ^= 1;
    }

    #pragma unroll
    for (int i = 0; i < 4; ++i) {
        int m = m0 + ty * 4 + i;
        float bv = bias[m];
        float o[8];
        #pragma unroll
        for (int j = 0; j < 8; ++j) o[j] = acc[i][j] + bv;
        if (RELU6) {
            #pragma unroll
            for (int j = 0; j < 8; ++j) o[j] = fminf(fmaxf(o[j], 0.f), 6.f);
        }
        size_t orow = zO + (size_t)m * NN + n0 + tx * 8;
        if (ADDRES) {
            float4 r0 = *(const float4*)&R[orow];
            float4 r1 = *(const float4*)&R[orow + 4];
            o[0]+=r0.x; o[1]+=r0.y; o[2]+=r0.z; o[3]+=r0.w;
            o[4]+=r1.x; o[5]+=r1.y; o[6]+=r1.z; o[7]+=r1.w;
        }
        *(float4*)&out[orow]     = make_float4(o[0],o[1],o[2],o[3]);
        *(float4*)&out[orow + 4] = make_float4(o[4],o[5],o[6],o[7]);
    }
}

// ---------------------------------------------------------------------------
// Fused attention (R0 design, proven). One block per (b, h, 64-row tile).
// Q/K rows and V rows read directly from the fused QKV buffer.
// ---------------------------------------------------------------------------
#define ATT_SMEM_FLOATS (16*132 + 64*132 + 64*132)

__global__ void __launch_bounds__(256) attn_kernel(
    const float* __restrict__ qkv, float* __restrict__ ob)
{
    extern __shared__ float sm[];
    float* Ks = sm;                 // 16*132
    float* Vs = Ks + 16 * 132;      // 64*132
    float* Ss = Vs + 64 * 132;      // 64*132

    const int tid = threadIdx.x;
    const int r   = tid >> 2;
    const int dg  = tid & 3;
    const int h   = blockIdx.y;
    const int r0  = blockIdx.x * 64;
    const int bz  = blockIdx.z;

    const float* bbase = qkv + (size_t)bz * QKV_M * NPOS;
    const float* qh = bbase + (size_t)(h * KDIM) * NPOS;
    const float* kh = bbase + (size_t)(256 + h * KDIM) * NPOS;
    const float* vh = bbase + (size_t)(512 + h * DV) * NPOS;
    const size_t baseO = (size_t)(bz * DH + h * DV) * NPOS;

    float ql[16];
    #pragma unroll
    for (int kd = 0; kd < 16; ++kd)
        ql[kd] = qh[(size_t)kd * NPOS + r0 + r] * 4.0f;

    float f[16];
    #pragma unroll
    for (int dd = 0; dd < 16; ++dd) f[dd] = 0.f;
    float ssum = 0.f;

    for (int t = 0; t < 8; ++t) {
        const int m0 = t * 128;
        __syncthreads();
        for (int idx = tid; idx < 16 * 32; idx += 256) {
            int kd = idx >> 5, mq = idx & 31;
            float4 v = *(const float4*)&kh[(size_t)kd * NPOS + m0 + mq * 4];
            *(float4*)&Ks[kd * 132 + mq * 4] = v;
        }
        for (int idx = tid; idx < 64 * 32; idx += 256) {
            int d = idx >> 5, mq = idx & 31;
            float4 v = *(const float4*)&vh[(size_t)d * NPOS + m0 + mq * 4];
            *(float4*)&Vs[d * 132 + mq * 4] = v;
        }
        __syncthreads();

        #pragma unroll
        for (int i = 0; i < 8; ++i) {
            int mm4 = i * 4 + dg;
            float4 a = {0.f, 0.f, 0.f, 0.f};
            #pragma unroll
            for (int kd = 0; kd < 16; ++kd) {
                float4 kv = *(const float4*)&Ks[kd * 132 + mm4 * 4];
                a.x += ql[kd] * kv.x; a.y += ql[kd] * kv.y;
                a.z += ql[kd] * kv.z; a.w += ql[kd] * kv.w;
            }
            float4 p;
            p.x = __expf(a.x); p.y = __expf(a.y);
            p.z = __expf(a.z); p.w = __expf(a.w);
            ssum += p.x + p.y + p.z + p.w;
            *(float4*)&Ss[r * 132 + mm4 * 4] = p;
        }
        __syncthreads();

        #pragma unroll 4
        for (int mm4 = 0; mm4 < 32; ++mm4) {
            float4 p4 = *(const float4*)&Ss[r * 132 + mm4 * 4];
            #pragma unroll
            for (int dd = 0; dd < 16; ++dd) {
                int d = dg + dd * 4;
                float4 v4 = *(const float4*)&Vs[d * 132 + mm4 * 4];
                f[dd] += p4.x * v4.x + p4.y * v4.y + p4.z * v4.z + p4.w * v4.w;
            }
        }
    }

    ssum += __shfl_xor_sync(0xffffffffu, ssum, 1);
    ssum += __shfl_xor_sync(0xffffffffu, ssum, 2);
    float inv = 1.0f / ssum;

    #pragma unroll
    for (int dd = 0; dd < 16; ++dd) {
        int d = dg + dd * 4;
        ob[baseO + (size_t)d * NPOS + r0 + r] = f[dd] * inv;
    }
}

// ---------------------------------------------------------------------------
// Launch
// ---------------------------------------------------------------------------
extern "C" void kernel_launch(void* const* d_in, const int* in_sizes, int n_in,
                              void* d_out, int out_size)
{
    (void)in_sizes; (void)n_in; (void)out_size;
    const float* x   = (const float*)d_in[0];
    const float* g1  = (const float*)d_in[1];
    const float* b1  = (const float*)d_in[2];
    const float* wq  = (const float*)d_in[3];
    const float* bq  = (const float*)d_in[4];
    const float* wk  = (const float*)d_in[5];
    const float* bk  = (const float*)d_in[6];
    const float* wv  = (const float*)d_in[7];
    const float* bv  = (const float*)d_in[8];
    const float* wp  = (const float*)d_in[9];
    const float* bp  = (const float*)d_in[10];
    const float* g2  = (const float*)d_in[11];
    const float* b2  = (const float*)d_in[12];
    const float* w1  = (const float*)d_in[13];
    const float* bb1 = (const float*)d_in[14];
    const float* w2  = (const float*)d_in[15];
    const float* bb2 = (const float*)d_in[16];
    float* out = (float*)d_out;

    float* base = nullptr;
    cudaGetSymbolAddress((void**)&base, g_buf);
    float* Yb   = base + OFF_Y;
    float* QKVb = base + OFF_QKV;
    float* Ob   = base + OFF_O;
    float* X2b  = base + OFF_X2;
    float* Y2b  = base + OFF_Y2;
    float* Hb   = base + OFF_H;
    float* Wqkv = base + OFF_WQKV;
    float* Bqkv = base + OFF_BQKV;

    cudaFuncSetAttribute(attn_kernel, cudaFuncAttributeMaxDynamicSharedMemorySize,
                         ATT_SMEM_FLOATS * (int)sizeof(float));

    // 0) weight concat
    pack_qkv_kernel<<<QKV_M, 256>>>(wq, wk, wv, bq, bk, bv, Wqkv, Bqkv);

    // 1) BN1
    bn_kernel<<<CDIM, 256>>>(x, Yb, g1, b1);

    // 2) fused QKV projection
    gemmL_kernel<0,0><<<dim3(NPOS/128, QKV_M/128, BATCH), 256>>>(
        Wqkv, Yb, Bqkv, nullptr, QKVb, QKV_M, CDIM, NPOS);

    // 3) attention
    attn_kernel<<<dim3(NPOS/64, NH, BATCH), 256, ATT_SMEM_FLOATS * sizeof(float)>>>(
        QKVb, Ob);

    // 4) projection + residual(x)
    gemmS_kernel<0,1><<<dim3(NPOS/128, CDIM/64, BATCH), 256>>>(
        wp, Ob, bp, x, X2b, CDIM, DH, NPOS);

    // 5) BN2
    bn_kernel<<<CDIM, 256>>>(X2b, Y2b, g2, b2);

    // 6) MLP
    gemmL_kernel<1,0><<<dim3(NPOS/128, HID/128, BATCH), 256>>>(
        w1, Y2b, bb1, nullptr, Hb, HID, CDIM, NPOS);
    gemmS_kernel<0,1><<<dim3(NPOS/128, CDIM/64, BATCH), 256>>>(
        w2, Hb, bb2, X2b, out, CDIM, HID, NPOS);
}

// round 7
// speedup vs baseline: 2.0786x; 1.3651x over previous
#include <cuda_runtime.h>
#include <cstdint>

// ---------------------------------------------------------------------------
// Problem constants
// ---------------------------------------------------------------------------
#define BATCH 8
#define CDIM  256
#define NPOS  1024
#define NH    16
#define KDIM  16
#define DV    64
#define DH    (NH*DV)       // 1024
#define HID   1024
#define QKV_M 1536

// ---------------------------------------------------------------------------
// Scratch (device global). Offsets in floats.
// ---------------------------------------------------------------------------
#define OFF_Y     0u                        // [8,256,1024]
#define OFF_QKV   (OFF_Y    + 2097152u)     // [8,1536,1024]
#define OFF_O     (OFF_QKV  + 12582912u)    // [8,1024,1024]
#define OFF_X2    (OFF_O    + 8388608u)     // [8,256,1024]
#define OFF_Y2    (OFF_X2   + 2097152u)     // [8,256,1024]
#define OFF_H     (OFF_Y2   + 2097152u)     // [8,1024,1024]
#define OFF_WQKV  (OFF_H    + 8388608u)     // [1536,256]
#define OFF_BQKV  (OFF_WQKV + 393216u)      // [1536]
#define SCRATCH_FLOATS (OFF_BQKV + 1536u)

__device__ float g_buf[SCRATCH_FLOATS];

// ---------------------------------------------------------------------------
// Concatenate wq/wk/wv (+biases) into one [1536,256] weight
// ---------------------------------------------------------------------------
__global__ void __launch_bounds__(256) pack_qkv_kernel(
    const float* __restrict__ wq, const float* __restrict__ wk,
    const float* __restrict__ wv, const float* __restrict__ bq,
    const float* __restrict__ bk, const float* __restrict__ bv,
    float* __restrict__ w, float* __restrict__ b)
{
    int row = blockIdx.x, c = threadIdx.x;
    const float* src; const float* bsrc; int r2;
    if (row < 256)      { src = wq; bsrc = bq; r2 = row; }
    else if (row < 512) { src = wk; bsrc = bk; r2 = row - 256; }
    else                { src = wv; bsrc = bv; r2 = row - 512; }
    w[(size_t)row * 256 + c] = src[(size_t)r2 * 256 + c];
    if (c == 0) b[row] = bsrc[r2];
}

// ---------------------------------------------------------------------------
// BatchNorm1d (train stats over (B,N)) + affine, float4-vectorized
// ---------------------------------------------------------------------------
__global__ void __launch_bounds__(256) bn_kernel(
    const float* __restrict__ x, float* __restrict__ y,
    const float* __restrict__ gamma, const float* __restrict__ beta)
{
    const int c = blockIdx.x, tid = threadIdx.x;
    __shared__ float sh[512];

    float s = 0.f, s2 = 0.f;
    for (int idx = tid; idx < BATCH * NPOS / 4; idx += 256) {
        int bb = idx >> 8, n4 = idx & 255;
        float4 v = *(const float4*)&x[((size_t)bb * CDIM + c) * NPOS + n4 * 4];
        s  += v.x + v.y + v.z + v.w;
        s2 += v.x*v.x + v.y*v.y + v.z*v.z + v.w*v.w;
    }
    sh[tid] = s; sh[256 + tid] = s2;
    __syncthreads();
    for (int off = 128; off; off >>= 1) {
        if (tid < off) { sh[tid] += sh[tid+off]; sh[256+tid] += sh[256+tid+off]; }
        __syncthreads();
    }
    const float inv_n = 1.0f / (float)(BATCH * NPOS);
    float mean = sh[0] * inv_n;
    float var  = sh[256] * inv_n - mean * mean;
    float scale = gamma[c] * rsqrtf(var + 1e-5f);
    float shift = beta[c] - mean * scale;

    for (int idx = tid; idx < BATCH * NPOS / 4; idx += 256) {
        int bb = idx >> 8, n4 = idx & 255;
        size_t o = ((size_t)bb * CDIM + c) * NPOS + n4 * 4;
        float4 v = *(const float4*)&x[o];
        v.x = v.x*scale+shift; v.y = v.y*scale+shift;
        v.z = v.z*scale+shift; v.w = v.w*scale+shift;
        *(float4*)&y[o] = v;
    }
}

// ---------------------------------------------------------------------------
// gemmL: 128x128x16 tiles, 256 threads, 8x8 scalar microtile, double-buffered.
// ---------------------------------------------------------------------------
template<int RELU6, int ADDRES>
__global__ void __launch_bounds__(256) gemmL_kernel(
    const float* __restrict__ W, const float* __restrict__ Y,
    const float* __restrict__ bias, const float* __restrict__ R,
    float* __restrict__ out, int M, int K, int NN)
{
    __shared__ float Ws[2][16][132];
    __shared__ float Ys[2][16][132];

    const int tid = threadIdx.x;
    const int tx = tid & 15, ty = tid >> 4;
    const int n0 = blockIdx.x * 128, m0 = blockIdx.y * 128;
    const float* Yb = Y + (size_t)blockIdx.z * K * NN;
    const size_t zO = (size_t)blockIdx.z * M * NN;

    const int wm = tid >> 1, wk = (tid & 1) * 8;
    const int yk = tid >> 4, yn = (tid & 15) * 8;

    const float* wp = W  + (size_t)(m0 + wm) * K + wk;
    const float* yp = Yb + (size_t)yk * NN + n0 + yn;

    float acc[8][8];
    #pragma unroll
    for (int i = 0; i < 8; ++i)
        #pragma unroll
        for (int j = 0; j < 8; ++j) acc[i][j] = 0.f;

    {
        float4 w0 = *(const float4*)wp;
        float4 w1 = *(const float4*)(wp + 4);
        float4 y0 = *(const float4*)yp;
        float4 y1 = *(const float4*)(yp + 4);
        Ws[0][wk+0][wm] = w0.x; Ws[0][wk+1][wm] = w0.y;
        Ws[0][wk+2][wm] = w0.z; Ws[0][wk+3][wm] = w0.w;
        Ws[0][wk+4][wm] = w1.x; Ws[0][wk+5][wm] = w1.y;
        Ws[0][wk+6][wm] = w1.z; Ws[0][wk+7][wm] = w1.w;
        *(float4*)&Ys[0][yk][yn]     = y0;
        *(float4*)&Ys[0][yk][yn + 4] = y1;
    }
    __syncthreads();

    const int ntiles = K >> 4;
    int buf = 0;
    for (int t = 0; t < ntiles; ++t) {
        float4 w0, w1, y0, y1;
        const bool more = (t + 1 < ntiles);
        if (more) {
            w0 = *(const float4*)(wp + (t + 1) * 16);
            w1 = *(const float4*)(wp + (t + 1) * 16 + 4);
            y0 = *(const float4*)(yp + (size_t)(t + 1) * 16 * NN);
            y1 = *(const float4*)(yp + (size_t)(t + 1) * 16 * NN + 4);
        }
        #pragma unroll
        for (int kk = 0; kk < 16; ++kk) {
            float4 a0 = *(const float4*)&Ws[buf][kk][ty * 8];
            float4 a1 = *(const float4*)&Ws[buf][kk][ty * 8 + 4];
            float4 b0 = *(const float4*)&Ys[buf][kk][tx * 8];
            float4 b1 = *(const float4*)&Ys[buf][kk][tx * 8 + 4];
            float a[8] = {a0.x,a0.y,a0.z,a0.w,a1.x,a1.y,a1.z,a1.w};
            float b[8] = {b0.x,b0.y,b0.z,b0.w,b1.x,b1.y,b1.z,b1.w};
            #pragma unroll
            for (int i = 0; i < 8; ++i)
                #pragma unroll
                for (int j = 0; j < 8; ++j)
                    acc[i][j] += a[i] * b[j];
        }
        if (more) {
            int nb = buf ^ 1;
            Ws[nb][wk+0][wm] = w0.x; Ws[nb][wk+1][wm] = w0.y;
            Ws[nb][wk+2][wm] = w0.z; Ws[nb][wk+3][wm] = w0.w;
            Ws[nb][wk+4][wm] = w1.x; Ws[nb][wk+5][wm] = w1.y;
            Ws[nb][wk+6][wm] = w1.z; Ws[nb][wk+7][wm] = w1.w;
            *(float4*)&Ys[nb][yk][yn]     = y0;
            *(float4*)&Ys[nb][yk][yn + 4] = y1;
        }
        __syncthreads();
        buf ^= 1;
    }

    #pragma unroll
    for (int i = 0; i < 8; ++i) {
        int m = m0 + ty * 8 + i;
        float bv = bias[m];
        float o[8];
        #pragma unroll
        for (int j = 0; j < 8; ++j) o[j] = acc[i][j] + bv;
        if (RELU6) {
            #pragma unroll
            for (int j = 0; j < 8; ++j) o[j] = fminf(fmaxf(o[j], 0.f), 6.f);
        }
        size_t orow = zO + (size_t)m * NN + n0 + tx * 8;
        if (ADDRES) {
            float4 r0 = *(const float4*)&R[orow];
            float4 r1 = *(const float4*)&R[orow + 4];
            o[0]+=r0.x; o[1]+=r0.y; o[2]+=r0.z; o[3]+=r0.w;
            o[4]+=r1.x; o[5]+=r1.y; o[6]+=r1.z; o[7]+=r1.w;
        }
        *(float4*)&out[orow]     = make_float4(o[0],o[1],o[2],o[3]);
        *(float4*)&out[orow + 4] = make_float4(o[4],o[5],o[6],o[7]);
    }
}

// ---------------------------------------------------------------------------
// gemmS: 64x128x16 tiles, 256 threads, 4x8 microtile, double-buffered.
// ---------------------------------------------------------------------------
template<int RELU6, int ADDRES>
__global__ void __launch_bounds__(256) gemmS_kernel(
    const float* __restrict__ W, const float* __restrict__ Y,
    const float* __restrict__ bias, const float* __restrict__ R,
    float* __restrict__ out, int M, int K, int NN)
{
    __shared__ float Ws[2][16][68];
    __shared__ float Ys[2][16][132];

    const int tid = threadIdx.x;
    const int tx = tid & 15, ty = tid >> 4;
    const int n0 = blockIdx.x * 128, m0 = blockIdx.y * 64;
    const float* Yb = Y + (size_t)blockIdx.z * K * NN;
    const size_t zO = (size_t)blockIdx.z * M * NN;

    const int wm = tid & 63, wk = (tid >> 6) * 4;
    const int yk = tid >> 4, yn = (tid & 15) * 8;

    const float* wp = W  + (size_t)(m0 + wm) * K + wk;
    const float* yp = Yb + (size_t)yk * NN + n0 + yn;

    float acc[4][8];
    #pragma unroll
    for (int i = 0; i < 4; ++i)
        #pragma unroll
        for (int j = 0; j < 8; ++j) acc[i][j] = 0.f;

    {
        float4 w0 = *(const float4*)wp;
        float4 y0 = *(const float4*)yp;
        float4 y1 = *(const float4*)(yp + 4);
        Ws[0][wk+0][wm] = w0.x; Ws[0][wk+1][wm] = w0.y;
        Ws[0][wk+2][wm] = w0.z; Ws[0][wk+3][wm] = w0.w;
        *(float4*)&Ys[0][yk][yn]     = y0;
        *(float4*)&Ys[0][yk][yn + 4] = y1;
    }
    __syncthreads();

    const int ntiles = K >> 4;
    int buf = 0;
    for (int t = 0; t < ntiles; ++t) {
        float4 w0, y0, y1;
        const bool more = (t + 1 < ntiles);
        if (more) {
            w0 = *(const float4*)(wp + (t + 1) * 16);
            y0 = *(const float4*)(yp + (size_t)(t + 1) * 16 * NN);
            y1 = *(const float4*)(yp + (size_t)(t + 1) * 16 * NN + 4);
        }
        #pragma unroll
        for (int kk = 0; kk < 16; ++kk) {
            float4 a0 = *(const float4*)&Ws[buf][kk][ty * 4];
            float4 b0 = *(const float4*)&Ys[buf][kk][tx * 8];
            float4 b1 = *(const float4*)&Ys[buf][kk][tx * 8 + 4];
            float a[4] = {a0.x,a0.y,a0.z,a0.w};
            float b[8] = {b0.x,b0.y,b0.z,b0.w,b1.x,b1.y,b1.z,b1.w};
            #pragma unroll
            for (int i = 0; i < 4; ++i)
                #pragma unroll
                for (int j = 0; j < 8; ++j)
                    acc[i][j] += a[i] * b[j];
        }
        if (more) {
            int nb = buf ^ 1;
            Ws[nb][wk+0][wm] = w0.x; Ws[nb][wk+1][wm] = w0.y;
            Ws[nb][wk+2][wm] = w0.z; Ws[nb][wk+3][wm] = w0.w;
            *(float4*)&Ys[nb][yk][yn]     = y0;
            *(float4*)&Ys[nb][yk][yn + 4] = y1;
        }
        __syncthreads();
        buf ^= 1;
    }

    #pragma unroll
    for (int i = 0; i < 4; ++i) {
        int m = m0 + ty * 4 + i;
        float bv = bias[m];
        float o[8];
        #pragma unroll
        for (int j = 0; j < 8; ++j) o[j] = acc[i][j] + bv;
        if (RELU6) {
            #pragma unroll
            for (int j = 0; j < 8; ++j) o[j] = fminf(fmaxf(o[j], 0.f), 6.f);
        }
        size_t orow = zO + (size_t)m * NN + n0 + tx * 8;
        if (ADDRES) {
            float4 r0 = *(const float4*)&R[orow];
            float4 r1 = *(const float4*)&R[orow + 4];
            o[0]+=r0.x; o[1]+=r0.y; o[2]+=r0.z; o[3]+=r0.w;
            o[4]+=r1.x; o[5]+=r1.y; o[6]+=r1.z; o[7]+=r1.w;
        }
        *(float4*)&out[orow]     = make_float4(o[0],o[1],o[2],o[3]);
        *(float4*)&out[orow + 4] = make_float4(o[4],o[5],o[6],o[7]);
    }
}

// ---------------------------------------------------------------------------
// Fused attention v3: PV stage is a register-tiled GEMM on transposed smem.
// Block = (b, h, 64-row tile). Stage1 map (r=tid>>2, dg=tid&3) computes
// scores+exp and writes P transposed St[m][r]. Stage2 map (rg=tid&15,
// dgp=tid>>4) does 4r x 4d microtile PV: 2 LDS.128 per 16 FMA.
// V is smem-transposed at load (Vt[m][d]) with 64B-coalesced global reads.
// ---------------------------------------------------------------------------
#define AT3_SMEM_FLOATS (16*132 + 128*68 + 128*68 + 64)   // Ks, Vt, St, rsum

__global__ void __launch_bounds__(256) attn3_kernel(
    const float* __restrict__ qkv, float* __restrict__ ob)
{
    extern __shared__ float sm[];
    float* Ks   = sm;                    // [16][132]
    float* Vt   = Ks + 16 * 132;         // [128][68] m-major, d cols
    float* St   = Vt + 128 * 68;         // [128][68] m-major, r cols
    float* rsum = St + 128 * 68;         // [64]

    const int tid = threadIdx.x;
    const int r   = tid >> 2;            // stage1: row 0..63
    const int dg  = tid & 3;             // stage1: col group
    const int rg  = tid & 15;            // stage2: r block (rg*4)
    const int dgp = tid >> 4;            // stage2: d block (dgp*4)
    const int h   = blockIdx.y;
    const int r0  = blockIdx.x * 64;
    const int bz  = blockIdx.z;

    const float* bbase = qkv + (size_t)bz * QKV_M * NPOS;
    const float* qh = bbase + (size_t)(h * KDIM) * NPOS;
    const float* kh = bbase + (size_t)(256 + h * KDIM) * NPOS;
    const float* vh = bbase + (size_t)(512 + h * DV) * NPOS;
    const size_t baseO = (size_t)(bz * DH + h * DV) * NPOS;

    float ql[16];
    #pragma unroll
    for (int kd = 0; kd < 16; ++kd)
        ql[kd] = qh[(size_t)kd * NPOS + r0 + r] * 4.0f;

    float acc[4][4];
    #pragma unroll
    for (int i = 0; i < 4; ++i)
        #pragma unroll
        for (int j = 0; j < 4; ++j) acc[i][j] = 0.f;
    float ssum = 0.f;

    const int vd  = tid >> 2;            // V loader: d = 0..63
    const int vmq = tid & 3;             // V loader: mq quad within group

    for (int t = 0; t < 8; ++t) {
        const int m0 = t * 128;
        __syncthreads();
        // K tile [16][128], coalesced float4
        for (int idx = tid; idx < 16 * 32; idx += 256) {
            int kd = idx >> 5, mq = idx & 31;
            float4 v = *(const float4*)&kh[(size_t)kd * NPOS + m0 + mq * 4];
            *(float4*)&Ks[kd * 132 + mq * 4] = v;
        }
        // V tile transposed -> Vt[m][d]; lanes: 8 d-rows x 64B chunks
        #pragma unroll
        for (int it = 0; it < 8; ++it) {
            int mq = vmq + it * 4;       // 0..31
            float4 v = *(const float4*)&vh[(size_t)vd * NPOS + m0 + mq * 4];
            Vt[(mq * 4 + 0) * 68 + vd] = v.x;
            Vt[(mq * 4 + 1) * 68 + vd] = v.y;
            Vt[(mq * 4 + 2) * 68 + vd] = v.z;
            Vt[(mq * 4 + 3) * 68 + vd] = v.w;
        }
        __syncthreads();

        // QK + exp, write P transposed into St[m][r]
        #pragma unroll
        for (int i = 0; i < 8; ++i) {
            int mm4 = i * 4 + dg;
            float4 a = {0.f, 0.f, 0.f, 0.f};
            #pragma unroll
            for (int kd = 0; kd < 16; ++kd) {
                float4 kv = *(const float4*)&Ks[kd * 132 + mm4 * 4];
                a.x += ql[kd] * kv.x; a.y += ql[kd] * kv.y;
                a.z += ql[kd] * kv.z; a.w += ql[kd] * kv.w;
            }
            float4 p;
            p.x = __expf(a.x); p.y = __expf(a.y);
            p.z = __expf(a.z); p.w = __expf(a.w);
            ssum += p.x + p.y + p.z + p.w;
            int mb = mm4 * 4;
            St[(mb + 0) * 68 + r] = p.x;
            St[(mb + 1) * 68 + r] = p.y;
            St[(mb + 2) * 68 + r] = p.z;
            St[(mb + 3) * 68 + r] = p.w;
        }
        __syncthreads();

        // PV: 4x4 microtile GEMM over 128 m-steps
        #pragma unroll 4
        for (int m = 0; m < 128; ++m) {
            float4 p4 = *(const float4*)&St[m * 68 + rg * 4];
            float4 v4 = *(const float4*)&Vt[m * 68 + dgp * 4];
            acc[0][0] += p4.x * v4.x; acc[0][1] += p4.x * v4.y;
            acc[0][2] += p4.x * v4.z; acc[0][3] += p4.x * v4.w;
            acc[1][0] += p4.y * v4.x; acc[1][1] += p4.y * v4.y;
            acc[1][2] += p4.y * v4.z; acc[1][3] += p4.y * v4.w;
            acc[2][0] += p4.z * v4.x; acc[2][1] += p4.z * v4.y;
            acc[2][2] += p4.z * v4.z; acc[2][3] += p4.z * v4.w;
            acc[3][0] += p4.w * v4.x; acc[3][1] += p4.w * v4.y;
            acc[3][2] += p4.w * v4.z; acc[3][3] += p4.w * v4.w;
        }
    }

    // full row sums (quad 4r..4r+3 owns row r)
    ssum += __shfl_xor_sync(0xffffffffu, ssum, 1);
    ssum += __shfl_xor_sync(0xffffffffu, ssum, 2);
    if (dg == 0) rsum[r] = ssum;
    __syncthreads();

    float inv[4];
    #pragma unroll
    for (int i = 0; i < 4; ++i) inv[i] = 1.0f / rsum[rg * 4 + i];

    #pragma unroll
    for (int j = 0; j < 4; ++j) {
        int d = dgp * 4 + j;
        #pragma unroll
        for (int i = 0; i < 4; ++i) {
            ob[baseO + (size_t)d * NPOS + r0 + rg * 4 + i] = acc[i][j] * inv[i];
        }
    }
}

// ---------------------------------------------------------------------------
// Launch
// ---------------------------------------------------------------------------
extern "C" void kernel_launch(void* const* d_in, const int* in_sizes, int n_in,
                              void* d_out, int out_size)
{
    (void)in_sizes; (void)n_in; (void)out_size;
    const float* x   = (const float*)d_in[0];
    const float* g1  = (const float*)d_in[1];
    const float* b1  = (const float*)d_in[2];
    const float* wq  = (const float*)d_in[3];
    const float* bq  = (const float*)d_in[4];
    const float* wk  = (const float*)d_in[5];
    const float* bk  = (const float*)d_in[6];
    const float* wv  = (const float*)d_in[7];
    const float* bv  = (const float*)d_in[8];
    const float* wp  = (const float*)d_in[9];
    const float* bp  = (const float*)d_in[10];
    const float* g2  = (const float*)d_in[11];
    const float* b2  = (const float*)d_in[12];
    const float* w1  = (const float*)d_in[13];
    const float* bb1 = (const float*)d_in[14];
    const float* w2  = (const float*)d_in[15];
    const float* bb2 = (const float*)d_in[16];
    float* out = (float*)d_out;

    float* base = nullptr;
    cudaGetSymbolAddress((void**)&base, g_buf);
    float* Yb   = base + OFF_Y;
    float* QKVb = base + OFF_QKV;
    float* Ob   = base + OFF_O;
    float* X2b  = base + OFF_X2;
    float* Y2b  = base + OFF_Y2;
    float* Hb   = base + OFF_H;
    float* Wqkv = base + OFF_WQKV;
    float* Bqkv = base + OFF_BQKV;

    cudaFuncSetAttribute(attn3_kernel, cudaFuncAttributeMaxDynamicSharedMemorySize,
                         AT3_SMEM_FLOATS * (int)sizeof(float));

    // 0) weight concat
    pack_qkv_kernel<<<QKV_M, 256>>>(wq, wk, wv, bq, bk, bv, Wqkv, Bqkv);

    // 1) BN1
    bn_kernel<<<CDIM, 256>>>(x, Yb, g1, b1);

    // 2) fused QKV projection
    gemmL_kernel<0,0><<<dim3(NPOS/128, QKV_M/128, BATCH), 256>>>(
        Wqkv, Yb, Bqkv, nullptr, QKVb, QKV_M, CDIM, NPOS);

    // 3) attention
    attn3_kernel<<<dim3(NPOS/64, NH, BATCH), 256, AT3_SMEM_FLOATS * sizeof(float)>>>(
        QKVb, Ob);

    // 4) projection + residual(x)
    gemmS_kernel<0,1><<<dim3(NPOS/128, CDIM/64, BATCH), 256>>>(
        wp, Ob, bp, x, X2b, CDIM, DH, NPOS);

    // 5) BN2
    bn_kernel<<<CDIM, 256>>>(X2b, Y2b, g2, b2);

    // 6) MLP
    gemmL_kernel<1,0><<<dim3(NPOS/128, HID/128, BATCH), 256>>>(
        w1, Y2b, bb1, nullptr, Hb, HID, CDIM, NPOS);
    gemmS_kernel<0,1><<<dim3(NPOS/128, CDIM/64, BATCH), 256>>>(
        w2, Hb, bb2, X2b, out, CDIM, HID, NPOS);
}

// round 8
// speedup vs baseline: 2.4288x; 1.1685x over previous
#include <cuda_runtime.h>
#include <cstdint>

// ---------------------------------------------------------------------------
// Problem constants
// ---------------------------------------------------------------------------
#define BATCH 8
#define CDIM  256
#define NPOS  1024
#define NH    16
#define KDIM  16
#define DV    64
#define DH    (NH*DV)       // 1024
#define HID   1024
#define QKV_M 1536

// ---------------------------------------------------------------------------
// Scratch (device global). Offsets in floats.
// ---------------------------------------------------------------------------
#define OFF_Y     0u                        // [8,256,1024]
#define OFF_QKV   (OFF_Y    + 2097152u)     // [8,1536,1024]
#define OFF_O     (OFF_QKV  + 12582912u)    // [8,1024,1024]
#define OFF_X2    (OFF_O    + 8388608u)     // [8,256,1024]
#define OFF_Y2    (OFF_X2   + 2097152u)     // [8,256,1024]
#define OFF_H     (OFF_Y2   + 2097152u)     // [8,1024,1024]
#define OFF_VT    (OFF_H    + 8388608u)     // [8,16,1024,64]
#define OFF_WQKV  (OFF_VT   + 8388608u)     // [1536,256]
#define OFF_BQKV  (OFF_WQKV + 393216u)      // [1536]
#define SCRATCH_FLOATS (OFF_BQKV + 1536u)

__device__ float g_buf[SCRATCH_FLOATS];

// ---------------------------------------------------------------------------
// Concatenate wq/wk/wv (+biases) into one [1536,256] weight
// ---------------------------------------------------------------------------
__global__ void __launch_bounds__(256) pack_qkv_kernel(
    const float* __restrict__ wq, const float* __restrict__ wk,
    const float* __restrict__ wv, const float* __restrict__ bq,
    const float* __restrict__ bk, const float* __restrict__ bv,
    float* __restrict__ w, float* __restrict__ b)
{
    int row = blockIdx.x, c = threadIdx.x;
    const float* src; const float* bsrc; int r2;
    if (row < 256)      { src = wq; bsrc = bq; r2 = row; }
    else if (row < 512) { src = wk; bsrc = bk; r2 = row - 256; }
    else                { src = wv; bsrc = bv; r2 = row - 512; }
    w[(size_t)row * 256 + c] = src[(size_t)r2 * 256 + c];
    if (c == 0) b[row] = bsrc[r2];
}

// ---------------------------------------------------------------------------
// BatchNorm1d (train stats over (B,N)) + affine, float4-vectorized
// ---------------------------------------------------------------------------
__global__ void __launch_bounds__(256) bn_kernel(
    const float* __restrict__ x, float* __restrict__ y,
    const float* __restrict__ gamma, const float* __restrict__ beta)
{
    const int c = blockIdx.x, tid = threadIdx.x;
    __shared__ float sh[512];

    float s = 0.f, s2 = 0.f;
    for (int idx = tid; idx < BATCH * NPOS / 4; idx += 256) {
        int bb = idx >> 8, n4 = idx & 255;
        float4 v = *(const float4*)&x[((size_t)bb * CDIM + c) * NPOS + n4 * 4];
        s  += v.x + v.y + v.z + v.w;
        s2 += v.x*v.x + v.y*v.y + v.z*v.z + v.w*v.w;
    }
    sh[tid] = s; sh[256 + tid] = s2;
    __syncthreads();
    for (int off = 128; off; off >>= 1) {
        if (tid < off) { sh[tid] += sh[tid+off]; sh[256+tid] += sh[256+tid+off]; }
        __syncthreads();
    }
    const float inv_n = 1.0f / (float)(BATCH * NPOS);
    float mean = sh[0] * inv_n;
    float var  = sh[256] * inv_n - mean * mean;
    float scale = gamma[c] * rsqrtf(var + 1e-5f);
    float shift = beta[c] - mean * scale;

    for (int idx = tid; idx < BATCH * NPOS / 4; idx += 256) {
        int bb = idx >> 8, n4 = idx & 255;
        size_t o = ((size_t)bb * CDIM + c) * NPOS + n4 * 4;
        float4 v = *(const float4*)&x[o];
        v.x = v.x*scale+shift; v.y = v.y*scale+shift;
        v.z = v.z*scale+shift; v.w = v.w*scale+shift;
        *(float4*)&y[o] = v;
    }
}

// ---------------------------------------------------------------------------
// gemmL: 128x128x16 tiles, 256 threads, 8x8 scalar microtile, double-buffered.
// ---------------------------------------------------------------------------
template<int RELU6, int ADDRES>
__global__ void __launch_bounds__(256) gemmL_kernel(
    const float* __restrict__ W, const float* __restrict__ Y,
    const float* __restrict__ bias, const float* __restrict__ R,
    float* __restrict__ out, int M, int K, int NN)
{
    __shared__ float Ws[2][16][132];
    __shared__ float Ys[2][16][132];

    const int tid = threadIdx.x;
    const int tx = tid & 15, ty = tid >> 4;
    const int n0 = blockIdx.x * 128, m0 = blockIdx.y * 128;
    const float* Yb = Y + (size_t)blockIdx.z * K * NN;
    const size_t zO = (size_t)blockIdx.z * M * NN;

    const int wm = tid >> 1, wk = (tid & 1) * 8;
    const int yk = tid >> 4, yn = (tid & 15) * 8;

    const float* wp = W  + (size_t)(m0 + wm) * K + wk;
    const float* yp = Yb + (size_t)yk * NN + n0 + yn;

    float acc[8][8];
    #pragma unroll
    for (int i = 0; i < 8; ++i)
        #pragma unroll
        for (int j = 0; j < 8; ++j) acc[i][j] = 0.f;

    {
        float4 w0 = *(const float4*)wp;
        float4 w1 = *(const float4*)(wp + 4);
        float4 y0 = *(const float4*)yp;
        float4 y1 = *(const float4*)(yp + 4);
        Ws[0][wk+0][wm] = w0.x; Ws[0][wk+1][wm] = w0.y;
        Ws[0][wk+2][wm] = w0.z; Ws[0][wk+3][wm] = w0.w;
        Ws[0][wk+4][wm] = w1.x; Ws[0][wk+5][wm] = w1.y;
        Ws[0][wk+6][wm] = w1.z; Ws[0][wk+7][wm] = w1.w;
        *(float4*)&Ys[0][yk][yn]     = y0;
        *(float4*)&Ys[0][yk][yn + 4] = y1;
    }
    __syncthreads();

    const int ntiles = K >> 4;
    int buf = 0;
    for (int t = 0; t < ntiles; ++t) {
        float4 w0, w1, y0, y1;
        const bool more = (t + 1 < ntiles);
        if (more) {
            w0 = *(const float4*)(wp + (t + 1) * 16);
            w1 = *(const float4*)(wp + (t + 1) * 16 + 4);
            y0 = *(const float4*)(yp + (size_t)(t + 1) * 16 * NN);
            y1 = *(const float4*)(yp + (size_t)(t + 1) * 16 * NN + 4);
        }
        #pragma unroll
        for (int kk = 0; kk < 16; ++kk) {
            float4 a0 = *(const float4*)&Ws[buf][kk][ty * 8];
            float4 a1 = *(const float4*)&Ws[buf][kk][ty * 8 + 4];
            float4 b0 = *(const float4*)&Ys[buf][kk][tx * 8];
            float4 b1 = *(const float4*)&Ys[buf][kk][tx * 8 + 4];
            float a[8] = {a0.x,a0.y,a0.z,a0.w,a1.x,a1.y,a1.z,a1.w};
            float b[8] = {b0.x,b0.y,b0.z,b0.w,b1.x,b1.y,b1.z,b1.w};
            #pragma unroll
            for (int i = 0; i < 8; ++i)
                #pragma unroll
                for (int j = 0; j < 8; ++j)
                    acc[i][j] += a[i] * b[j];
        }
        if (more) {
            int nb = buf ^ 1;
            Ws[nb][wk+0][wm] = w0.x; Ws[nb][wk+1][wm] = w0.y;
            Ws[nb][wk+2][wm] = w0.z; Ws[nb][wk+3][wm] = w0.w;
            Ws[nb][wk+4][wm] = w1.x; Ws[nb][wk+5][wm] = w1.y;
            Ws[nb][wk+6][wm] = w1.z; Ws[nb][wk+7][wm] = w1.w;
            *(float4*)&Ys[nb][yk][yn]     = y0;
            *(float4*)&Ys[nb][yk][yn + 4] = y1;
        }
        __syncthreads();
        buf ^= 1;
    }

    #pragma unroll
    for (int i = 0; i < 8; ++i) {
        int m = m0 + ty * 8 + i;
        float bv = bias[m];
        float o[8];
        #pragma unroll
        for (int j = 0; j < 8; ++j) o[j] = acc[i][j] + bv;
        if (RELU6) {
            #pragma unroll
            for (int j = 0; j < 8; ++j) o[j] = fminf(fmaxf(o[j], 0.f), 6.f);
        }
        size_t orow = zO + (size_t)m * NN + n0 + tx * 8;
        if (ADDRES) {
            float4 r0 = *(const float4*)&R[orow];
            float4 r1 = *(const float4*)&R[orow + 4];
            o[0]+=r0.x; o[1]+=r0.y; o[2]+=r0.z; o[3]+=r0.w;
            o[4]+=r1.x; o[5]+=r1.y; o[6]+=r1.z; o[7]+=r1.w;
        }
        *(float4*)&out[orow]     = make_float4(o[0],o[1],o[2],o[3]);
        *(float4*)&out[orow + 4] = make_float4(o[4],o[5],o[6],o[7]);
    }
}

// ---------------------------------------------------------------------------
// gemmS: 64x128x16 tiles, 256 threads, 4x8 microtile, double-buffered.
// ---------------------------------------------------------------------------
template<int RELU6, int ADDRES>
__global__ void __launch_bounds__(256) gemmS_kernel(
    const float* __restrict__ W, const float* __restrict__ Y,
    const float* __restrict__ bias, const float* __restrict__ R,
    float* __restrict__ out, int M, int K, int NN)
{
    __shared__ float Ws[2][16][68];
    __shared__ float Ys[2][16][132];

    const int tid = threadIdx.x;
    const int tx = tid & 15, ty = tid >> 4;
    const int n0 = blockIdx.x * 128, m0 = blockIdx.y * 64;
    const float* Yb = Y + (size_t)blockIdx.z * K * NN;
    const size_t zO = (size_t)blockIdx.z * M * NN;

    const int wm = tid & 63, wk = (tid >> 6) * 4;
    const int yk = tid >> 4, yn = (tid & 15) * 8;

    const float* wp = W  + (size_t)(m0 + wm) * K + wk;
    const float* yp = Yb + (size_t)yk * NN + n0 + yn;

    float acc[4][8];
    #pragma unroll
    for (int i = 0; i < 4; ++i)
        #pragma unroll
        for (int j = 0; j < 8; ++j) acc[i][j] = 0.f;

    {
        float4 w0 = *(const float4*)wp;
        float4 y0 = *(const float4*)yp;
        float4 y1 = *(const float4*)(yp + 4);
        Ws[0][wk+0][wm] = w0.x; Ws[0][wk+1][wm] = w0.y;
        Ws[0][wk+2][wm] = w0.z; Ws[0][wk+3][wm] = w0.w;
        *(float4*)&Ys[0][yk][yn]     = y0;
        *(float4*)&Ys[0][yk][yn + 4] = y1;
    }
    __syncthreads();

    const int ntiles = K >> 4;
    int buf = 0;
    for (int t = 0; t < ntiles; ++t) {
        float4 w0, y0, y1;
        const bool more = (t + 1 < ntiles);
        if (more) {
            w0 = *(const float4*)(wp + (t + 1) * 16);
            y0 = *(const float4*)(yp + (size_t)(t + 1) * 16 * NN);
            y1 = *(const float4*)(yp + (size_t)(t + 1) * 16 * NN + 4);
        }
        #pragma unroll
        for (int kk = 0; kk < 16; ++kk) {
            float4 a0 = *(const float4*)&Ws[buf][kk][ty * 4];
            float4 b0 = *(const float4*)&Ys[buf][kk][tx * 8];
            float4 b1 = *(const float4*)&Ys[buf][kk][tx * 8 + 4];
            float a[4] = {a0.x,a0.y,a0.z,a0.w};
            float b[8] = {b0.x,b0.y,b0.z,b0.w,b1.x,b1.y,b1.z,b1.w};
            #pragma unroll
            for (int i = 0; i < 4; ++i)
                #pragma unroll
                for (int j = 0; j < 8; ++j)
                    acc[i][j] += a[i] * b[j];
        }
        if (more) {
            int nb = buf ^ 1;
            Ws[nb][wk+0][wm] = w0.x; Ws[nb][wk+1][wm] = w0.y;
            Ws[nb][wk+2][wm] = w0.z; Ws[nb][wk+3][wm] = w0.w;
            *(float4*)&Ys[nb][yk][yn]     = y0;
            *(float4*)&Ys[nb][yk][yn + 4] = y1;
        }
        __syncthreads();
        buf ^= 1;
    }

    #pragma unroll
    for (int i = 0; i < 4; ++i) {
        int m = m0 + ty * 4 + i;
        float bv = bias[m];
        float o[8];
        #pragma unroll
        for (int j = 0; j < 8; ++j) o[j] = acc[i][j] + bv;
        if (RELU6) {
            #pragma unroll
            for (int j = 0; j < 8; ++j) o[j] = fminf(fmaxf(o[j], 0.f), 6.f);
        }
        size_t orow = zO + (size_t)m * NN + n0 + tx * 8;
        if (ADDRES) {
            float4 r0 = *(const float4*)&R[orow];
            float4 r1 = *(const float4*)&R[orow + 4];
            o[0]+=r0.x; o[1]+=r0.y; o[2]+=r0.z; o[3]+=r0.w;
            o[4]+=r1.x; o[5]+=r1.y; o[6]+=r1.z; o[7]+=r1.w;
        }
        *(float4*)&out[orow]     = make_float4(o[0],o[1],o[2],o[3]);
        *(float4*)&out[orow + 4] = make_float4(o[4],o[5],o[6],o[7]);
    }
}

// ---------------------------------------------------------------------------
// Transpose V slice of QKV: [b][512+h*64+d][m] -> Vt[b][h][m][d]
// grid = (NPOS/32, DV/32, BATCH*NH), 256 threads  (R2-verified, ~13us)
// ---------------------------------------------------------------------------
__global__ void __launch_bounds__(256) transpose_v_kernel(
    const float* __restrict__ qkv, float* __restrict__ vt)
{
    __shared__ float tile[32][33];
    const int bh = blockIdx.z;
    const int b = bh >> 4, h = bh & 15;
    const float* src = qkv + ((size_t)b * QKV_M + 512 + h * DV) * NPOS;
    float* dst = vt + (size_t)bh * NPOS * DV;
    const int m0 = blockIdx.x * 32, d0 = blockIdx.y * 32;
    const int tx = threadIdx.x & 31, ty0 = threadIdx.x >> 5;

    #pragma unroll
    for (int ty = ty0; ty < 32; ty += 8)
        tile[ty][tx] = src[(size_t)(d0 + ty) * NPOS + m0 + tx];
    __syncthreads();
    #pragma unroll
    for (int ty = ty0; ty < 32; ty += 8)
        dst[(size_t)(m0 + ty) * DV + d0 + tx] = tile[tx][ty];
}

// ---------------------------------------------------------------------------
// Fused attention v4: both stages register-tiled 4x4, one thread map.
// Block = (b, h, 64-row tile), 256 threads, 64-col m-tiles (16 tiles).
// smem ~48KB -> 4 CTAs/SM (32 warps). V pre-transposed in global.
// Stage1: thread (rg,cg) computes rows rg*4..+3 x cols cg*4..+3:
//   per kd: 2 LDS.128 -> 16 FMA. exp + STS.128 transposed into St[m][r].
// Stage2: per m-step: 2 LDS.128 -> 16 FMA into persistent accO.
// ---------------------------------------------------------------------------
__global__ void __launch_bounds__(256, 4) attn4_kernel(
    const float* __restrict__ qkv, const float* __restrict__ vt,
    float* __restrict__ ob)
{
    __shared__ float Qs[16][68];
    __shared__ float Ks[16][68];
    __shared__ float Vs[64][68];
    __shared__ float St[64][68];
    __shared__ float Rp[16][68];
    __shared__ float Rinv[64];

    const int tid = threadIdx.x;
    const int rg  = tid & 15;       // row group (rows rg*4..+3)
    const int cg  = tid >> 4;       // col group stage1 / d group stage2
    const int h   = blockIdx.y;
    const int r0  = blockIdx.x * 64;
    const int bz  = blockIdx.z;

    const float* qh  = qkv + (size_t)(bz * QKV_M + h * KDIM) * NPOS;
    const float* kh  = qkv + (size_t)(bz * QKV_M + 256 + h * KDIM) * NPOS;
    const float* vth = vt + (size_t)(bz * NH + h) * NPOS * DV;
    const size_t baseO = (size_t)(bz * DH + h * DV) * NPOS;

    // Q tile -> smem, scale sqrt(kd)=4 folded
    {
        int kd = tid >> 4, r4 = (tid & 15) * 4;
        float4 q = *(const float4*)&qh[(size_t)kd * NPOS + r0 + r4];
        q.x *= 4.f; q.y *= 4.f; q.z *= 4.f; q.w *= 4.f;
        *(float4*)&Qs[kd][r4] = q;
    }

    float accO[4][4];
    #pragma unroll
    for (int i = 0; i < 4; ++i)
        #pragma unroll
        for (int j = 0; j < 4; ++j) accO[i][j] = 0.f;
    float rs0 = 0.f, rs1 = 0.f, rs2 = 0.f, rs3 = 0.f;

    for (int t = 0; t < 16; ++t) {
        const int m0 = t * 64;
        __syncthreads();
        // K tile [16][64]: one float4 per thread
        {
            int kd = tid >> 4, mq = tid & 15;
            *(float4*)&Ks[kd][mq * 4] =
                *(const float4*)&kh[(size_t)kd * NPOS + m0 + mq * 4];
        }
        // V tile [64][64] from pre-transposed global: 4 float4 per thread
        #pragma unroll
        for (int p = 0; p < 4; ++p) {
            int idx = tid + p * 256;
            int mm = idx >> 4, dq = idx & 15;
            *(float4*)&Vs[mm][dq * 4] =
                *(const float4*)&vth[(size_t)(m0 + mm) * DV + dq * 4];
        }
        __syncthreads();

        // Stage1: QK 4x4
        float s00=0,s01=0,s02=0,s03=0, s10=0,s11=0,s12=0,s13=0;
        float s20=0,s21=0,s22=0,s23=0, s30=0,s31=0,s32=0,s33=0;
        #pragma unroll
        for (int kd = 0; kd < 16; ++kd) {
            float4 q4 = *(const float4*)&Qs[kd][rg * 4];
            float4 k4 = *(const float4*)&Ks[kd][cg * 4];
            s00 += q4.x*k4.x; s01 += q4.x*k4.y; s02 += q4.x*k4.z; s03 += q4.x*k4.w;
            s10 += q4.y*k4.x; s11 += q4.y*k4.y; s12 += q4.y*k4.z; s13 += q4.y*k4.w;
            s20 += q4.z*k4.x; s21 += q4.z*k4.y; s22 += q4.z*k4.z; s23 += q4.z*k4.w;
            s30 += q4.w*k4.x; s31 += q4.w*k4.y; s32 += q4.w*k4.z; s33 += q4.w*k4.w;
        }
        // exp + transposed store St[m][r] (vectorized over rows)
        {
            float4 p;
            p.x = __expf(s00); p.y = __expf(s10); p.z = __expf(s20); p.w = __expf(s30);
            rs0 += p.x; rs1 += p.y; rs2 += p.z; rs3 += p.w;
            *(float4*)&St[cg * 4 + 0][rg * 4] = p;
            p.x = __expf(s01); p.y = __expf(s11); p.z = __expf(s21); p.w = __expf(s31);
            rs0 += p.x; rs1 += p.y; rs2 += p.z; rs3 += p.w;
            *(float4*)&St[cg * 4 + 1][rg * 4] = p;
            p.x = __expf(s02); p.y = __expf(s12); p.z = __expf(s22); p.w = __expf(s32);
            rs0 += p.x; rs1 += p.y; rs2 += p.z; rs3 += p.w;
            *(float4*)&St[cg * 4 + 2][rg * 4] = p;
            p.x = __expf(s03); p.y = __expf(s13); p.z = __expf(s23); p.w = __expf(s33);
            rs0 += p.x; rs1 += p.y; rs2 += p.z; rs3 += p.w;
            *(float4*)&St[cg * 4 + 3][rg * 4] = p;
        }
        __syncthreads();

        // Stage2: PV 4x4 over 64 m-steps
        #pragma unroll 8
        for (int m = 0; m < 64; ++m) {
            float4 p4 = *(const float4*)&St[m][rg * 4];
            float4 v4 = *(const float4*)&Vs[m][cg * 4];
            accO[0][0] += p4.x*v4.x; accO[0][1] += p4.x*v4.y;
            accO[0][2] += p4.x*v4.z; accO[0][3] += p4.x*v4.w;
            accO[1][0] += p4.y*v4.x; accO[1][1] += p4.y*v4.y;
            accO[1][2] += p4.y*v4.z; accO[1][3] += p4.y*v4.w;
            accO[2][0] += p4.z*v4.x; accO[2][1] += p4.z*v4.y;
            accO[2][2] += p4.z*v4.z; accO[2][3] += p4.z*v4.w;
            accO[3][0] += p4.w*v4.x; accO[3][1] += p4.w*v4.y;
            accO[3][2] += p4.w*v4.z; accO[3][3] += p4.w*v4.w;
        }
    }

    // row-sum reduction across the 16 cg groups
    *(float4*)&Rp[cg][rg * 4] = make_float4(rs0, rs1, rs2, rs3);
    __syncthreads();
    if (tid < 64) {
        float s = 0.f;
        #pragma unroll
        for (int g = 0; g < 16; ++g) s += Rp[g][tid];
        Rinv[tid] = 1.0f / s;
    }
    __syncthreads();

    float inv0 = Rinv[rg*4+0], inv1 = Rinv[rg*4+1];
    float inv2 = Rinv[rg*4+2], inv3 = Rinv[rg*4+3];

    #pragma unroll
    for (int j = 0; j < 4; ++j) {
        size_t od = baseO + (size_t)(cg * 4 + j) * NPOS + r0 + rg * 4;
        float4 o;
        o.x = accO[0][j] * inv0; o.y = accO[1][j] * inv1;
        o.z = accO[2][j] * inv2; o.w = accO[3][j] * inv3;
        *(float4*)&ob[od] = o;
    }
}

// ---------------------------------------------------------------------------
// Launch
// ---------------------------------------------------------------------------
extern "C" void kernel_launch(void* const* d_in, const int* in_sizes, int n_in,
                              void* d_out, int out_size)
{
    (void)in_sizes; (void)n_in; (void)out_size;
    const float* x   = (const float*)d_in[0];
    const float* g1  = (const float*)d_in[1];
    const float* b1  = (const float*)d_in[2];
    const float* wq  = (const float*)d_in[3];
    const float* bq  = (const float*)d_in[4];
    const float* wk  = (const float*)d_in[5];
    const float* bk  = (const float*)d_in[6];
    const float* wv  = (const float*)d_in[7];
    const float* bv  = (const float*)d_in[8];
    const float* wp  = (const float*)d_in[9];
    const float* bp  = (const float*)d_in[10];
    const float* g2  = (const float*)d_in[11];
    const float* b2  = (const float*)d_in[12];
    const float* w1  = (const float*)d_in[13];
    const float* bb1 = (const float*)d_in[14];
    const float* w2  = (const float*)d_in[15];
    const float* bb2 = (const float*)d_in[16];
    float* out = (float*)d_out;

    float* base = nullptr;
    cudaGetSymbolAddress((void**)&base, g_buf);
    float* Yb   = base + OFF_Y;
    float* QKVb = base + OFF_QKV;
    float* Ob   = base + OFF_O;
    float* X2b  = base + OFF_X2;
    float* Y2b  = base + OFF_Y2;
    float* Hb   = base + OFF_H;
    float* VTb  = base + OFF_VT;
    float* Wqkv = base + OFF_WQKV;
    float* Bqkv = base + OFF_BQKV;

    // 0) weight concat
    pack_qkv_kernel<<<QKV_M, 256>>>(wq, wk, wv, bq, bk, bv, Wqkv, Bqkv);

    // 1) BN1
    bn_kernel<<<CDIM, 256>>>(x, Yb, g1, b1);

    // 2) fused QKV projection
    gemmL_kernel<0,0><<<dim3(NPOS/128, QKV_M/128, BATCH), 256>>>(
        Wqkv, Yb, Bqkv, nullptr, QKVb, QKV_M, CDIM, NPOS);

    // 3) transpose V, then attention
    transpose_v_kernel<<<dim3(NPOS/32, DV/32, BATCH*NH), 256>>>(QKVb, VTb);
    attn4_kernel<<<dim3(NPOS/64, NH, BATCH), 256>>>(QKVb, VTb, Ob);

    // 4) projection + residual(x)
    gemmS_kernel<0,1><<<dim3(NPOS/128, CDIM/64, BATCH), 256>>>(
        wp, Ob, bp, x, X2b, CDIM, DH, NPOS);

    // 5) BN2
    bn_kernel<<<CDIM, 256>>>(X2b, Y2b, g2, b2);

    // 6) MLP
    gemmL_kernel<1,0><<<dim3(NPOS/128, HID/128, BATCH), 256>>>(
        w1, Y2b, bb1, nullptr, Hb, HID, CDIM, NPOS);
    gemmS_kernel<0,1><<<dim3(NPOS/128, CDIM/64, BATCH), 256>>>(
        w2, Hb, bb2, X2b, out, CDIM, HID, NPOS);
}

// round 11
// speedup vs baseline: 3.7737x; 1.5538x over previous
#include <cuda_runtime.h>
#include <cstdint>

// ---------------------------------------------------------------------------
// Problem constants
// ---------------------------------------------------------------------------
#define BATCH 8
#define CDIM  256
#define NPOS  1024
#define NH    16
#define KDIM  16
#define DV    64
#define DH    (NH*DV)       // 1024
#define HID   1024
#define QKV_M 1536

// ---------------------------------------------------------------------------
// Scratch (device global). Offsets in floats.
// ---------------------------------------------------------------------------
#define OFF_Y     0u                        // [8,256,1024]
#define OFF_YT    (OFF_Y    + 2097152u)     // [8,1024,256]   (n, k)
#define OFF_QKV   (OFF_YT   + 2097152u)     // [8,1536,1024]
#define OFF_OT    (OFF_QKV  + 12582912u)    // [8,1024,1024]  (n, dh)
#define OFF_X2    (OFF_OT   + 8388608u)     // [8,256,1024]
#define OFF_Y2    (OFF_X2   + 2097152u)     // [8,256,1024]
#define OFF_Y2T   (OFF_Y2   + 2097152u)     // [8,1024,256]
#define OFF_H     (OFF_Y2T  + 2097152u)     // [8,1024,1024]  (hid, n)
#define OFF_HT    (OFF_H    + 8388608u)     // [8,1024,1024]  (n, hid)
#define OFF_VT    (OFF_HT   + 8388608u)     // [8,16,1024,64]
#define OFF_WQKV  (OFF_VT   + 8388608u)     // [1536,256]
#define OFF_BQKV  (OFF_WQKV + 393216u)      // [1536]
#define SCRATCH_FLOATS (OFF_BQKV + 1536u)

__device__ float g_buf[SCRATCH_FLOATS];

// ---------------------------------------------------------------------------
// tf32 helpers (mma.sync path — supported on bare sm_103 target)
// ---------------------------------------------------------------------------
__device__ __forceinline__ float to_tf32(float x) {
    float r;
    asm("cvt.rna.tf32.f32 %0, %1;" : "=f"(r) : "f"(x));
    return r;
}
__device__ __forceinline__ void mma_tf32(float* d, const uint32_t* a,
                                         const uint32_t* b) {
    asm volatile(
        "mma.sync.aligned.m16n8k8.row.col.f32.tf32.tf32.f32 "
        "{%0,%1,%2,%3}, {%4,%5,%6,%7}, {%8,%9}, {%0,%1,%2,%3};"
        : "+f"(d[0]), "+f"(d[1]), "+f"(d[2]), "+f"(d[3])
        : "r"(a[0]), "r"(a[1]), "r"(a[2]), "r"(a[3]), "r"(b[0]), "r"(b[1]));
}

// ---------------------------------------------------------------------------
// Concatenate wq/wk/wv (+biases) into one [1536,256] weight
// ---------------------------------------------------------------------------
__global__ void __launch_bounds__(256) pack_qkv_kernel(
    const float* __restrict__ wq, const float* __restrict__ wk,
    const float* __restrict__ wv, const float* __restrict__ bq,
    const float* __restrict__ bk, const float* __restrict__ bv,
    float* __restrict__ w, float* __restrict__ b)
{
    int row = blockIdx.x, c = threadIdx.x;
    const float* src; const float* bsrc; int r2;
    if (row < 256)      { src = wq; bsrc = bq; r2 = row; }
    else if (row < 512) { src = wk; bsrc = bk; r2 = row - 256; }
    else                { src = wv; bsrc = bv; r2 = row - 512; }
    w[(size_t)row * 256 + c] = src[(size_t)r2 * 256 + c];
    if (c == 0) b[row] = bsrc[r2];
}

// ---------------------------------------------------------------------------
// BatchNorm1d (train stats over (B,N)) + affine, float4-vectorized
// ---------------------------------------------------------------------------
__global__ void __launch_bounds__(256) bn_kernel(
    const float* __restrict__ x, float* __restrict__ y,
    const float* __restrict__ gamma, const float* __restrict__ beta)
{
    const int c = blockIdx.x, tid = threadIdx.x;
    __shared__ float sh[512];

    float s = 0.f, s2 = 0.f;
    for (int idx = tid; idx < BATCH * NPOS / 4; idx += 256) {
        int bb = idx >> 8, n4 = idx & 255;
        float4 v = *(const float4*)&x[((size_t)bb * CDIM + c) * NPOS + n4 * 4];
        s  += v.x + v.y + v.z + v.w;
        s2 += v.x*v.x + v.y*v.y + v.z*v.z + v.w*v.w;
    }
    sh[tid] = s; sh[256 + tid] = s2;
    __syncthreads();
    for (int off = 128; off; off >>= 1) {
        if (tid < off) { sh[tid] += sh[tid+off]; sh[256+tid] += sh[256+tid+off]; }
        __syncthreads();
    }
    const float inv_n = 1.0f / (float)(BATCH * NPOS);
    float mean = sh[0] * inv_n;
    float var  = sh[256] * inv_n - mean * mean;
    float scale = gamma[c] * rsqrtf(var + 1e-5f);
    float shift = beta[c] - mean * scale;

    for (int idx = tid; idx < BATCH * NPOS / 4; idx += 256) {
        int bb = idx >> 8, n4 = idx & 255;
        size_t o = ((size_t)bb * CDIM + c) * NPOS + n4 * 4;
        float4 v = *(const float4*)&x[o];
        v.x = v.x*scale+shift; v.y = v.y*scale+shift;
        v.z = v.z*scale+shift; v.w = v.w*scale+shift;
        *(float4*)&y[o] = v;
    }
}

// ---------------------------------------------------------------------------
// Generic batched 32x32 tiled transpose: in [B][R][C] -> out [B][C][R]
// grid = (C/32, R/32, B), 256 threads
// ---------------------------------------------------------------------------
__global__ void __launch_bounds__(256) transpose_kernel(
    const float* __restrict__ src, float* __restrict__ dst, int R, int C)
{
    __shared__ float tile[32][33];
    const int b = blockIdx.z;
    const float* s = src + (size_t)b * R * C;
    float* d = dst + (size_t)b * R * C;
    const int c0 = blockIdx.x * 32, r0 = blockIdx.y * 32;
    const int tx = threadIdx.x & 31, ty0 = threadIdx.x >> 5;

    #pragma unroll
    for (int ty = ty0; ty < 32; ty += 8)
        tile[ty][tx] = s[(size_t)(r0 + ty) * C + c0 + tx];
    __syncthreads();
    #pragma unroll
    for (int ty = ty0; ty < 32; ty += 8)
        d[(size_t)(c0 + ty) * R + r0 + tx] = tile[tx][ty];
}

// ---------------------------------------------------------------------------
// mma.sync tf32 GEMM: out[z][m][n] = act(sum_k W[m][k]*Bt[n][k] + bias[m]) (+R)
// W row-major [M,K], Bt row-major [NN,K] (= B col-major). K % 32 == 0.
// Block tile BM x 128, 256 threads = 8 warps (2m x 4n), warp = (BM/2) x 32.
// Each warp tile: m16n8k8 mma grid, fragments loaded scalar from smem
// (stride-36 rows -> conflict-free: bank = (4*gid + t4) % 32, all distinct).
// grid = (NN/128, M/BM, BATCH)
// ---------------------------------------------------------------------------
template<int BM, int RELU6, int ADDRES>
__global__ void __launch_bounds__(256) mma_gemm_kernel(
    const float* __restrict__ W, const float* __restrict__ Bt,
    const float* __restrict__ bias, const float* __restrict__ R,
    float* __restrict__ out, int M, int K, int NN)
{
    constexpr int MT = BM / 32;          // m16 tiles per warp
    __shared__ float As[BM][36];
    __shared__ float Bs[128][36];

    const int tid = threadIdx.x;
    const int w   = tid >> 5, lane = tid & 31;
    const int gid = lane >> 2, t4 = lane & 3;
    const int n0  = blockIdx.x * 128, m0 = blockIdx.y * BM;
    const int wm  = (w & 1) * (BM / 2);
    const int wn  = (w >> 1) * 32;
    const float* Btb = Bt + (size_t)blockIdx.z * NN * K;
    const size_t zO  = (size_t)blockIdx.z * (size_t)M * NN;

    const int lrow = tid >> 3;           // 0..31
    const int lq   = tid & 7;            // 0..7 (float4 col)

    float d[MT][4][4];
    #pragma unroll
    for (int mt = 0; mt < MT; ++mt)
        #pragma unroll
        for (int nt = 0; nt < 4; ++nt)
            #pragma unroll
            for (int j = 0; j < 4; ++j) d[mt][nt][j] = 0.f;

    for (int kc = 0; kc < K; kc += 32) {
        __syncthreads();
        // stage A (BM x 32) and B (128 x 32), tf32-rounded
        #pragma unroll
        for (int p = 0; p < BM / 32; ++p) {
            int row = lrow + p * 32;
            float4 v = *(const float4*)&W[(size_t)(m0 + row) * K + kc + lq * 4];
            v.x = to_tf32(v.x); v.y = to_tf32(v.y);
            v.z = to_tf32(v.z); v.w = to_tf32(v.w);
            *(float4*)&As[row][lq * 4] = v;
        }
        #pragma unroll
        for (int p = 0; p < 4; ++p) {
            int row = lrow + p * 32;
            float4 v = *(const float4*)&Btb[(size_t)(n0 + row) * K + kc + lq * 4];
            v.x = to_tf32(v.x); v.y = to_tf32(v.y);
            v.z = to_tf32(v.z); v.w = to_tf32(v.w);
            *(float4*)&Bs[row][lq * 4] = v;
        }
        __syncthreads();

        #pragma unroll
        for (int k8 = 0; k8 < 4; ++k8) {
            const int kb = k8 * 8;
            uint32_t a[MT][4], b[4][2];
            #pragma unroll
            for (int mt = 0; mt < MT; ++mt) {
                int r1 = wm + mt * 16 + gid;
                a[mt][0] = __float_as_uint(As[r1][kb + t4]);
                a[mt][1] = __float_as_uint(As[r1 + 8][kb + t4]);
                a[mt][2] = __float_as_uint(As[r1][kb + t4 + 4]);
                a[mt][3] = __float_as_uint(As[r1 + 8][kb + t4 + 4]);
            }
            #pragma unroll
            for (int nt = 0; nt < 4; ++nt) {
                int rn = wn + nt * 8 + gid;
                b[nt][0] = __float_as_uint(Bs[rn][kb + t4]);
                b[nt][1] = __float_as_uint(Bs[rn][kb + t4 + 4]);
            }
            #pragma unroll
            for (int mt = 0; mt < MT; ++mt)
                #pragma unroll
                for (int nt = 0; nt < 4; ++nt)
                    mma_tf32(d[mt][nt], a[mt], b[nt]);
        }
    }

    // epilogue: c0,c1 -> (gid, 2*t4 .. +1), c2,c3 -> (gid+8, ...)
    #pragma unroll
    for (int mt = 0; mt < MT; ++mt) {
        int m1 = m0 + wm + mt * 16 + gid;
        int m2 = m1 + 8;
        float bv1 = bias[m1], bv2 = bias[m2];
        #pragma unroll
        for (int nt = 0; nt < 4; ++nt) {
            int n = n0 + wn + nt * 8 + 2 * t4;
            float c0 = d[mt][nt][0] + bv1, c1 = d[mt][nt][1] + bv1;
            float c2 = d[mt][nt][2] + bv2, c3 = d[mt][nt][3] + bv2;
            if (RELU6) {
                c0 = fminf(fmaxf(c0, 0.f), 6.f); c1 = fminf(fmaxf(c1, 0.f), 6.f);
                c2 = fminf(fmaxf(c2, 0.f), 6.f); c3 = fminf(fmaxf(c3, 0.f), 6.f);
            }
            size_t o1 = zO + (size_t)m1 * NN + n;
            size_t o2 = zO + (size_t)m2 * NN + n;
            if (ADDRES) {
                float2 r1 = *(const float2*)&R[o1];
                float2 r2 = *(const float2*)&R[o2];
                c0 += r1.x; c1 += r1.y; c2 += r2.x; c3 += r2.y;
            }
            *(float2*)&out[o1] = make_float2(c0, c1);
            *(float2*)&out[o2] = make_float2(c2, c3);
        }
    }
}

// ---------------------------------------------------------------------------
// Transpose V slice of QKV: [b][512+h*64+d][m] -> Vt[b][h][m][d]
// ---------------------------------------------------------------------------
__global__ void __launch_bounds__(256) transpose_v_kernel(
    const float* __restrict__ qkv, float* __restrict__ vt)
{
    __shared__ float tile[32][33];
    const int bh = blockIdx.z;
    const int b = bh >> 4, h = bh & 15;
    const float* src = qkv + ((size_t)b * QKV_M + 512 + h * DV) * NPOS;
    float* dst = vt + (size_t)bh * NPOS * DV;
    const int m0 = blockIdx.x * 32, d0 = blockIdx.y * 32;
    const int tx = threadIdx.x & 31, ty0 = threadIdx.x >> 5;

    #pragma unroll
    for (int ty = ty0; ty < 32; ty += 8)
        tile[ty][tx] = src[(size_t)(d0 + ty) * NPOS + m0 + tx];
    __syncthreads();
    #pragma unroll
    for (int ty = ty0; ty < 32; ty += 8)
        dst[(size_t)(m0 + ty) * DV + d0 + tx] = tile[tx][ty];
}

// ---------------------------------------------------------------------------
// Fused attention v4 (R8-proven compute); epilogue now writes O transposed
// as Ot[b][n][dh] (dh-contiguous float4) to feed the proj mma GEMM.
// ---------------------------------------------------------------------------
__global__ void __launch_bounds__(256, 4) attn4_kernel(
    const float* __restrict__ qkv, const float* __restrict__ vt,
    float* __restrict__ ot)
{
    __shared__ float Qs[16][68];
    __shared__ float Ks[16][68];
    __shared__ float Vs[64][68];
    __shared__ float St[64][68];
    __shared__ float Rp[16][68];
    __shared__ float Rinv[64];

    const int tid = threadIdx.x;
    const int rg  = tid & 15;
    const int cg  = tid >> 4;
    const int h   = blockIdx.y;
    const int r0  = blockIdx.x * 64;
    const int bz  = blockIdx.z;

    const float* qh  = qkv + (size_t)(bz * QKV_M + h * KDIM) * NPOS;
    const float* kh  = qkv + (size_t)(bz * QKV_M + 256 + h * KDIM) * NPOS;
    const float* vth = vt + (size_t)(bz * NH + h) * NPOS * DV;

    {
        int kd = tid >> 4, r4 = (tid & 15) * 4;
        float4 q = *(const float4*)&qh[(size_t)kd * NPOS + r0 + r4];
        q.x *= 4.f; q.y *= 4.f; q.z *= 4.f; q.w *= 4.f;
        *(float4*)&Qs[kd][r4] = q;
    }

    float accO[4][4];
    #pragma unroll
    for (int i = 0; i < 4; ++i)
        #pragma unroll
        for (int j = 0; j < 4; ++j) accO[i][j] = 0.f;
    float rs0 = 0.f, rs1 = 0.f, rs2 = 0.f, rs3 = 0.f;

    for (int t = 0; t < 16; ++t) {
        const int m0 = t * 64;
        __syncthreads();
        {
            int kd = tid >> 4, mq = tid & 15;
            *(float4*)&Ks[kd][mq * 4] =
                *(const float4*)&kh[(size_t)kd * NPOS + m0 + mq * 4];
        }
        #pragma unroll
        for (int p = 0; p < 4; ++p) {
            int idx = tid + p * 256;
            int mm = idx >> 4, dq = idx & 15;
            *(float4*)&Vs[mm][dq * 4] =
                *(const float4*)&vth[(size_t)(m0 + mm) * DV + dq * 4];
        }
        __syncthreads();

        float s00=0,s01=0,s02=0,s03=0, s10=0,s11=0,s12=0,s13=0;
        float s20=0,s21=0,s22=0,s23=0, s30=0,s31=0,s32=0,s33=0;
        #pragma unroll
        for (int kd = 0; kd < 16; ++kd) {
            float4 q4 = *(const float4*)&Qs[kd][rg * 4];
            float4 k4 = *(const float4*)&Ks[kd][cg * 4];
            s00 += q4.x*k4.x; s01 += q4.x*k4.y; s02 += q4.x*k4.z; s03 += q4.x*k4.w;
            s10 += q4.y*k4.x; s11 += q4.y*k4.y; s12 += q4.y*k4.z; s13 += q4.y*k4.w;
            s20 += q4.z*k4.x; s21 += q4.z*k4.y; s22 += q4.z*k4.z; s23 += q4.z*k4.w;
            s30 += q4.w*k4.x; s31 += q4.w*k4.y; s32 += q4.w*k4.z; s33 += q4.w*k4.w;
        }
        {
            float4 p;
            p.x = __expf(s00); p.y = __expf(s10); p.z = __expf(s20); p.w = __expf(s30);
            rs0 += p.x; rs1 += p.y; rs2 += p.z; rs3 += p.w;
            *(float4*)&St[cg * 4 + 0][rg * 4] = p;
            p.x = __expf(s01); p.y = __expf(s11); p.z = __expf(s21); p.w = __expf(s31);
            rs0 += p.x; rs1 += p.y; rs2 += p.z; rs3 += p.w;
            *(float4*)&St[cg * 4 + 1][rg * 4] = p;
            p.x = __expf(s02); p.y = __expf(s12); p.z = __expf(s22); p.w = __expf(s32);
            rs0 += p.x; rs1 += p.y; rs2 += p.z; rs3 += p.w;
            *(float4*)&St[cg * 4 + 2][rg * 4] = p;
            p.x = __expf(s03); p.y = __expf(s13); p.z = __expf(s23); p.w = __expf(s33);
            rs0 += p.x; rs1 += p.y; rs2 += p.z; rs3 += p.w;
            *(float4*)&St[cg * 4 + 3][rg * 4] = p;
        }
        __syncthreads();

        #pragma unroll 8
        for (int m = 0; m < 64; ++m) {
            float4 p4 = *(const float4*)&St[m][rg * 4];
            float4 v4 = *(const float4*)&Vs[m][cg * 4];
            accO[0][0] += p4.x*v4.x; accO[0][1] += p4.x*v4.y;
            accO[0][2] += p4.x*v4.z; accO[0][3] += p4.x*v4.w;
            accO[1][0] += p4.y*v4.x; accO[1][1] += p4.y*v4.y;
            accO[1][2] += p4.y*v4.z; accO[1][3] += p4.y*v4.w;
            accO[2][0] += p4.z*v4.x; accO[2][1] += p4.z*v4.y;
            accO[2][2] += p4.z*v4.z; accO[2][3] += p4.z*v4.w;
            accO[3][0] += p4.w*v4.x; accO[3][1] += p4.w*v4.y;
            accO[3][2] += p4.w*v4.z; accO[3][3] += p4.w*v4.w;
        }
    }

    *(float4*)&Rp[cg][rg * 4] = make_float4(rs0, rs1, rs2, rs3);
    __syncthreads();
    if (tid < 64) {
        float s = 0.f;
        #pragma unroll
        for (int g = 0; g < 16; ++g) s += Rp[g][tid];
        Rinv[tid] = 1.0f / s;
    }
    __syncthreads();

    const float invr[4] = {Rinv[rg*4+0], Rinv[rg*4+1], Rinv[rg*4+2], Rinv[rg*4+3]};

    // Ot[b][n][dh]: row n = r0+rg*4+i, cols h*64 + cg*4 .. +3 (float4)
    #pragma unroll
    for (int i = 0; i < 4; ++i) {
        size_t od = (size_t)bz * NPOS * DH
                  + (size_t)(r0 + rg * 4 + i) * DH + h * DV + cg * 4;
        float4 o;
        o.x = accO[i][0] * invr[i]; o.y = accO[i][1] * invr[i];
        o.z = accO[i][2] * invr[i]; o.w = accO[i][3] * invr[i];
        *(float4*)&ot[od] = o;
    }
}

// ---------------------------------------------------------------------------
// Launch
// ---------------------------------------------------------------------------
extern "C" void kernel_launch(void* const* d_in, const int* in_sizes, int n_in,
                              void* d_out, int out_size)
{
    (void)in_sizes; (void)n_in; (void)out_size;
    const float* x   = (const float*)d_in[0];
    const float* g1  = (const float*)d_in[1];
    const float* b1  = (const float*)d_in[2];
    const float* wq  = (const float*)d_in[3];
    const float* bq  = (const float*)d_in[4];
    const float* wk  = (const float*)d_in[5];
    const float* bk  = (const float*)d_in[6];
    const float* wv  = (const float*)d_in[7];
    const float* bv  = (const float*)d_in[8];
    const float* wp  = (const float*)d_in[9];
    const float* bp  = (const float*)d_in[10];
    const float* g2  = (const float*)d_in[11];
    const float* b2  = (const float*)d_in[12];
    const float* w1  = (const float*)d_in[13];
    const float* bb1 = (const float*)d_in[14];
    const float* w2  = (const float*)d_in[15];
    const float* bb2 = (const float*)d_in[16];
    float* out = (float*)d_out;

    float* base = nullptr;
    cudaGetSymbolAddress((void**)&base, g_buf);
    float* Yb   = base + OFF_Y;
    float* YTb  = base + OFF_YT;
    float* QKVb = base + OFF_QKV;
    float* OTb  = base + OFF_OT;
    float* X2b  = base + OFF_X2;
    float* Y2b  = base + OFF_Y2;
    float* Y2Tb = base + OFF_Y2T;
    float* Hb   = base + OFF_H;
    float* HTb  = base + OFF_HT;
    float* VTb  = base + OFF_VT;
    float* Wqkv = base + OFF_WQKV;
    float* Bqkv = base + OFF_BQKV;

    // 0) weight concat
    pack_qkv_kernel<<<QKV_M, 256>>>(wq, wk, wv, bq, bk, bv, Wqkv, Bqkv);

    // 1) BN1, transpose Y -> Yt [n][k]
    bn_kernel<<<CDIM, 256>>>(x, Yb, g1, b1);
    transpose_kernel<<<dim3(NPOS/32, CDIM/32, BATCH), 256>>>(Yb, YTb, CDIM, NPOS);

    // 2) fused QKV projection (mma tf32): [1536,256] x [1024,256]^T
    mma_gemm_kernel<128,0,0><<<dim3(NPOS/128, QKV_M/128, BATCH), 256>>>(
        Wqkv, YTb, Bqkv, nullptr, QKVb, QKV_M, CDIM, NPOS);

    // 3) transpose V, attention (writes Ot [n][dh])
    transpose_v_kernel<<<dim3(NPOS/32, DV/32, BATCH*NH), 256>>>(QKVb, VTb);
    attn4_kernel<<<dim3(NPOS/64, NH, BATCH), 256>>>(QKVb, VTb, OTb);

    // 4) projection (mma tf32, K=1024) + residual(x) -> X2
    mma_gemm_kernel<64,0,1><<<dim3(NPOS/128, CDIM/64, BATCH), 256>>>(
        wp, OTb, bp, x, X2b, CDIM, DH, NPOS);

    // 5) BN2, transpose Y2 -> Y2t
    bn_kernel<<<CDIM, 256>>>(X2b, Y2b, g2, b2);
    transpose_kernel<<<dim3(NPOS/32, CDIM/32, BATCH), 256>>>(Y2b, Y2Tb, CDIM, NPOS);

    // 6) MLP1 (mma tf32 + relu6) -> H [hid][n], transpose -> Ht [n][hid]
    mma_gemm_kernel<128,1,0><<<dim3(NPOS/128, HID/128, BATCH), 256>>>(
        w1, Y2Tb, bb1, nullptr, Hb, HID, CDIM, NPOS);
    transpose_kernel<<<dim3(NPOS/32, HID/32, BATCH), 256>>>(Hb, HTb, HID, NPOS);

    // 7) MLP2 (mma tf32, K=1024) + residual(X2) -> out
    mma_gemm_kernel<64,0,1><<<dim3(NPOS/128, CDIM/64, BATCH), 256>>>(
        w2, HTb, bb2, X2b, out, CDIM, HID, NPOS);
}

// round 13
// speedup vs baseline: 5.9741x; 1.5831x over previous
#include <cuda_runtime.h>
#include <cstdint>

// ---------------------------------------------------------------------------
// Problem constants
// ---------------------------------------------------------------------------
#define BATCH 8
#define CDIM  256
#define NPOS  1024
#define NH    16
#define KDIM  16
#define DV    64
#define DH    (NH*DV)       // 1024
#define HID   1024
#define QKV_M 1536

// ---------------------------------------------------------------------------
// Scratch (device global). Offsets in floats.
// ---------------------------------------------------------------------------
#define OFF_Y     0u                        // [8,256,1024]
#define OFF_YT    (OFF_Y    + 2097152u)     // [8,1024,256]   (n, k)
#define OFF_QKV   (OFF_YT   + 2097152u)     // [8,1536,1024]
#define OFF_QKT   (OFF_QKV  + 12582912u)    // [8,1024,512]   (n, qk-row)
#define OFF_OT    (OFF_QKT  + 4194304u)     // [8,1024,1024]  (n, dh)
#define OFF_X2    (OFF_OT   + 8388608u)     // [8,256,1024]
#define OFF_Y2    (OFF_X2   + 2097152u)     // [8,256,1024]
#define OFF_Y2T   (OFF_Y2   + 2097152u)     // [8,1024,256]
#define OFF_H     (OFF_Y2T  + 2097152u)     // [8,1024,1024]  (hid, n)
#define OFF_HT    (OFF_H    + 8388608u)     // [8,1024,1024]  (n, hid)
#define OFF_WQKV  (OFF_HT   + 8388608u)     // [1536,256]
#define OFF_BQKV  (OFF_WQKV + 393216u)      // [1536]
#define SCRATCH_FLOATS (OFF_BQKV + 1536u)

__device__ float g_buf[SCRATCH_FLOATS];

// ---------------------------------------------------------------------------
// tf32 mma helpers
// ---------------------------------------------------------------------------
__device__ __forceinline__ float to_tf32(float x) {
    float r;
    asm("cvt.rna.tf32.f32 %0, %1;" : "=f"(r) : "f"(x));
    return r;
}
__device__ __forceinline__ void mma_tf32(float* d, const uint32_t* a,
                                         const uint32_t* b) {
    asm volatile(
        "mma.sync.aligned.m16n8k8.row.col.f32.tf32.tf32.f32 "
        "{%0,%1,%2,%3}, {%4,%5,%6,%7}, {%8,%9}, {%0,%1,%2,%3};"
        : "+f"(d[0]), "+f"(d[1]), "+f"(d[2]), "+f"(d[3])
        : "r"(a[0]), "r"(a[1]), "r"(a[2]), "r"(a[3]), "r"(b[0]), "r"(b[1]));
}

// ---------------------------------------------------------------------------
// Concatenate wq/wk/wv (+biases) into one [1536,256] weight
// ---------------------------------------------------------------------------
__global__ void __launch_bounds__(256) pack_qkv_kernel(
    const float* __restrict__ wq, const float* __restrict__ wk,
    const float* __restrict__ wv, const float* __restrict__ bq,
    const float* __restrict__ bk, const float* __restrict__ bv,
    float* __restrict__ w, float* __restrict__ b)
{
    int row = blockIdx.x, c = threadIdx.x;
    const float* src; const float* bsrc; int r2;
    if (row < 256)      { src = wq; bsrc = bq; r2 = row; }
    else if (row < 512) { src = wk; bsrc = bk; r2 = row - 256; }
    else                { src = wv; bsrc = bv; r2 = row - 512; }
    w[(size_t)row * 256 + c] = src[(size_t)r2 * 256 + c];
    if (c == 0) b[row] = bsrc[r2];
}

// ---------------------------------------------------------------------------
// BatchNorm1d (train stats over (B,N)) + affine, float4-vectorized
// ---------------------------------------------------------------------------
__global__ void __launch_bounds__(256) bn_kernel(
    const float* __restrict__ x, float* __restrict__ y,
    const float* __restrict__ gamma, const float* __restrict__ beta)
{
    const int c = blockIdx.x, tid = threadIdx.x;
    __shared__ float sh[512];

    float s = 0.f, s2 = 0.f;
    for (int idx = tid; idx < BATCH * NPOS / 4; idx += 256) {
        int bb = idx >> 8, n4 = idx & 255;
        float4 v = *(const float4*)&x[((size_t)bb * CDIM + c) * NPOS + n4 * 4];
        s  += v.x + v.y + v.z + v.w;
        s2 += v.x*v.x + v.y*v.y + v.z*v.z + v.w*v.w;
    }
    sh[tid] = s; sh[256 + tid] = s2;
    __syncthreads();
    for (int off = 128; off; off >>= 1) {
        if (tid < off) { sh[tid] += sh[tid+off]; sh[256+tid] += sh[256+tid+off]; }
        __syncthreads();
    }
    const float inv_n = 1.0f / (float)(BATCH * NPOS);
    float mean = sh[0] * inv_n;
    float var  = sh[256] * inv_n - mean * mean;
    float scale = gamma[c] * rsqrtf(var + 1e-5f);
    float shift = beta[c] - mean * scale;

    for (int idx = tid; idx < BATCH * NPOS / 4; idx += 256) {
        int bb = idx >> 8, n4 = idx & 255;
        size_t o = ((size_t)bb * CDIM + c) * NPOS + n4 * 4;
        float4 v = *(const float4*)&x[o];
        v.x = v.x*scale+shift; v.y = v.y*scale+shift;
        v.z = v.z*scale+shift; v.w = v.w*scale+shift;
        *(float4*)&y[o] = v;
    }
}

// ---------------------------------------------------------------------------
// Batched 32x32 tiled transpose with explicit batch strides:
// src view [B][R][C] (batch stride sstr) -> dst [B][C][R] (batch stride dstr)
// grid = (C/32, R/32, B), 256 threads
// ---------------------------------------------------------------------------
__global__ void __launch_bounds__(256) transpose_b_kernel(
    const float* __restrict__ src, float* __restrict__ dst,
    int R, int C, size_t sstr, size_t dstr)
{
    __shared__ float tile[32][33];
    const int b = blockIdx.z;
    const float* s = src + (size_t)b * sstr;
    float* d = dst + (size_t)b * dstr;
    const int c0 = blockIdx.x * 32, r0 = blockIdx.y * 32;
    const int tx = threadIdx.x & 31, ty0 = threadIdx.x >> 5;

    #pragma unroll
    for (int ty = ty0; ty < 32; ty += 8)
        tile[ty][tx] = s[(size_t)(r0 + ty) * C + c0 + tx];
    __syncthreads();
    #pragma unroll
    for (int ty = ty0; ty < 32; ty += 8)
        d[(size_t)(c0 + ty) * R + r0 + tx] = tile[tx][ty];
}

// ---------------------------------------------------------------------------
// mma.sync tf32 GEMM (R11-proven): out = act(W @ Bt^T + bias) (+R)
// ---------------------------------------------------------------------------
template<int BM, int RELU6, int ADDRES>
__global__ void __launch_bounds__(256) mma_gemm_kernel(
    const float* __restrict__ W, const float* __restrict__ Bt,
    const float* __restrict__ bias, const float* __restrict__ R,
    float* __restrict__ out, int M, int K, int NN)
{
    constexpr int MT = BM / 32;
    __shared__ float As[BM][36];
    __shared__ float Bs[128][36];

    const int tid = threadIdx.x;
    const int w   = tid >> 5, lane = tid & 31;
    const int gid = lane >> 2, t4 = lane & 3;
    const int n0  = blockIdx.x * 128, m0 = blockIdx.y * BM;
    const int wm  = (w & 1) * (BM / 2);
    const int wn  = (w >> 1) * 32;
    const float* Btb = Bt + (size_t)blockIdx.z * NN * K;
    const size_t zO  = (size_t)blockIdx.z * (size_t)M * NN;

    const int lrow = tid >> 3;
    const int lq   = tid & 7;

    float d[MT][4][4];
    #pragma unroll
    for (int mt = 0; mt < MT; ++mt)
        #pragma unroll
        for (int nt = 0; nt < 4; ++nt)
            #pragma unroll
            for (int j = 0; j < 4; ++j) d[mt][nt][j] = 0.f;

    for (int kc = 0; kc < K; kc += 32) {
        __syncthreads();
        #pragma unroll
        for (int p = 0; p < BM / 32; ++p) {
            int row = lrow + p * 32;
            float4 v = *(const float4*)&W[(size_t)(m0 + row) * K + kc + lq * 4];
            v.x = to_tf32(v.x); v.y = to_tf32(v.y);
            v.z = to_tf32(v.z); v.w = to_tf32(v.w);
            *(float4*)&As[row][lq * 4] = v;
        }
        #pragma unroll
        for (int p = 0; p < 4; ++p) {
            int row = lrow + p * 32;
            float4 v = *(const float4*)&Btb[(size_t)(n0 + row) * K + kc + lq * 4];
            v.x = to_tf32(v.x); v.y = to_tf32(v.y);
            v.z = to_tf32(v.z); v.w = to_tf32(v.w);
            *(float4*)&Bs[row][lq * 4] = v;
        }
        __syncthreads();

        #pragma unroll
        for (int k8 = 0; k8 < 4; ++k8) {
            const int kb = k8 * 8;
            uint32_t a[MT][4], b[4][2];
            #pragma unroll
            for (int mt = 0; mt < MT; ++mt) {
                int r1 = wm + mt * 16 + gid;
                a[mt][0] = __float_as_uint(As[r1][kb + t4]);
                a[mt][1] = __float_as_uint(As[r1 + 8][kb + t4]);
                a[mt][2] = __float_as_uint(As[r1][kb + t4 + 4]);
                a[mt][3] = __float_as_uint(As[r1 + 8][kb + t4 + 4]);
            }
            #pragma unroll
            for (int nt = 0; nt < 4; ++nt) {
                int rn = wn + nt * 8 + gid;
                b[nt][0] = __float_as_uint(Bs[rn][kb + t4]);
                b[nt][1] = __float_as_uint(Bs[rn][kb + t4 + 4]);
            }
            #pragma unroll
            for (int mt = 0; mt < MT; ++mt)
                #pragma unroll
                for (int nt = 0; nt < 4; ++nt)
                    mma_tf32(d[mt][nt], a[mt], b[nt]);
        }
    }

    #pragma unroll
    for (int mt = 0; mt < MT; ++mt) {
        int m1 = m0 + wm + mt * 16 + gid;
        int m2 = m1 + 8;
        float bv1 = bias[m1], bv2 = bias[m2];
        #pragma unroll
        for (int nt = 0; nt < 4; ++nt) {
            int n = n0 + wn + nt * 8 + 2 * t4;
            float c0 = d[mt][nt][0] + bv1, c1 = d[mt][nt][1] + bv1;
            float c2 = d[mt][nt][2] + bv2, c3 = d[mt][nt][3] + bv2;
            if (RELU6) {
                c0 = fminf(fmaxf(c0, 0.f), 6.f); c1 = fminf(fmaxf(c1, 0.f), 6.f);
                c2 = fminf(fmaxf(c2, 0.f), 6.f); c3 = fminf(fmaxf(c3, 0.f), 6.f);
            }
            size_t o1 = zO + (size_t)m1 * NN + n;
            size_t o2 = zO + (size_t)m2 * NN + n;
            if (ADDRES) {
                float2 r1 = *(const float2*)&R[o1];
                float2 r2 = *(const float2*)&R[o2];
                c0 += r1.x; c1 += r1.y; c2 += r2.x; c3 += r2.y;
            }
            *(float2*)&out[o1] = make_float2(c0, c1);
            *(float2*)&out[o2] = make_float2(c2, c3);
        }
    }
}

// ---------------------------------------------------------------------------
// Fused attention v5: QK^T and PV on tf32 mma.sync.
// Block = (b, h, 64 q-rows), 256 threads = 8 warps: wm=(w&3)*16 rows,
// wn=(w>>2)*32 cols. m-tiles of 64 keys, 16 tiles.
// Q,K from pre-transposed QKt[b][n][512]; V used in original [d][m] layout
// (exactly the col-major B operand PV needs).
// ---------------------------------------------------------------------------
__global__ void __launch_bounds__(256) attn5_kernel(
    const float* __restrict__ qkv, const float* __restrict__ qkt,
    float* __restrict__ ot)
{
    __shared__ float Qs[64][20];
    __shared__ float Ks[64][20];
    __shared__ float Vs[64][68];
    __shared__ float Ps[64][68];
    __shared__ float Rpart[8][16];
    __shared__ float Rinv[64];

    const int tid  = threadIdx.x;
    const int w    = tid >> 5, lane = tid & 31;
    const int gid  = lane >> 2, t4 = lane & 3;
    const int wm   = (w & 3) * 16;
    const int wn   = (w >> 2) * 32;
    const int h    = blockIdx.y;
    const int r0   = blockIdx.x * 64;
    const int bz   = blockIdx.z;

    const float* qktb = qkt + (size_t)bz * NPOS * 512;
    const float* vh   = qkv + (size_t)(bz * QKV_M + 512 + h * DV) * NPOS;

    // Q tile [64][16] (tf32, sqrt(kd)=4 folded): 1 float4/thread
    {
        int r = tid >> 2, q4 = tid & 3;
        float4 q = *(const float4*)&qktb[(size_t)(r0 + r) * 512 + h * KDIM + q4 * 4];
        q.x = to_tf32(q.x * 4.f); q.y = to_tf32(q.y * 4.f);
        q.z = to_tf32(q.z * 4.f); q.w = to_tf32(q.w * 4.f);
        *(float4*)&Qs[r][q4 * 4] = q;
    }

    float acc[4][4];
    #pragma unroll
    for (int nt = 0; nt < 4; ++nt)
        #pragma unroll
        for (int j = 0; j < 4; ++j) acc[nt][j] = 0.f;
    float rs_lo = 0.f, rs_hi = 0.f;

    for (int t = 0; t < 16; ++t) {
        const int m0 = t * 64;
        __syncthreads();
        // K tile [64][16] from QKt cols 256+h*16: 1 float4/thread
        {
            int m = tid >> 2, q4 = tid & 3;
            float4 k = *(const float4*)&qktb[(size_t)(m0 + m) * 512 + 256 + h * KDIM + q4 * 4];
            k.x = to_tf32(k.x); k.y = to_tf32(k.y);
            k.z = to_tf32(k.z); k.w = to_tf32(k.w);
            *(float4*)&Ks[m][q4 * 4] = k;
        }
        // V tile [64 d][64 m]: 4 float4/thread (coalesced on m)
        #pragma unroll
        for (int p = 0; p < 4; ++p) {
            int idx = tid + p * 256;
            int dd = idx >> 4, mq = idx & 15;
            float4 v = *(const float4*)&vh[(size_t)dd * NPOS + m0 + mq * 4];
            v.x = to_tf32(v.x); v.y = to_tf32(v.y);
            v.z = to_tf32(v.z); v.w = to_tf32(v.w);
            *(float4*)&Vs[dd][mq * 4] = v;
        }
        __syncthreads();

        // QK: 4 n-tiles x 2 k8 steps; exp + tf32 P store
        #pragma unroll
        for (int nt = 0; nt < 4; ++nt) {
            float s[4] = {0.f, 0.f, 0.f, 0.f};
            #pragma unroll
            for (int k8 = 0; k8 < 2; ++k8) {
                const int kb = k8 * 8;
                uint32_t a[4], b[2];
                a[0] = __float_as_uint(Qs[wm + gid][kb + t4]);
                a[1] = __float_as_uint(Qs[wm + gid + 8][kb + t4]);
                a[2] = __float_as_uint(Qs[wm + gid][kb + t4 + 4]);
                a[3] = __float_as_uint(Qs[wm + gid + 8][kb + t4 + 4]);
                int rn = wn + nt * 8 + gid;
                b[0] = __float_as_uint(Ks[rn][kb + t4]);
                b[1] = __float_as_uint(Ks[rn][kb + t4 + 4]);
                mma_tf32(s, a, b);
            }
            float e0 = __expf(s[0]), e1 = __expf(s[1]);
            float e2 = __expf(s[2]), e3 = __expf(s[3]);
            rs_lo += e0 + e1; rs_hi += e2 + e3;
            *(float2*)&Ps[wm + gid][wn + nt * 8 + 2 * t4] =
                make_float2(to_tf32(e0), to_tf32(e1));
            *(float2*)&Ps[wm + gid + 8][wn + nt * 8 + 2 * t4] =
                make_float2(to_tf32(e2), to_tf32(e3));
        }
        __syncthreads();

        // PV: 8 k8 steps x 4 n-tiles into persistent acc
        #pragma unroll
        for (int k8 = 0; k8 < 8; ++k8) {
            const int kb = k8 * 8;
            uint32_t a[4];
            a[0] = __float_as_uint(Ps[wm + gid][kb + t4]);
            a[1] = __float_as_uint(Ps[wm + gid + 8][kb + t4]);
            a[2] = __float_as_uint(Ps[wm + gid][kb + t4 + 4]);
            a[3] = __float_as_uint(Ps[wm + gid + 8][kb + t4 + 4]);
            #pragma unroll
            for (int nt = 0; nt < 4; ++nt) {
                uint32_t b[2];
                int rd = wn + nt * 8 + gid;
                b[0] = __float_as_uint(Vs[rd][kb + t4]);
                b[1] = __float_as_uint(Vs[rd][kb + t4 + 4]);
                mma_tf32(acc[nt], a, b);
            }
        }
    }

    // row sums: reduce over t4 lanes, then across the two col-half warps
    rs_lo += __shfl_xor_sync(0xffffffffu, rs_lo, 1);
    rs_lo += __shfl_xor_sync(0xffffffffu, rs_lo, 2);
    rs_hi += __shfl_xor_sync(0xffffffffu, rs_hi, 1);
    rs_hi += __shfl_xor_sync(0xffffffffu, rs_hi, 2);
    if (t4 == 0) {
        Rpart[w][gid] = rs_lo;
        Rpart[w][8 + gid] = rs_hi;
    }
    __syncthreads();
    if (tid < 64) {
        int w1 = tid >> 4;
        Rinv[tid] = 1.0f / (Rpart[w1][tid & 15] + Rpart[w1 + 4][tid & 15]);
    }
    __syncthreads();

    const float i_lo = Rinv[wm + gid];
    const float i_hi = Rinv[wm + gid + 8];
    const size_t obase = (size_t)bz * NPOS * DH;
    #pragma unroll
    for (int nt = 0; nt < 4; ++nt) {
        int d = h * DV + wn + nt * 8 + 2 * t4;
        *(float2*)&ot[obase + (size_t)(r0 + wm + gid) * DH + d] =
            make_float2(acc[nt][0] * i_lo, acc[nt][1] * i_lo);
        *(float2*)&ot[obase + (size_t)(r0 + wm + gid + 8) * DH + d] =
            make_float2(acc[nt][2] * i_hi, acc[nt][3] * i_hi);
    }
}

// ---------------------------------------------------------------------------
// Launch
// ---------------------------------------------------------------------------
extern "C" void kernel_launch(void* const* d_in, const int* in_sizes, int n_in,
                              void* d_out, int out_size)
{
    (void)in_sizes; (void)n_in; (void)out_size;
    const float* x   = (const float*)d_in[0];
    const float* g1  = (const float*)d_in[1];
    const float* b1  = (const float*)d_in[2];
    const float* wq  = (const float*)d_in[3];
    const float* bq  = (const float*)d_in[4];
    const float* wk  = (const float*)d_in[5];
    const float* bk  = (const float*)d_in[6];
    const float* wv  = (const float*)d_in[7];
    const float* bv  = (const float*)d_in[8];
    const float* wp  = (const float*)d_in[9];
    const float* bp  = (const float*)d_in[10];
    const float* g2  = (const float*)d_in[11];
    const float* b2  = (const float*)d_in[12];
    const float* w1  = (const float*)d_in[13];
    const float* bb1 = (const float*)d_in[14];
    const float* w2  = (const float*)d_in[15];
    const float* bb2 = (const float*)d_in[16];
    float* out = (float*)d_out;

    float* base = nullptr;
    cudaGetSymbolAddress((void**)&base, g_buf);
    float* Yb   = base + OFF_Y;
    float* YTb  = base + OFF_YT;
    float* QKVb = base + OFF_QKV;
    float* QKTb = base + OFF_QKT;
    float* OTb  = base + OFF_OT;
    float* X2b  = base + OFF_X2;
    float* Y2b  = base + OFF_Y2;
    float* Y2Tb = base + OFF_Y2T;
    float* Hb   = base + OFF_H;
    float* HTb  = base + OFF_HT;
    float* Wqkv = base + OFF_WQKV;
    float* Bqkv = base + OFF_BQKV;

    // 0) weight concat
    pack_qkv_kernel<<<QKV_M, 256>>>(wq, wk, wv, bq, bk, bv, Wqkv, Bqkv);

    // 1) BN1, transpose Y -> Yt [n][k]
    bn_kernel<<<CDIM, 256>>>(x, Yb, g1, b1);
    transpose_b_kernel<<<dim3(NPOS/32, CDIM/32, BATCH), 256>>>(
        Yb, YTb, CDIM, NPOS, (size_t)CDIM*NPOS, (size_t)CDIM*NPOS);

    // 2) fused QKV projection (mma tf32)
    mma_gemm_kernel<128,0,0><<<dim3(NPOS/128, QKV_M/128, BATCH), 256>>>(
        Wqkv, YTb, Bqkv, nullptr, QKVb, QKV_M, CDIM, NPOS);

    // 3) transpose QK rows (512 rows) -> QKt [n][512], then attention (mma)
    transpose_b_kernel<<<dim3(NPOS/32, 512/32, BATCH), 256>>>(
        QKVb, QKTb, 512, NPOS, (size_t)QKV_M*NPOS, (size_t)512*NPOS);
    attn5_kernel<<<dim3(NPOS/64, NH, BATCH), 256>>>(QKVb, QKTb, OTb);

    // 4) projection (mma tf32, K=1024) + residual(x) -> X2
    mma_gemm_kernel<64,0,1><<<dim3(NPOS/128, CDIM/64, BATCH), 256>>>(
        wp, OTb, bp, x, X2b, CDIM, DH, NPOS);

    // 5) BN2, transpose Y2 -> Y2t
    bn_kernel<<<CDIM, 256>>>(X2b, Y2b, g2, b2);
    transpose_b_kernel<<<dim3(NPOS/32, CDIM/32, BATCH), 256>>>(
        Y2b, Y2Tb, CDIM, NPOS, (size_t)CDIM*NPOS, (size_t)CDIM*NPOS);

    // 6) MLP1 (mma tf32 + relu6) -> H [hid][n], transpose -> Ht [n][hid]
    mma_gemm_kernel<128,1,0><<<dim3(NPOS/128, HID/128, BATCH), 256>>>(
        w1, Y2Tb, bb1, nullptr, Hb, HID, CDIM, NPOS);
    transpose_b_kernel<<<dim3(NPOS/32, HID/32, BATCH), 256>>>(
        Hb, HTb, HID, NPOS, (size_t)HID*NPOS, (size_t)HID*NPOS);

    // 7) MLP2 (mma tf32, K=1024) + residual(X2) -> out
    mma_gemm_kernel<64,0,1><<<dim3(NPOS/128, CDIM/64, BATCH), 256>>>(
        w2, HTb, bb2, X2b, out, CDIM, HID, NPOS);
}

// round 15
// speedup vs baseline: 6.3240x; 1.0586x over previous
#include <cuda_runtime.h>
#include <cstdint>

// ---------------------------------------------------------------------------
// Problem constants
// ---------------------------------------------------------------------------
#define BATCH 8
#define CDIM  256
#define NPOS  1024
#define NH    16
#define KDIM  16
#define DV    64
#define DH    (NH*DV)       // 1024
#define HID   1024
#define QKV_M 1536

// ---------------------------------------------------------------------------
// Scratch (device global). Offsets in floats.
// ---------------------------------------------------------------------------
#define OFF_SC    0u                        // scale/shift [2][256]
#define OFF_YT    (OFF_SC   + 1024u)        // [8,1024,256]   (n, k)
#define OFF_QKV   (OFF_YT   + 2097152u)     // [8,1536,1024]
#define OFF_QKT   (OFF_QKV  + 12582912u)    // [8,1024,512]   (n, qk-row)
#define OFF_OT    (OFF_QKT  + 4194304u)     // [8,1024,1024]  (n, dh)
#define OFF_X2    (OFF_OT   + 8388608u)     // [8,256,1024]
#define OFF_Y2T   (OFF_X2   + 2097152u)     // [8,1024,256]
#define OFF_H     (OFF_Y2T  + 2097152u)     // [8,1024,1024]  (hid, n)
#define OFF_WQKV  (OFF_H    + 8388608u)     // [1536,256]
#define OFF_BQKV  (OFF_WQKV + 393216u)      // [1536]
#define SCRATCH_FLOATS (OFF_BQKV + 1536u)

__device__ float g_buf[SCRATCH_FLOATS];

// ---------------------------------------------------------------------------
// helpers
// ---------------------------------------------------------------------------
__device__ __forceinline__ uint32_t smem_u32(const void* p) {
    uint32_t a;
    asm("{ .reg .u64 t; cvta.to.shared.u64 t, %1; cvt.u32.u64 %0, t; }"
        : "=r"(a) : "l"(p));
    return a;
}
__device__ __forceinline__ float to_tf32(float x) {
    float r;
    asm("cvt.rna.tf32.f32 %0, %1;" : "=f"(r) : "f"(x));
    return r;
}
__device__ __forceinline__ void mma_tf32(float* d, const uint32_t* a,
                                         const uint32_t* b) {
    asm volatile(
        "mma.sync.aligned.m16n8k8.row.col.f32.tf32.tf32.f32 "
        "{%0,%1,%2,%3}, {%4,%5,%6,%7}, {%8,%9}, {%0,%1,%2,%3};"
        : "+f"(d[0]), "+f"(d[1]), "+f"(d[2]), "+f"(d[3])
        : "r"(a[0]), "r"(a[1]), "r"(a[2]), "r"(a[3]), "r"(b[0]), "r"(b[1]));
}
#define CP_ASYNC16(dst, src) \
    asm volatile("cp.async.cg.shared.global [%0], [%1], 16;" \
                 :: "r"(dst), "l"(src) : "memory")
#define CP_COMMIT() asm volatile("cp.async.commit_group;" ::: "memory")
#define CP_WAIT0()  asm volatile("cp.async.wait_group 0;" ::: "memory")

// ---------------------------------------------------------------------------
// Concatenate wq/wk/wv (+biases) into one [1536,256] weight
// ---------------------------------------------------------------------------
__global__ void __launch_bounds__(256) pack_qkv_kernel(
    const float* __restrict__ wq, const float* __restrict__ wk,
    const float* __restrict__ wv, const float* __restrict__ bq,
    const float* __restrict__ bk, const float* __restrict__ bv,
    float* __restrict__ w, float* __restrict__ b)
{
    int row = blockIdx.x, c = threadIdx.x;
    const float* src; const float* bsrc; int r2;
    if (row < 256)      { src = wq; bsrc = bq; r2 = row; }
    else if (row < 512) { src = wk; bsrc = bk; r2 = row - 256; }
    else                { src = wv; bsrc = bv; r2 = row - 512; }
    w[(size_t)row * 256 + c] = src[(size_t)r2 * 256 + c];
    if (c == 0) b[row] = bsrc[r2];
}

// ---------------------------------------------------------------------------
// BN stats: per-channel scale/shift (train-mode stats over (B,N))
// grid = CDIM, 256 threads
// ---------------------------------------------------------------------------
__global__ void __launch_bounds__(256) bn_stats_kernel(
    const float* __restrict__ x, const float* __restrict__ gamma,
    const float* __restrict__ beta, float* __restrict__ scale,
    float* __restrict__ shift)
{
    const int c = blockIdx.x, tid = threadIdx.x;
    __shared__ float sh[512];

    float s = 0.f, s2 = 0.f;
    for (int idx = tid; idx < BATCH * NPOS / 4; idx += 256) {
        int bb = idx >> 8, n4 = idx & 255;
        float4 v = *(const float4*)&x[((size_t)bb * CDIM + c) * NPOS + n4 * 4];
        s  += v.x + v.y + v.z + v.w;
        s2 += v.x*v.x + v.y*v.y + v.z*v.z + v.w*v.w;
    }
    sh[tid] = s; sh[256 + tid] = s2;
    __syncthreads();
    for (int off = 128; off; off >>= 1) {
        if (tid < off) { sh[tid] += sh[tid+off]; sh[256+tid] += sh[256+tid+off]; }
        __syncthreads();
    }
    if (tid == 0) {
        const float inv_n = 1.0f / (float)(BATCH * NPOS);
        float mean = sh[0] * inv_n;
        float var  = sh[256] * inv_n - mean * mean;
        float sc = gamma[c] * rsqrtf(var + 1e-5f);
        scale[c] = sc;
        shift[c] = beta[c] - mean * sc;
    }
}

// ---------------------------------------------------------------------------
// Fused BN-apply + transpose: x[b][c][n] -> yt[b][n][c] = x*scale[c]+shift[c]
// grid = (NPOS/32, CDIM/32, BATCH), 256 threads
// ---------------------------------------------------------------------------
__global__ void __launch_bounds__(256) bnt_apply_kernel(
    const float* __restrict__ x, const float* __restrict__ scale,
    const float* __restrict__ shift, float* __restrict__ yt)
{
    __shared__ float tile[32][33];
    const int b = blockIdx.z;
    const float* s = x + (size_t)b * CDIM * NPOS;
    float* d = yt + (size_t)b * NPOS * CDIM;
    const int n0 = blockIdx.x * 32, c0 = blockIdx.y * 32;
    const int tx = threadIdx.x & 31, ty0 = threadIdx.x >> 5;

    #pragma unroll
    for (int ty = ty0; ty < 32; ty += 8) {
        int c = c0 + ty;
        tile[ty][tx] = s[(size_t)c * NPOS + n0 + tx] * scale[c] + shift[c];
    }
    __syncthreads();
    #pragma unroll
    for (int ty = ty0; ty < 32; ty += 8)
        d[(size_t)(n0 + ty) * CDIM + c0 + tx] = tile[tx][ty];
}

// ---------------------------------------------------------------------------
// Plain batched 32x32 transpose with explicit strides (for QKT)
// ---------------------------------------------------------------------------
__global__ void __launch_bounds__(256) transpose_b_kernel(
    const float* __restrict__ src, float* __restrict__ dst,
    int R, int C, size_t sstr, size_t dstr)
{
    __shared__ float tile[32][33];
    const int b = blockIdx.z;
    const float* s = src + (size_t)b * sstr;
    float* d = dst + (size_t)b * dstr;
    const int c0 = blockIdx.x * 32, r0 = blockIdx.y * 32;
    const int tx = threadIdx.x & 31, ty0 = threadIdx.x >> 5;

    #pragma unroll
    for (int ty = ty0; ty < 32; ty += 8)
        tile[ty][tx] = s[(size_t)(r0 + ty) * C + c0 + tx];
    __syncthreads();
    #pragma unroll
    for (int ty = ty0; ty < 32; ty += 8)
        d[(size_t)(c0 + ty) * R + r0 + tx] = tile[tx][ty];
}

// ---------------------------------------------------------------------------
// mma2: cp.async double-buffered tf32 GEMM.
// out[z][m][n] = act(sum_k W[m][k] * B(k,n) + bias[m]) (+R)
// BROW=0: B = Bt[NN][K] (col-major B). BROW=1: B = [K][NN] (row-major B).
// Block BM x 128, 256 thr = 8 warps (2m x 4n). K % 32 == 0.
// Dynamic smem: As[2][BM][36], Bs[2][128][36] or Bs[2][32][136].
// NOTE: tf32 rounding is HW truncation here (no cvt on the cp.async path).
// ---------------------------------------------------------------------------
template<int BM, int BROW, int RELU6, int ADDRES>
__global__ void __launch_bounds__(256) mma2_kernel(
    const float* __restrict__ W, const float* __restrict__ B,
    const float* __restrict__ bias, const float* __restrict__ R,
    float* __restrict__ out, int M, int K, int NN)
{
    constexpr int MT   = BM / 32;
    constexpr int ASTR = BM * 36;
    constexpr int BSTR = BROW ? 32 * 136 : 128 * 36;
    extern __shared__ float dsm[];
    float* As = dsm;
    float* Bs = dsm + 2 * ASTR;

    const int tid  = threadIdx.x;
    const int w    = tid >> 5, lane = tid & 31;
    const int gid  = lane >> 2, t4 = lane & 3;
    const int n0   = blockIdx.x * 128, m0 = blockIdx.y * BM;
    const int wm   = (w & 1) * (BM / 2);
    const int wn   = (w >> 1) * 32;
    const float* Bb = B + (size_t)blockIdx.z * (size_t)NN * K;
    const size_t zO = (size_t)blockIdx.z * (size_t)M * NN;

    const uint32_t as_base = smem_u32(As);
    const uint32_t bs_base = smem_u32(Bs);
    const int lrow = tid >> 3, lq = tid & 7;
    const int kr = tid >> 5, nq = tid & 31;

    float d[MT][4][4];
    #pragma unroll
    for (int mt = 0; mt < MT; ++mt)
        #pragma unroll
        for (int nt = 0; nt < 4; ++nt)
            #pragma unroll
            for (int j = 0; j < 4; ++j) d[mt][nt][j] = 0.f;

    auto load_tile = [&](int buf, int kc) {
        #pragma unroll
        for (int p = 0; p < BM / 32; ++p) {
            int row = lrow + p * 32;
            uint32_t dst = as_base + (uint32_t)((buf * ASTR + row * 36 + lq * 4) * 4);
            CP_ASYNC16(dst, &W[(size_t)(m0 + row) * K + kc + lq * 4]);
        }
        if (BROW == 0) {
            #pragma unroll
            for (int p = 0; p < 4; ++p) {
                int row = lrow + p * 32;
                uint32_t dst = bs_base + (uint32_t)((buf * BSTR + row * 36 + lq * 4) * 4);
                CP_ASYNC16(dst, &Bb[(size_t)(n0 + row) * K + kc + lq * 4]);
            }
        } else {
            #pragma unroll
            for (int p = 0; p < 4; ++p) {
                int k = kr + p * 8;
                uint32_t dst = bs_base + (uint32_t)((buf * BSTR + k * 136 + nq * 4) * 4);
                CP_ASYNC16(dst, &Bb[(size_t)(kc + k) * NN + n0 + nq * 4]);
            }
        }
    };

    load_tile(0, 0);
    CP_COMMIT();
    CP_WAIT0();
    __syncthreads();

    const int ntiles = K >> 5;
    int buf = 0;
    for (int t = 0; t < ntiles; ++t) {
        if (t + 1 < ntiles) { load_tile(buf ^ 1, (t + 1) * 32); CP_COMMIT(); }

        const float* Ab = As + buf * ASTR;
        const float* Bc = Bs + buf * BSTR;
        #pragma unroll
        for (int k8 = 0; k8 < 4; ++k8) {
            const int kb = k8 * 8;
            uint32_t a[MT][4], b[4][2];
            #pragma unroll
            for (int mt = 0; mt < MT; ++mt) {
                int r1 = wm + mt * 16 + gid;
                a[mt][0] = __float_as_uint(Ab[r1 * 36 + kb + t4]);
                a[mt][1] = __float_as_uint(Ab[(r1 + 8) * 36 + kb + t4]);
                a[mt][2] = __float_as_uint(Ab[r1 * 36 + kb + t4 + 4]);
                a[mt][3] = __float_as_uint(Ab[(r1 + 8) * 36 + kb + t4 + 4]);
            }
            #pragma unroll
            for (int nt = 0; nt < 4; ++nt) {
                int rn = wn + nt * 8 + gid;
                if (BROW == 0) {
                    b[nt][0] = __float_as_uint(Bc[rn * 36 + kb + t4]);
                    b[nt][1] = __float_as_uint(Bc[rn * 36 + kb + t4 + 4]);
                } else {
                    b[nt][0] = __float_as_uint(Bc[(kb + t4) * 136 + rn]);
                    b[nt][1] = __float_as_uint(Bc[(kb + t4 + 4) * 136 + rn]);
                }
            }
            #pragma unroll
            for (int mt = 0; mt < MT; ++mt)
                #pragma unroll
                for (int nt = 0; nt < 4; ++nt)
                    mma_tf32(d[mt][nt], a[mt], b[nt]);
        }

        if (t + 1 < ntiles) CP_WAIT0();
        __syncthreads();
        buf ^= 1;
    }

    #pragma unroll
    for (int mt = 0; mt < MT; ++mt) {
        int m1 = m0 + wm + mt * 16 + gid;
        int m2 = m1 + 8;
        float bv1 = bias[m1], bv2 = bias[m2];
        #pragma unroll
        for (int nt = 0; nt < 4; ++nt) {
            int n = n0 + wn + nt * 8 + 2 * t4;
            float c0 = d[mt][nt][0] + bv1, c1 = d[mt][nt][1] + bv1;
            float c2 = d[mt][nt][2] + bv2, c3 = d[mt][nt][3] + bv2;
            if (RELU6) {
                c0 = fminf(fmaxf(c0, 0.f), 6.f); c1 = fminf(fmaxf(c1, 0.f), 6.f);
                c2 = fminf(fmaxf(c2, 0.f), 6.f); c3 = fminf(fmaxf(c3, 0.f), 6.f);
            }
            size_t o1 = zO + (size_t)m1 * NN + n;
            size_t o2 = zO + (size_t)m2 * NN + n;
            if (ADDRES) {
                float2 r1 = *(const float2*)&R[o1];
                float2 r2 = *(const float2*)&R[o2];
                c0 += r1.x; c1 += r1.y; c2 += r2.x; c3 += r2.y;
            }
            *(float2*)&out[o1] = make_float2(c0, c1);
            *(float2*)&out[o2] = make_float2(c2, c3);
        }
    }
}

// ---------------------------------------------------------------------------
// Fused attention v5 (R13-proven): QK^T and PV on tf32 mma.sync.
// ---------------------------------------------------------------------------
__global__ void __launch_bounds__(256) attn5_kernel(
    const float* __restrict__ qkv, const float* __restrict__ qkt,
    float* __restrict__ ot)
{
    __shared__ float Qs[64][20];
    __shared__ float Ks[64][20];
    __shared__ float Vs[64][68];
    __shared__ float Ps[64][68];
    __shared__ float Rpart[8][16];
    __shared__ float Rinv[64];

    const int tid  = threadIdx.x;
    const int w    = tid >> 5, lane = tid & 31;
    const int gid  = lane >> 2, t4 = lane & 3;
    const int wm   = (w & 3) * 16;
    const int wn   = (w >> 2) * 32;
    const int h    = blockIdx.y;
    const int r0   = blockIdx.x * 64;
    const int bz   = blockIdx.z;

    const float* qktb = qkt + (size_t)bz * NPOS * 512;
    const float* vh   = qkv + (size_t)(bz * QKV_M + 512 + h * DV) * NPOS;

    {
        int r = tid >> 2, q4 = tid & 3;
        float4 q = *(const float4*)&qktb[(size_t)(r0 + r) * 512 + h * KDIM + q4 * 4];
        q.x = to_tf32(q.x * 4.f); q.y = to_tf32(q.y * 4.f);
        q.z = to_tf32(q.z * 4.f); q.w = to_tf32(q.w * 4.f);
        *(float4*)&Qs[r][q4 * 4] = q;
    }

    float acc[4][4];
    #pragma unroll
    for (int nt = 0; nt < 4; ++nt)
        #pragma unroll
        for (int j = 0; j < 4; ++j) acc[nt][j] = 0.f;
    float rs_lo = 0.f, rs_hi = 0.f;

    for (int t = 0; t < 16; ++t) {
        const int m0 = t * 64;
        __syncthreads();
        {
            int m = tid >> 2, q4 = tid & 3;
            float4 k = *(const float4*)&qktb[(size_t)(m0 + m) * 512 + 256 + h * KDIM + q4 * 4];
            k.x = to_tf32(k.x); k.y = to_tf32(k.y);
            k.z = to_tf32(k.z); k.w = to_tf32(k.w);
            *(float4*)&Ks[m][q4 * 4] = k;
        }
        #pragma unroll
        for (int p = 0; p < 4; ++p) {
            int idx = tid + p * 256;
            int dd = idx >> 4, mq = idx & 15;
            float4 v = *(const float4*)&vh[(size_t)dd * NPOS + m0 + mq * 4];
            v.x = to_tf32(v.x); v.y = to_tf32(v.y);
            v.z = to_tf32(v.z); v.w = to_tf32(v.w);
            *(float4*)&Vs[dd][mq * 4] = v;
        }
        __syncthreads();

        #pragma unroll
        for (int nt = 0; nt < 4; ++nt) {
            float s[4] = {0.f, 0.f, 0.f, 0.f};
            #pragma unroll
            for (int k8 = 0; k8 < 2; ++k8) {
                const int kb = k8 * 8;
                uint32_t a[4], b[2];
                a[0] = __float_as_uint(Qs[wm + gid][kb + t4]);
                a[1] = __float_as_uint(Qs[wm + gid + 8][kb + t4]);
                a[2] = __float_as_uint(Qs[wm + gid][kb + t4 + 4]);
                a[3] = __float_as_uint(Qs[wm + gid + 8][kb + t4 + 4]);
                int rn = wn + nt * 8 + gid;
                b[0] = __float_as_uint(Ks[rn][kb + t4]);
                b[1] = __float_as_uint(Ks[rn][kb + t4 + 4]);
                mma_tf32(s, a, b);
            }
            float e0 = __expf(s[0]), e1 = __expf(s[1]);
            float e2 = __expf(s[2]), e3 = __expf(s[3]);
            rs_lo += e0 + e1; rs_hi += e2 + e3;
            *(float2*)&Ps[wm + gid][wn + nt * 8 + 2 * t4] =
                make_float2(to_tf32(e0), to_tf32(e1));
            *(float2*)&Ps[wm + gid + 8][wn + nt * 8 + 2 * t4] =
                make_float2(to_tf32(e2), to_tf32(e3));
        }
        __syncthreads();

        #pragma unroll
        for (int k8 = 0; k8 < 8; ++k8) {
            const int kb = k8 * 8;
            uint32_t a[4];
            a[0] = __float_as_uint(Ps[wm + gid][kb + t4]);
            a[1] = __float_as_uint(Ps[wm + gid + 8][kb + t4]);
            a[2] = __float_as_uint(Ps[wm + gid][kb + t4 + 4]);
            a[3] = __float_as_uint(Ps[wm + gid + 8][kb + t4 + 4]);
            #pragma unroll
            for (int nt = 0; nt < 4; ++nt) {
                uint32_t b[2];
                int rd = wn + nt * 8 + gid;
                b[0] = __float_as_uint(Vs[rd][kb + t4]);
                b[1] = __float_as_uint(Vs[rd][kb + t4 + 4]);
                mma_tf32(acc[nt], a, b);
            }
        }
    }

    rs_lo += __shfl_xor_sync(0xffffffffu, rs_lo, 1);
    rs_lo += __shfl_xor_sync(0xffffffffu, rs_lo, 2);
    rs_hi += __shfl_xor_sync(0xffffffffu, rs_hi, 1);
    rs_hi += __shfl_xor_sync(0xffffffffu, rs_hi, 2);
    if (t4 == 0) {
        Rpart[w][gid] = rs_lo;
        Rpart[w][8 + gid] = rs_hi;
    }
    __syncthreads();
    if (tid < 64) {
        int w1 = tid >> 4;
        Rinv[tid] = 1.0f / (Rpart[w1][tid & 15] + Rpart[w1 + 4][tid & 15]);
    }
    __syncthreads();

    const float i_lo = Rinv[wm + gid];
    const float i_hi = Rinv[wm + gid + 8];
    const size_t obase = (size_t)bz * NPOS * DH;
    #pragma unroll
    for (int nt = 0; nt < 4; ++nt) {
        int d = h * DV + wn + nt * 8 + 2 * t4;
        *(float2*)&ot[obase + (size_t)(r0 + wm + gid) * DH + d] =
            make_float2(acc[nt][0] * i_lo, acc[nt][1] * i_lo);
        *(float2*)&ot[obase + (size_t)(r0 + wm + gid + 8) * DH + d] =
            make_float2(acc[nt][2] * i_hi, acc[nt][3] * i_hi);
    }
}

// ---------------------------------------------------------------------------
// Launch
// ---------------------------------------------------------------------------
extern "C" void kernel_launch(void* const* d_in, const int* in_sizes, int n_in,
                              void* d_out, int out_size)
{
    (void)in_sizes; (void)n_in; (void)out_size;
    const float* x   = (const float*)d_in[0];
    const float* g1  = (const float*)d_in[1];
    const float* b1  = (const float*)d_in[2];
    const float* wq  = (const float*)d_in[3];
    const float* bq  = (const float*)d_in[4];
    const float* wk  = (const float*)d_in[5];
    const float* bk  = (const float*)d_in[6];
    const float* wv  = (const float*)d_in[7];
    const float* bv  = (const float*)d_in[8];
    const float* wp  = (const float*)d_in[9];
    const float* bp  = (const float*)d_in[10];
    const float* g2  = (const float*)d_in[11];
    const float* b2  = (const float*)d_in[12];
    const float* w1  = (const float*)d_in[13];
    const float* bb1 = (const float*)d_in[14];
    const float* w2  = (const float*)d_in[15];
    const float* bb2 = (const float*)d_in[16];
    float* out = (float*)d_out;

    float* base = nullptr;
    cudaGetSymbolAddress((void**)&base, g_buf);
    float* SCb  = base + OFF_SC;       // scale[256], shift[256]
    float* YTb  = base + OFF_YT;
    float* QKVb = base + OFF_QKV;
    float* QKTb = base + OFF_QKT;
    float* OTb  = base + OFF_OT;
    float* X2b  = base + OFF_X2;
    float* Y2Tb = base + OFF_Y2T;
    float* Hb   = base + OFF_H;
    float* Wqkv = base + OFF_WQKV;
    float* Bqkv = base + OFF_BQKV;
    float* scl = SCb, * shf = SCb + 256;

    // dynamic smem sizes
    const int SM_128_0 = (2 * 128 * 36 + 2 * 128 * 36) * 4;   // 73728
    const int SM_64_0  = (2 * 64 * 36 + 2 * 128 * 36) * 4;    // 55296
    const int SM_64_1  = (2 * 64 * 36 + 2 * 32 * 136) * 4;    // 53248
    cudaFuncSetAttribute(mma2_kernel<128,0,0,0>,
                         cudaFuncAttributeMaxDynamicSharedMemorySize, SM_128_0);
    cudaFuncSetAttribute(mma2_kernel<128,0,1,0>,
                         cudaFuncAttributeMaxDynamicSharedMemorySize, SM_128_0);
    cudaFuncSetAttribute(mma2_kernel<64,0,0,1>,
                         cudaFuncAttributeMaxDynamicSharedMemorySize, SM_64_0);
    cudaFuncSetAttribute(mma2_kernel<64,1,0,1>,
                         cudaFuncAttributeMaxDynamicSharedMemorySize, SM_64_1);

    // 0) weight concat
    pack_qkv_kernel<<<QKV_M, 256>>>(wq, wk, wv, bq, bk, bv, Wqkv, Bqkv);

    // 1) BN1 stats + fused apply-transpose -> YT [n][k]
    bn_stats_kernel<<<CDIM, 256>>>(x, g1, b1, scl, shf);
    bnt_apply_kernel<<<dim3(NPOS/32, CDIM/32, BATCH), 256>>>(x, scl, shf, YTb);

    // 2) fused QKV projection (cp.async mma tf32)
    mma2_kernel<128,0,0,0><<<dim3(NPOS/128, QKV_M/128, BATCH), 256, SM_128_0>>>(
        Wqkv, YTb, Bqkv, nullptr, QKVb, QKV_M, CDIM, NPOS);

    // 3) transpose QK rows -> QKt [n][512], attention (mma)
    transpose_b_kernel<<<dim3(NPOS/32, 512/32, BATCH), 256>>>(
        QKVb, QKTb, 512, NPOS, (size_t)QKV_M*NPOS, (size_t)512*NPOS);
    attn5_kernel<<<dim3(NPOS/64, NH, BATCH), 256>>>(QKVb, QKTb, OTb);

    // 4) projection (K=1024) + residual(x) -> X2
    mma2_kernel<64,0,0,1><<<dim3(NPOS/128, CDIM/64, BATCH), 256, SM_64_0>>>(
        wp, OTb, bp, x, X2b, CDIM, DH, NPOS);

    // 5) BN2 stats + fused apply-transpose -> Y2T
    bn_stats_kernel<<<CDIM, 256>>>(X2b, g2, b2, scl, shf);
    bnt_apply_kernel<<<dim3(NPOS/32, CDIM/32, BATCH), 256>>>(X2b, scl, shf, Y2Tb);

    // 6) MLP1 (tf32 + relu6) -> H [hid][n]
    mma2_kernel<128,0,1,0><<<dim3(NPOS/128, HID/128, BATCH), 256, SM_128_0>>>(
        w1, Y2Tb, bb1, nullptr, Hb, HID, CDIM, NPOS);

    // 7) MLP2 (B row-major H, K=1024) + residual(X2) -> out
    mma2_kernel<64,1,0,1><<<dim3(NPOS/128, CDIM/64, BATCH), 256, SM_64_1>>>(
        w2, Hb, bb2, X2b, out, CDIM, HID, NPOS);
}

// round 16
// speedup vs baseline: 6.8080x; 1.0765x over previous
#include <cuda_runtime.h>
#include <cstdint>

// ---------------------------------------------------------------------------
// Problem constants
// ---------------------------------------------------------------------------
#define BATCH 8
#define CDIM  256
#define NPOS  1024
#define NH    16
#define KDIM  16
#define DV    64
#define DH    (NH*DV)       // 1024
#define HID   1024
#define QKV_M 1536

// ---------------------------------------------------------------------------
// Scratch (device global). Offsets in floats.
// ---------------------------------------------------------------------------
#define OFF_SC    0u                        // scale/shift [2][256]
#define OFF_YT    (OFF_SC   + 1024u)        // [8,1024,256]   (n, k)
#define OFF_QKV   (OFF_YT   + 2097152u)     // [8,1536,1024]
#define OFF_QKT   (OFF_QKV  + 12582912u)    // [8,1024,512]   (n, qk-row)
#define OFF_OT    (OFF_QKT  + 4194304u)     // [8,1024,1024]  (n, dh)
#define OFF_X2    (OFF_OT   + 8388608u)     // [8,256,1024]
#define OFF_Y2T   (OFF_X2   + 2097152u)     // [8,1024,256]
#define OFF_H     (OFF_Y2T  + 2097152u)     // [8,1024,1024]  (hid, n)
#define OFF_WQKV  (OFF_H    + 8388608u)     // [1536,256]
#define OFF_BQKV  (OFF_WQKV + 393216u)      // [1536]
#define SCRATCH_FLOATS (OFF_BQKV + 1536u)

__device__ float g_buf[SCRATCH_FLOATS];

// ---------------------------------------------------------------------------
// helpers
// ---------------------------------------------------------------------------
__device__ __forceinline__ uint32_t smem_u32(const void* p) {
    uint32_t a;
    asm("{ .reg .u64 t; cvta.to.shared.u64 t, %1; cvt.u32.u64 %0, t; }"
        : "=r"(a) : "l"(p));
    return a;
}
__device__ __forceinline__ void mma_tf32(float* d, const uint32_t* a,
                                         const uint32_t* b) {
    asm volatile(
        "mma.sync.aligned.m16n8k8.row.col.f32.tf32.tf32.f32 "
        "{%0,%1,%2,%3}, {%4,%5,%6,%7}, {%8,%9}, {%0,%1,%2,%3};"
        : "+f"(d[0]), "+f"(d[1]), "+f"(d[2]), "+f"(d[3])
        : "r"(a[0]), "r"(a[1]), "r"(a[2]), "r"(a[3]), "r"(b[0]), "r"(b[1]));
}
#define CP_ASYNC16(dst, src) \
    asm volatile("cp.async.cg.shared.global [%0], [%1], 16;" \
                 :: "r"(dst), "l"(src) : "memory")
#define CP_COMMIT() asm volatile("cp.async.commit_group;" ::: "memory")
#define CP_WAIT0()  asm volatile("cp.async.wait_group 0;" ::: "memory")

// ---------------------------------------------------------------------------
// Concatenate wq/wk/wv (+biases) into one [1536,256] weight
// ---------------------------------------------------------------------------
__global__ void __launch_bounds__(256) pack_qkv_kernel(
    const float* __restrict__ wq, const float* __restrict__ wk,
    const float* __restrict__ wv, const float* __restrict__ bq,
    const float* __restrict__ bk, const float* __restrict__ bv,
    float* __restrict__ w, float* __restrict__ b)
{
    int row = blockIdx.x, c = threadIdx.x;
    const float* src; const float* bsrc; int r2;
    if (row < 256)      { src = wq; bsrc = bq; r2 = row; }
    else if (row < 512) { src = wk; bsrc = bk; r2 = row - 256; }
    else                { src = wv; bsrc = bv; r2 = row - 512; }
    w[(size_t)row * 256 + c] = src[(size_t)r2 * 256 + c];
    if (c == 0) b[row] = bsrc[r2];
}

// ---------------------------------------------------------------------------
// BN stats: per-channel scale/shift (train-mode stats over (B,N))
// ---------------------------------------------------------------------------
__global__ void __launch_bounds__(256) bn_stats_kernel(
    const float* __restrict__ x, const float* __restrict__ gamma,
    const float* __restrict__ beta, float* __restrict__ scale,
    float* __restrict__ shift)
{
    const int c = blockIdx.x, tid = threadIdx.x;
    __shared__ float sh[512];

    float s = 0.f, s2 = 0.f;
    for (int idx = tid; idx < BATCH * NPOS / 4; idx += 256) {
        int bb = idx >> 8, n4 = idx & 255;
        float4 v = *(const float4*)&x[((size_t)bb * CDIM + c) * NPOS + n4 * 4];
        s  += v.x + v.y + v.z + v.w;
        s2 += v.x*v.x + v.y*v.y + v.z*v.z + v.w*v.w;
    }
    sh[tid] = s; sh[256 + tid] = s2;
    __syncthreads();
    for (int off = 128; off; off >>= 1) {
        if (tid < off) { sh[tid] += sh[tid+off]; sh[256+tid] += sh[256+tid+off]; }
        __syncthreads();
    }
    if (tid == 0) {
        const float inv_n = 1.0f / (float)(BATCH * NPOS);
        float mean = sh[0] * inv_n;
        float var  = sh[256] * inv_n - mean * mean;
        float sc = gamma[c] * rsqrtf(var + 1e-5f);
        scale[c] = sc;
        shift[c] = beta[c] - mean * sc;
    }
}

// ---------------------------------------------------------------------------
// Fused BN-apply + transpose: x[b][c][n] -> yt[b][n][c]
// ---------------------------------------------------------------------------
__global__ void __launch_bounds__(256) bnt_apply_kernel(
    const float* __restrict__ x, const float* __restrict__ scale,
    const float* __restrict__ shift, float* __restrict__ yt)
{
    __shared__ float tile[32][33];
    const int b = blockIdx.z;
    const float* s = x + (size_t)b * CDIM * NPOS;
    float* d = yt + (size_t)b * NPOS * CDIM;
    const int n0 = blockIdx.x * 32, c0 = blockIdx.y * 32;
    const int tx = threadIdx.x & 31, ty0 = threadIdx.x >> 5;

    #pragma unroll
    for (int ty = ty0; ty < 32; ty += 8) {
        int c = c0 + ty;
        tile[ty][tx] = s[(size_t)c * NPOS + n0 + tx] * scale[c] + shift[c];
    }
    __syncthreads();
    #pragma unroll
    for (int ty = ty0; ty < 32; ty += 8)
        d[(size_t)(n0 + ty) * CDIM + c0 + tx] = tile[tx][ty];
}

// ---------------------------------------------------------------------------
// Plain batched 32x32 transpose with explicit strides (for QKT)
// ---------------------------------------------------------------------------
__global__ void __launch_bounds__(256) transpose_b_kernel(
    const float* __restrict__ src, float* __restrict__ dst,
    int R, int C, size_t sstr, size_t dstr)
{
    __shared__ float tile[32][33];
    const int b = blockIdx.z;
    const float* s = src + (size_t)b * sstr;
    float* d = dst + (size_t)b * dstr;
    const int c0 = blockIdx.x * 32, r0 = blockIdx.y * 32;
    const int tx = threadIdx.x & 31, ty0 = threadIdx.x >> 5;

    #pragma unroll
    for (int ty = ty0; ty < 32; ty += 8)
        tile[ty][tx] = s[(size_t)(r0 + ty) * C + c0 + tx];
    __syncthreads();
    #pragma unroll
    for (int ty = ty0; ty < 32; ty += 8)
        d[(size_t)(c0 + ty) * R + r0 + tx] = tile[tx][ty];
}

// ---------------------------------------------------------------------------
// mma2: cp.async double-buffered tf32 GEMM (R15-proven), BM=64 everywhere
// for occupancy (55/53 KB smem -> 3-4 CTAs/SM).
// ---------------------------------------------------------------------------
template<int BM, int BROW, int RELU6, int ADDRES>
__global__ void __launch_bounds__(256) mma2_kernel(
    const float* __restrict__ W, const float* __restrict__ B,
    const float* __restrict__ bias, const float* __restrict__ R,
    float* __restrict__ out, int M, int K, int NN)
{
    constexpr int MT   = BM / 32;
    constexpr int ASTR = BM * 36;
    constexpr int BSTR = BROW ? 32 * 136 : 128 * 36;
    extern __shared__ float dsm[];
    float* As = dsm;
    float* Bs = dsm + 2 * ASTR;

    const int tid  = threadIdx.x;
    const int w    = tid >> 5, lane = tid & 31;
    const int gid  = lane >> 2, t4 = lane & 3;
    const int n0   = blockIdx.x * 128, m0 = blockIdx.y * BM;
    const int wm   = (w & 1) * (BM / 2);
    const int wn   = (w >> 1) * 32;
    const float* Bb = B + (size_t)blockIdx.z * (size_t)NN * K;
    const size_t zO = (size_t)blockIdx.z * (size_t)M * NN;

    const uint32_t as_base = smem_u32(As);
    const uint32_t bs_base = smem_u32(Bs);
    const int lrow = tid >> 3, lq = tid & 7;
    const int kr = tid >> 5, nq = tid & 31;

    float d[MT][4][4];
    #pragma unroll
    for (int mt = 0; mt < MT; ++mt)
        #pragma unroll
        for (int nt = 0; nt < 4; ++nt)
            #pragma unroll
            for (int j = 0; j < 4; ++j) d[mt][nt][j] = 0.f;

    auto load_tile = [&](int buf, int kc) {
        #pragma unroll
        for (int p = 0; p < BM / 32; ++p) {
            int row = lrow + p * 32;
            uint32_t dst = as_base + (uint32_t)((buf * ASTR + row * 36 + lq * 4) * 4);
            CP_ASYNC16(dst, &W[(size_t)(m0 + row) * K + kc + lq * 4]);
        }
        if (BROW == 0) {
            #pragma unroll
            for (int p = 0; p < 4; ++p) {
                int row = lrow + p * 32;
                uint32_t dst = bs_base + (uint32_t)((buf * BSTR + row * 36 + lq * 4) * 4);
                CP_ASYNC16(dst, &Bb[(size_t)(n0 + row) * K + kc + lq * 4]);
            }
        } else {
            #pragma unroll
            for (int p = 0; p < 4; ++p) {
                int k = kr + p * 8;
                uint32_t dst = bs_base + (uint32_t)((buf * BSTR + k * 136 + nq * 4) * 4);
                CP_ASYNC16(dst, &Bb[(size_t)(kc + k) * NN + n0 + nq * 4]);
            }
        }
    };

    load_tile(0, 0);
    CP_COMMIT();
    CP_WAIT0();
    __syncthreads();

    const int ntiles = K >> 5;
    int buf = 0;
    for (int t = 0; t < ntiles; ++t) {
        if (t + 1 < ntiles) { load_tile(buf ^ 1, (t + 1) * 32); CP_COMMIT(); }

        const float* Ab = As + buf * ASTR;
        const float* Bc = Bs + buf * BSTR;
        #pragma unroll
        for (int k8 = 0; k8 < 4; ++k8) {
            const int kb = k8 * 8;
            uint32_t a[MT][4], b[4][2];
            #pragma unroll
            for (int mt = 0; mt < MT; ++mt) {
                int r1 = wm + mt * 16 + gid;
                a[mt][0] = __float_as_uint(Ab[r1 * 36 + kb + t4]);
                a[mt][1] = __float_as_uint(Ab[(r1 + 8) * 36 + kb + t4]);
                a[mt][2] = __float_as_uint(Ab[r1 * 36 + kb + t4 + 4]);
                a[mt][3] = __float_as_uint(Ab[(r1 + 8) * 36 + kb + t4 + 4]);
            }
            #pragma unroll
            for (int nt = 0; nt < 4; ++nt) {
                int rn = wn + nt * 8 + gid;
                if (BROW == 0) {
                    b[nt][0] = __float_as_uint(Bc[rn * 36 + kb + t4]);
                    b[nt][1] = __float_as_uint(Bc[rn * 36 + kb + t4 + 4]);
                } else {
                    b[nt][0] = __float_as_uint(Bc[(kb + t4) * 136 + rn]);
                    b[nt][1] = __float_as_uint(Bc[(kb + t4 + 4) * 136 + rn]);
                }
            }
            #pragma unroll
            for (int mt = 0; mt < MT; ++mt)
                #pragma unroll
                for (int nt = 0; nt < 4; ++nt)
                    mma_tf32(d[mt][nt], a[mt], b[nt]);
        }

        if (t + 1 < ntiles) CP_WAIT0();
        __syncthreads();
        buf ^= 1;
    }

    #pragma unroll
    for (int mt = 0; mt < MT; ++mt) {
        int m1 = m0 + wm + mt * 16 + gid;
        int m2 = m1 + 8;
        float bv1 = bias[m1], bv2 = bias[m2];
        #pragma unroll
        for (int nt = 0; nt < 4; ++nt) {
            int n = n0 + wn + nt * 8 + 2 * t4;
            float c0 = d[mt][nt][0] + bv1, c1 = d[mt][nt][1] + bv1;
            float c2 = d[mt][nt][2] + bv2, c3 = d[mt][nt][3] + bv2;
            if (RELU6) {
                c0 = fminf(fmaxf(c0, 0.f), 6.f); c1 = fminf(fmaxf(c1, 0.f), 6.f);
                c2 = fminf(fmaxf(c2, 0.f), 6.f); c3 = fminf(fmaxf(c3, 0.f), 6.f);
            }
            size_t o1 = zO + (size_t)m1 * NN + n;
            size_t o2 = zO + (size_t)m2 * NN + n;
            if (ADDRES) {
                float2 r1 = *(const float2*)&R[o1];
                float2 r2 = *(const float2*)&R[o2];
                c0 += r1.x; c1 += r1.y; c2 += r2.x; c3 += r2.y;
            }
            *(float2*)&out[o1] = make_float2(c0, c1);
            *(float2*)&out[o2] = make_float2(c2, c3);
        }
    }
}

// ---------------------------------------------------------------------------
// Fused attention v6: tf32 mma, cp.async double-buffered K/V tiles, no cvt
// (HW truncation to tf32, validated R15). Dynamic smem 68352 B -> 3 CTAs/SM.
// Layout (floats): Qs[64][20] @0, Ks[2][64][20] @1280, Vs[2][64][68] @3840,
// Ps[64][68] @12544, Rpart[8][16] @16896, Rinv[64] @17024. Total 17088.
// ---------------------------------------------------------------------------
#define AT6_SMEM_FLOATS 17088

__global__ void __launch_bounds__(256) attn6_kernel(
    const float* __restrict__ qkv, const float* __restrict__ qkt,
    float* __restrict__ ot)
{
    extern __shared__ float sm6[];
    float* Qs    = sm6;             // [64][20]
    float* Ks    = sm6 + 1280;      // [2][64][20]
    float* Vs    = sm6 + 3840;      // [2][64][68]
    float* Ps    = sm6 + 12544;     // [64][68]
    float* Rpart = sm6 + 16896;     // [8][16]
    float* Rinv  = sm6 + 17024;     // [64]

    const int tid  = threadIdx.x;
    const int w    = tid >> 5, lane = tid & 31;
    const int gid  = lane >> 2, t4 = lane & 3;
    const int wm   = (w & 3) * 16;
    const int wn   = (w >> 2) * 32;
    const int h    = blockIdx.y;
    const int r0   = blockIdx.x * 64;
    const int bz   = blockIdx.z;

    const float* qktb = qkt + (size_t)bz * NPOS * 512;
    const float* vh   = qkv + (size_t)(bz * QKV_M + 512 + h * DV) * NPOS;

    const uint32_t ks_base = smem_u32(Ks);
    const uint32_t vs_base = smem_u32(Vs);

    // Q tile [64][16], scale sqrt(kd)=4 folded (no cvt; HW truncates)
    {
        int r = tid >> 2, q4 = tid & 3;
        float4 q = *(const float4*)&qktb[(size_t)(r0 + r) * 512 + h * KDIM + q4 * 4];
        q.x *= 4.f; q.y *= 4.f; q.z *= 4.f; q.w *= 4.f;
        *(float4*)&Qs[r * 20 + q4 * 4] = q;
    }

    auto load_kv = [&](int buf, int m0) {
        {
            int m = tid >> 2, q4 = tid & 3;
            uint32_t dst = ks_base + (uint32_t)((buf * 1280 + m * 20 + q4 * 4) * 4);
            CP_ASYNC16(dst, &qktb[(size_t)(m0 + m) * 512 + 256 + h * KDIM + q4 * 4]);
        }
        #pragma unroll
        for (int p = 0; p < 4; ++p) {
            int idx = tid + p * 256;
            int dd = idx >> 4, mq = idx & 15;
            uint32_t dst = vs_base + (uint32_t)((buf * 4352 + dd * 68 + mq * 4) * 4);
            CP_ASYNC16(dst, &vh[(size_t)dd * NPOS + m0 + mq * 4]);
        }
    };

    float acc[4][4];
    #pragma unroll
    for (int nt = 0; nt < 4; ++nt)
        #pragma unroll
        for (int j = 0; j < 4; ++j) acc[nt][j] = 0.f;
    float rs_lo = 0.f, rs_hi = 0.f;

    load_kv(0, 0);
    CP_COMMIT();
    CP_WAIT0();
    __syncthreads();

    int buf = 0;
    for (int t = 0; t < 16; ++t) {
        if (t + 1 < 16) { load_kv(buf ^ 1, (t + 1) * 64); CP_COMMIT(); }

        const float* Kb = Ks + buf * 1280;
        const float* Vb = Vs + buf * 4352;

        // QK + exp + P store (raw fp32 bits; HMMA truncates to tf32)
        #pragma unroll
        for (int nt = 0; nt < 4; ++nt) {
            float s[4] = {0.f, 0.f, 0.f, 0.f};
            #pragma unroll
            for (int k8 = 0; k8 < 2; ++k8) {
                const int kb = k8 * 8;
                uint32_t a[4], b[2];
                a[0] = __float_as_uint(Qs[(wm + gid) * 20 + kb + t4]);
                a[1] = __float_as_uint(Qs[(wm + gid + 8) * 20 + kb + t4]);
                a[2] = __float_as_uint(Qs[(wm + gid) * 20 + kb + t4 + 4]);
                a[3] = __float_as_uint(Qs[(wm + gid + 8) * 20 + kb + t4 + 4]);
                int rn = wn + nt * 8 + gid;
                b[0] = __float_as_uint(Kb[rn * 20 + kb + t4]);
                b[1] = __float_as_uint(Kb[rn * 20 + kb + t4 + 4]);
                mma_tf32(s, a, b);
            }
            float e0 = __expf(s[0]), e1 = __expf(s[1]);
            float e2 = __expf(s[2]), e3 = __expf(s[3]);
            rs_lo += e0 + e1; rs_hi += e2 + e3;
            *(float2*)&Ps[(wm + gid) * 68 + wn + nt * 8 + 2 * t4] =
                make_float2(e0, e1);
            *(float2*)&Ps[(wm + gid + 8) * 68 + wn + nt * 8 + 2 * t4] =
                make_float2(e2, e3);
        }
        __syncthreads();

        // PV
        #pragma unroll
        for (int k8 = 0; k8 < 8; ++k8) {
            const int kb = k8 * 8;
            uint32_t a[4];
            a[0] = __float_as_uint(Ps[(wm + gid) * 68 + kb + t4]);
            a[1] = __float_as_uint(Ps[(wm + gid + 8) * 68 + kb + t4]);
            a[2] = __float_as_uint(Ps[(wm + gid) * 68 + kb + t4 + 4]);
            a[3] = __float_as_uint(Ps[(wm + gid + 8) * 68 + kb + t4 + 4]);
            #pragma unroll
            for (int nt = 0; nt < 4; ++nt) {
                uint32_t b[2];
                int rd = wn + nt * 8 + gid;
                b[0] = __float_as_uint(Vb[rd * 68 + kb + t4]);
                b[1] = __float_as_uint(Vb[rd * 68 + kb + t4 + 4]);
                mma_tf32(acc[nt], a, b);
            }
        }

        if (t + 1 < 16) CP_WAIT0();
        __syncthreads();
        buf ^= 1;
    }

    rs_lo += __shfl_xor_sync(0xffffffffu, rs_lo, 1);
    rs_lo += __shfl_xor_sync(0xffffffffu, rs_lo, 2);
    rs_hi += __shfl_xor_sync(0xffffffffu, rs_hi, 1);
    rs_hi += __shfl_xor_sync(0xffffffffu, rs_hi, 2);
    if (t4 == 0) {
        Rpart[w * 16 + gid] = rs_lo;
        Rpart[w * 16 + 8 + gid] = rs_hi;
    }
    __syncthreads();
    if (tid < 64) {
        int w1 = tid >> 4;
        Rinv[tid] = 1.0f / (Rpart[w1 * 16 + (tid & 15)] +
                            Rpart[(w1 + 4) * 16 + (tid & 15)]);
    }
    __syncthreads();

    const float i_lo = Rinv[wm + gid];
    const float i_hi = Rinv[wm + gid + 8];
    const size_t obase = (size_t)bz * NPOS * DH;
    #pragma unroll
    for (int nt = 0; nt < 4; ++nt) {
        int d = h * DV + wn + nt * 8 + 2 * t4;
        *(float2*)&ot[obase + (size_t)(r0 + wm + gid) * DH + d] =
            make_float2(acc[nt][0] * i_lo, acc[nt][1] * i_lo);
        *(float2*)&ot[obase + (size_t)(r0 + wm + gid + 8) * DH + d] =
            make_float2(acc[nt][2] * i_hi, acc[nt][3] * i_hi);
    }
}

// ---------------------------------------------------------------------------
// Launch
// ---------------------------------------------------------------------------
extern "C" void kernel_launch(void* const* d_in, const int* in_sizes, int n_in,
                              void* d_out, int out_size)
{
    (void)in_sizes; (void)n_in; (void)out_size;
    const float* x   = (const float*)d_in[0];
    const float* g1  = (const float*)d_in[1];
    const float* b1  = (const float*)d_in[2];
    const float* wq  = (const float*)d_in[3];
    const float* bq  = (const float*)d_in[4];
    const float* wk  = (const float*)d_in[5];
    const float* bk  = (const float*)d_in[6];
    const float* wv  = (const float*)d_in[7];
    const float* bv  = (const float*)d_in[8];
    const float* wp  = (const float*)d_in[9];
    const float* bp  = (const float*)d_in[10];
    const float* g2  = (const float*)d_in[11];
    const float* b2  = (const float*)d_in[12];
    const float* w1  = (const float*)d_in[13];
    const float* bb1 = (const float*)d_in[14];
    const float* w2  = (const float*)d_in[15];
    const float* bb2 = (const float*)d_in[16];
    float* out = (float*)d_out;

    float* base = nullptr;
    cudaGetSymbolAddress((void**)&base, g_buf);
    float* SCb  = base + OFF_SC;
    float* YTb  = base + OFF_YT;
    float* QKVb = base + OFF_QKV;
    float* QKTb = base + OFF_QKT;
    float* OTb  = base + OFF_OT;
    float* X2b  = base + OFF_X2;
    float* Y2Tb = base + OFF_Y2T;
    float* Hb   = base + OFF_H;
    float* Wqkv = base + OFF_WQKV;
    float* Bqkv = base + OFF_BQKV;
    float* scl = SCb, * shf = SCb + 256;

    const int SM_64_0 = (2 * 64 * 36 + 2 * 128 * 36) * 4;    // 55296
    const int SM_64_1 = (2 * 64 * 36 + 2 * 32 * 136) * 4;    // 53248
    const int SM_AT6  = AT6_SMEM_FLOATS * 4;                 // 68352
    cudaFuncSetAttribute(mma2_kernel<64,0,0,0>,
                         cudaFuncAttributeMaxDynamicSharedMemorySize, SM_64_0);
    cudaFuncSetAttribute(mma2_kernel<64,0,1,0>,
                         cudaFuncAttributeMaxDynamicSharedMemorySize, SM_64_0);
    cudaFuncSetAttribute(mma2_kernel<64,0,0,1>,
                         cudaFuncAttributeMaxDynamicSharedMemorySize, SM_64_0);
    cudaFuncSetAttribute(mma2_kernel<64,1,0,1>,
                         cudaFuncAttributeMaxDynamicSharedMemorySize, SM_64_1);
    cudaFuncSetAttribute(attn6_kernel,
                         cudaFuncAttributeMaxDynamicSharedMemorySize, SM_AT6);

    // 0) weight concat
    pack_qkv_kernel<<<QKV_M, 256>>>(wq, wk, wv, bq, bk, bv, Wqkv, Bqkv);

    // 1) BN1 stats + fused apply-transpose -> YT [n][k]
    bn_stats_kernel<<<CDIM, 256>>>(x, g1, b1, scl, shf);
    bnt_apply_kernel<<<dim3(NPOS/32, CDIM/32, BATCH), 256>>>(x, scl, shf, YTb);

    // 2) fused QKV projection
    mma2_kernel<64,0,0,0><<<dim3(NPOS/128, QKV_M/64, BATCH), 256, SM_64_0>>>(
        Wqkv, YTb, Bqkv, nullptr, QKVb, QKV_M, CDIM, NPOS);

    // 3) transpose QK rows -> QKt [n][512], attention
    transpose_b_kernel<<<dim3(NPOS/32, 512/32, BATCH), 256>>>(
        QKVb, QKTb, 512, NPOS, (size_t)QKV_M*NPOS, (size_t)512*NPOS);
    attn6_kernel<<<dim3(NPOS/64, NH, BATCH), 256, SM_AT6>>>(QKVb, QKTb, OTb);

    // 4) projection (K=1024) + residual(x) -> X2
    mma2_kernel<64,0,0,1><<<dim3(NPOS/128, CDIM/64, BATCH), 256, SM_64_0>>>(
        wp, OTb, bp, x, X2b, CDIM, DH, NPOS);

    // 5) BN2 stats + fused apply-transpose -> Y2T
    bn_stats_kernel<<<CDIM, 256>>>(X2b, g2, b2, scl, shf);
    bnt_apply_kernel<<<dim3(NPOS/32, CDIM/32, BATCH), 256>>>(X2b, scl, shf, Y2Tb);

    // 6) MLP1 (tf32 + relu6) -> H [hid][n]
    mma2_kernel<64,0,1,0><<<dim3(NPOS/128, HID/64, BATCH), 256, SM_64_0>>>(
        w1, Y2Tb, bb1, nullptr, Hb, HID, CDIM, NPOS);

    // 7) MLP2 (B row-major H, K=1024) + residual(X2) -> out
    mma2_kernel<64,1,0,1><<<dim3(NPOS/128, CDIM/64, BATCH), 256, SM_64_1>>>(
        w2, Hb, bb2, X2b, out, CDIM, HID, NPOS);
}

// round 17
// speedup vs baseline: 6.9074x; 1.0146x over previous
#include <cuda_runtime.h>
#include <cstdint>

// ---------------------------------------------------------------------------
// Problem constants
// ---------------------------------------------------------------------------
#define BATCH 8
#define CDIM  256
#define NPOS  1024
#define NH    16
#define KDIM  16
#define DV    64
#define DH    (NH*DV)       // 1024
#define HID   1024
#define QKV_M 1536

// ---------------------------------------------------------------------------
// Scratch (device global). Offsets in floats.
// ---------------------------------------------------------------------------
#define OFF_SC    0u                        // scale/shift [2][256]
#define OFF_QKV   (OFF_SC   + 1024u)        // [8,1536,1024]
#define OFF_QKT   (OFF_QKV  + 12582912u)    // [8,1024,512]   (n, qk-row)
#define OFF_OT    (OFF_QKT  + 4194304u)     // [8,1024,1024]  (n, dh)
#define OFF_X2    (OFF_OT   + 8388608u)     // [8,256,1024]
#define OFF_H     (OFF_X2   + 2097152u)     // [8,1024,1024]  (hid, n)
#define OFF_WQKV  (OFF_H    + 8388608u)     // [1536,256]
#define OFF_BQKV  (OFF_WQKV + 393216u)      // [1536]
#define SCRATCH_FLOATS (OFF_BQKV + 1536u)

__device__ float g_buf[SCRATCH_FLOATS];

// ---------------------------------------------------------------------------
// helpers
// ---------------------------------------------------------------------------
__device__ __forceinline__ uint32_t smem_u32(const void* p) {
    uint32_t a;
    asm("{ .reg .u64 t; cvta.to.shared.u64 t, %1; cvt.u32.u64 %0, t; }"
        : "=r"(a) : "l"(p));
    return a;
}
__device__ __forceinline__ void mma_tf32(float* d, const uint32_t* a,
                                         const uint32_t* b) {
    asm volatile(
        "mma.sync.aligned.m16n8k8.row.col.f32.tf32.tf32.f32 "
        "{%0,%1,%2,%3}, {%4,%5,%6,%7}, {%8,%9}, {%0,%1,%2,%3};"
        : "+f"(d[0]), "+f"(d[1]), "+f"(d[2]), "+f"(d[3])
        : "r"(a[0]), "r"(a[1]), "r"(a[2]), "r"(a[3]), "r"(b[0]), "r"(b[1]));
}
#define CP_ASYNC16(dst, src) \
    asm volatile("cp.async.cg.shared.global [%0], [%1], 16;" \
                 :: "r"(dst), "l"(src) : "memory")
#define CP_COMMIT() asm volatile("cp.async.commit_group;" ::: "memory")
#define CP_WAIT0()  asm volatile("cp.async.wait_group 0;" ::: "memory")

// ---------------------------------------------------------------------------
// Concatenate wq/wk/wv (+biases) into one [1536,256] weight
// ---------------------------------------------------------------------------
__global__ void __launch_bounds__(256) pack_qkv_kernel(
    const float* __restrict__ wq, const float* __restrict__ wk,
    const float* __restrict__ wv, const float* __restrict__ bq,
    const float* __restrict__ bk, const float* __restrict__ bv,
    float* __restrict__ w, float* __restrict__ b)
{
    int row = blockIdx.x, c = threadIdx.x;
    const float* src; const float* bsrc; int r2;
    if (row < 256)      { src = wq; bsrc = bq; r2 = row; }
    else if (row < 512) { src = wk; bsrc = bk; r2 = row - 256; }
    else                { src = wv; bsrc = bv; r2 = row - 512; }
    w[(size_t)row * 256 + c] = src[(size_t)r2 * 256 + c];
    if (c == 0) b[row] = bsrc[r2];
}

// ---------------------------------------------------------------------------
// BN stats: per-channel scale/shift (train-mode stats over (B,N))
// ---------------------------------------------------------------------------
__global__ void __launch_bounds__(256) bn_stats_kernel(
    const float* __restrict__ x, const float* __restrict__ gamma,
    const float* __restrict__ beta, float* __restrict__ scale,
    float* __restrict__ shift)
{
    const int c = blockIdx.x, tid = threadIdx.x;
    __shared__ float sh[512];

    float s = 0.f, s2 = 0.f;
    for (int idx = tid; idx < BATCH * NPOS / 4; idx += 256) {
        int bb = idx >> 8, n4 = idx & 255;
        float4 v = *(const float4*)&x[((size_t)bb * CDIM + c) * NPOS + n4 * 4];
        s  += v.x + v.y + v.z + v.w;
        s2 += v.x*v.x + v.y*v.y + v.z*v.z + v.w*v.w;
    }
    sh[tid] = s; sh[256 + tid] = s2;
    __syncthreads();
    for (int off = 128; off; off >>= 1) {
        if (tid < off) { sh[tid] += sh[tid+off]; sh[256+tid] += sh[256+tid+off]; }
        __syncthreads();
    }
    if (tid == 0) {
        const float inv_n = 1.0f / (float)(BATCH * NPOS);
        float mean = sh[0] * inv_n;
        float var  = sh[256] * inv_n - mean * mean;
        float sc = gamma[c] * rsqrtf(var + 1e-5f);
        scale[c] = sc;
        shift[c] = beta[c] - mean * sc;
    }
}

// ---------------------------------------------------------------------------
// Plain batched 32x32 transpose with explicit strides (for QKT)
// ---------------------------------------------------------------------------
__global__ void __launch_bounds__(256) transpose_b_kernel(
    const float* __restrict__ src, float* __restrict__ dst,
    int R, int C, size_t sstr, size_t dstr)
{
    __shared__ float tile[32][33];
    const int b = blockIdx.z;
    const float* s = src + (size_t)b * sstr;
    float* d = dst + (size_t)b * dstr;
    const int c0 = blockIdx.x * 32, r0 = blockIdx.y * 32;
    const int tx = threadIdx.x & 31, ty0 = threadIdx.x >> 5;

    #pragma unroll
    for (int ty = ty0; ty < 32; ty += 8)
        tile[ty][tx] = s[(size_t)(r0 + ty) * C + c0 + tx];
    __syncthreads();
    #pragma unroll
    for (int ty = ty0; ty < 32; ty += 8)
        d[(size_t)(c0 + ty) * R + r0 + tx] = tile[tx][ty];
}

// ---------------------------------------------------------------------------
// mma2: cp.async double-buffered tf32 GEMM, BM=64.
// out[z][m][n] = act(sum_k W[m][k] * B(k,n) + bias[m]) (+R)
// BROW=0: B = Bt[NN][K]. BROW=1: B = [K][NN] row-major.
// BNSCALE (BROW=1 only): B element (k,n) -> B*scale[k]+shift[k] applied at
// fragment load (fuses BatchNorm-apply into the GEMM; scale/shift staged in
// a small per-tile smem array inside load_tile).
// Dynamic smem: As[2][BM*36], Bs[2][BSTR], Ssc[2*32], Ssh[2*32].
// ---------------------------------------------------------------------------
template<int BM, int BROW, int BNSCALE, int RELU6, int ADDRES>
__global__ void __launch_bounds__(256) mma2_kernel(
    const float* __restrict__ W, const float* __restrict__ B,
    const float* __restrict__ bias, const float* __restrict__ R,
    const float* __restrict__ scl, const float* __restrict__ shf,
    float* __restrict__ out, int M, int K, int NN)
{
    constexpr int MT   = BM / 32;
    constexpr int ASTR = BM * 36;
    constexpr int BSTR = BROW ? 32 * 136 : 128 * 36;
    extern __shared__ float dsm[];
    float* As  = dsm;
    float* Bs  = dsm + 2 * ASTR;
    float* Ssc = dsm + 2 * ASTR + 2 * BSTR;       // [2][32]
    float* Ssh = Ssc + 64;                        // [2][32]

    const int tid  = threadIdx.x;
    const int w    = tid >> 5, lane = tid & 31;
    const int gid  = lane >> 2, t4 = lane & 3;
    const int n0   = blockIdx.x * 128, m0 = blockIdx.y * BM;
    const int wm   = (w & 1) * (BM / 2);
    const int wn   = (w >> 1) * 32;
    const float* Bb = B + (size_t)blockIdx.z * (size_t)NN * K;
    const size_t zO = (size_t)blockIdx.z * (size_t)M * NN;

    const uint32_t as_base = smem_u32(As);
    const uint32_t bs_base = smem_u32(Bs);
    const int lrow = tid >> 3, lq = tid & 7;
    const int kr = tid >> 5, nq = tid & 31;

    float d[MT][4][4];
    #pragma unroll
    for (int mt = 0; mt < MT; ++mt)
        #pragma unroll
        for (int nt = 0; nt < 4; ++nt)
            #pragma unroll
            for (int j = 0; j < 4; ++j) d[mt][nt][j] = 0.f;

    auto load_tile = [&](int buf, int kc) {
        #pragma unroll
        for (int p = 0; p < BM / 32; ++p) {
            int row = lrow + p * 32;
            uint32_t dst = as_base + (uint32_t)((buf * ASTR + row * 36 + lq * 4) * 4);
            CP_ASYNC16(dst, &W[(size_t)(m0 + row) * K + kc + lq * 4]);
        }
        if (BROW == 0) {
            #pragma unroll
            for (int p = 0; p < 4; ++p) {
                int row = lrow + p * 32;
                uint32_t dst = bs_base + (uint32_t)((buf * BSTR + row * 36 + lq * 4) * 4);
                CP_ASYNC16(dst, &Bb[(size_t)(n0 + row) * K + kc + lq * 4]);
            }
        } else {
            #pragma unroll
            for (int p = 0; p < 4; ++p) {
                int k = kr + p * 8;
                uint32_t dst = bs_base + (uint32_t)((buf * BSTR + k * 136 + nq * 4) * 4);
                CP_ASYNC16(dst, &Bb[(size_t)(kc + k) * NN + n0 + nq * 4]);
            }
            if (BNSCALE) {
                if (tid < 32)       Ssc[buf * 32 + tid] = scl[kc + tid];
                else if (tid < 64)  Ssh[buf * 32 + tid - 32] = shf[kc + tid - 32];
            }
        }
    };

    load_tile(0, 0);
    CP_COMMIT();
    CP_WAIT0();
    __syncthreads();

    const int ntiles = K >> 5;
    int buf = 0;
    for (int t = 0; t < ntiles; ++t) {
        if (t + 1 < ntiles) { load_tile(buf ^ 1, (t + 1) * 32); CP_COMMIT(); }

        const float* Ab = As + buf * ASTR;
        const float* Bc = Bs + buf * BSTR;
        #pragma unroll
        for (int k8 = 0; k8 < 4; ++k8) {
            const int kb = k8 * 8;
            uint32_t a[MT][4], b[4][2];
            #pragma unroll
            for (int mt = 0; mt < MT; ++mt) {
                int r1 = wm + mt * 16 + gid;
                a[mt][0] = __float_as_uint(Ab[r1 * 36 + kb + t4]);
                a[mt][1] = __float_as_uint(Ab[(r1 + 8) * 36 + kb + t4]);
                a[mt][2] = __float_as_uint(Ab[r1 * 36 + kb + t4 + 4]);
                a[mt][3] = __float_as_uint(Ab[(r1 + 8) * 36 + kb + t4 + 4]);
            }
            float s0, f0, s1, f1;
            if (BROW == 1 && BNSCALE) {
                s0 = Ssc[buf * 32 + kb + t4];     f0 = Ssh[buf * 32 + kb + t4];
                s1 = Ssc[buf * 32 + kb + t4 + 4]; f1 = Ssh[buf * 32 + kb + t4 + 4];
            }
            #pragma unroll
            for (int nt = 0; nt < 4; ++nt) {
                int rn = wn + nt * 8 + gid;
                if (BROW == 0) {
                    b[nt][0] = __float_as_uint(Bc[rn * 36 + kb + t4]);
                    b[nt][1] = __float_as_uint(Bc[rn * 36 + kb + t4 + 4]);
                } else {
                    float v0 = Bc[(kb + t4) * 136 + rn];
                    float v1 = Bc[(kb + t4 + 4) * 136 + rn];
                    if (BNSCALE) { v0 = fmaf(v0, s0, f0); v1 = fmaf(v1, s1, f1); }
                    b[nt][0] = __float_as_uint(v0);
                    b[nt][1] = __float_as_uint(v1);
                }
            }
            #pragma unroll
            for (int mt = 0; mt < MT; ++mt)
                #pragma unroll
                for (int nt = 0; nt < 4; ++nt)
                    mma_tf32(d[mt][nt], a[mt], b[nt]);
        }

        if (t + 1 < ntiles) CP_WAIT0();
        __syncthreads();
        buf ^= 1;
    }

    #pragma unroll
    for (int mt = 0; mt < MT; ++mt) {
        int m1 = m0 + wm + mt * 16 + gid;
        int m2 = m1 + 8;
        float bv1 = bias[m1], bv2 = bias[m2];
        #pragma unroll
        for (int nt = 0; nt < 4; ++nt) {
            int n = n0 + wn + nt * 8 + 2 * t4;
            float c0 = d[mt][nt][0] + bv1, c1 = d[mt][nt][1] + bv1;
            float c2 = d[mt][nt][2] + bv2, c3 = d[mt][nt][3] + bv2;
            if (RELU6) {
                c0 = fminf(fmaxf(c0, 0.f), 6.f); c1 = fminf(fmaxf(c1, 0.f), 6.f);
                c2 = fminf(fmaxf(c2, 0.f), 6.f); c3 = fminf(fmaxf(c3, 0.f), 6.f);
            }
            size_t o1 = zO + (size_t)m1 * NN + n;
            size_t o2 = zO + (size_t)m2 * NN + n;
            if (ADDRES) {
                float2 r1 = *(const float2*)&R[o1];
                float2 r2 = *(const float2*)&R[o2];
                c0 += r1.x; c1 += r1.y; c2 += r2.x; c3 += r2.y;
            }
            *(float2*)&out[o1] = make_float2(c0, c1);
            *(float2*)&out[o2] = make_float2(c2, c3);
        }
    }
}

// ---------------------------------------------------------------------------
// Fused attention v6 (R16-proven): tf32 mma, cp.async double-buffered K/V.
// ---------------------------------------------------------------------------
#define AT6_SMEM_FLOATS 17088

__global__ void __launch_bounds__(256) attn6_kernel(
    const float* __restrict__ qkv, const float* __restrict__ qkt,
    float* __restrict__ ot)
{
    extern __shared__ float sm6[];
    float* Qs    = sm6;             // [64][20]
    float* Ks    = sm6 + 1280;      // [2][64][20]
    float* Vs    = sm6 + 3840;      // [2][64][68]
    float* Ps    = sm6 + 12544;     // [64][68]
    float* Rpart = sm6 + 16896;     // [8][16]
    float* Rinv  = sm6 + 17024;     // [64]

    const int tid  = threadIdx.x;
    const int w    = tid >> 5, lane = tid & 31;
    const int gid  = lane >> 2, t4 = lane & 3;
    const int wm   = (w & 3) * 16;
    const int wn   = (w >> 2) * 32;
    const int h    = blockIdx.y;
    const int r0   = blockIdx.x * 64;
    const int bz   = blockIdx.z;

    const float* qktb = qkt + (size_t)bz * NPOS * 512;
    const float* vh   = qkv + (size_t)(bz * QKV_M + 512 + h * DV) * NPOS;

    const uint32_t ks_base = smem_u32(Ks);
    const uint32_t vs_base = smem_u32(Vs);

    {
        int r = tid >> 2, q4 = tid & 3;
        float4 q = *(const float4*)&qktb[(size_t)(r0 + r) * 512 + h * KDIM + q4 * 4];
        q.x *= 4.f; q.y *= 4.f; q.z *= 4.f; q.w *= 4.f;
        *(float4*)&Qs[r * 20 + q4 * 4] = q;
    }

    auto load_kv = [&](int buf, int m0) {
        {
            int m = tid >> 2, q4 = tid & 3;
            uint32_t dst = ks_base + (uint32_t)((buf * 1280 + m * 20 + q4 * 4) * 4);
            CP_ASYNC16(dst, &qktb[(size_t)(m0 + m) * 512 + 256 + h * KDIM + q4 * 4]);
        }
        #pragma unroll
        for (int p = 0; p < 4; ++p) {
            int idx = tid + p * 256;
            int dd = idx >> 4, mq = idx & 15;
            uint32_t dst = vs_base + (uint32_t)((buf * 4352 + dd * 68 + mq * 4) * 4);
            CP_ASYNC16(dst, &vh[(size_t)dd * NPOS + m0 + mq * 4]);
        }
    };

    float acc[4][4];
    #pragma unroll
    for (int nt = 0; nt < 4; ++nt)
        #pragma unroll
        for (int j = 0; j < 4; ++j) acc[nt][j] = 0.f;
    float rs_lo = 0.f, rs_hi = 0.f;

    load_kv(0, 0);
    CP_COMMIT();
    CP_WAIT0();
    __syncthreads();

    int buf = 0;
    for (int t = 0; t < 16; ++t) {
        if (t + 1 < 16) { load_kv(buf ^ 1, (t + 1) * 64); CP_COMMIT(); }

        const float* Kb = Ks + buf * 1280;
        const float* Vb = Vs + buf * 4352;

        #pragma unroll
        for (int nt = 0; nt < 4; ++nt) {
            float s[4] = {0.f, 0.f, 0.f, 0.f};
            #pragma unroll
            for (int k8 = 0; k8 < 2; ++k8) {
                const int kb = k8 * 8;
                uint32_t a[4], b[2];
                a[0] = __float_as_uint(Qs[(wm + gid) * 20 + kb + t4]);
                a[1] = __float_as_uint(Qs[(wm + gid + 8) * 20 + kb + t4]);
                a[2] = __float_as_uint(Qs[(wm + gid) * 20 + kb + t4 + 4]);
                a[3] = __float_as_uint(Qs[(wm + gid + 8) * 20 + kb + t4 + 4]);
                int rn = wn + nt * 8 + gid;
                b[0] = __float_as_uint(Kb[rn * 20 + kb + t4]);
                b[1] = __float_as_uint(Kb[rn * 20 + kb + t4 + 4]);
                mma_tf32(s, a, b);
            }
            float e0 = __expf(s[0]), e1 = __expf(s[1]);
            float e2 = __expf(s[2]), e3 = __expf(s[3]);
            rs_lo += e0 + e1; rs_hi += e2 + e3;
            *(float2*)&Ps[(wm + gid) * 68 + wn + nt * 8 + 2 * t4] =
                make_float2(e0, e1);
            *(float2*)&Ps[(wm + gid + 8) * 68 + wn + nt * 8 + 2 * t4] =
                make_float2(e2, e3);
        }
        __syncthreads();

        #pragma unroll
        for (int k8 = 0; k8 < 8; ++k8) {
            const int kb = k8 * 8;
            uint32_t a[4];
            a[0] = __float_as_uint(Ps[(wm + gid) * 68 + kb + t4]);
            a[1] = __float_as_uint(Ps[(wm + gid + 8) * 68 + kb + t4]);
            a[2] = __float_as_uint(Ps[(wm + gid) * 68 + kb + t4 + 4]);
            a[3] = __float_as_uint(Ps[(wm + gid + 8) * 68 + kb + t4 + 4]);
            #pragma unroll
            for (int nt = 0; nt < 4; ++nt) {
                uint32_t b[2];
                int rd = wn + nt * 8 + gid;
                b[0] = __float_as_uint(Vb[rd * 68 + kb + t4]);
                b[1] = __float_as_uint(Vb[rd * 68 + kb + t4 + 4]);
                mma_tf32(acc[nt], a, b);
            }
        }

        if (t + 1 < 16) CP_WAIT0();
        __syncthreads();
        buf ^= 1;
    }

    rs_lo += __shfl_xor_sync(0xffffffffu, rs_lo, 1);
    rs_lo += __shfl_xor_sync(0xffffffffu, rs_lo, 2);
    rs_hi += __shfl_xor_sync(0xffffffffu, rs_hi, 1);
    rs_hi += __shfl_xor_sync(0xffffffffu, rs_hi, 2);
    if (t4 == 0) {
        Rpart[w * 16 + gid] = rs_lo;
        Rpart[w * 16 + 8 + gid] = rs_hi;
    }
    __syncthreads();
    if (tid < 64) {
        int w1 = tid >> 4;
        Rinv[tid] = 1.0f / (Rpart[w1 * 16 + (tid & 15)] +
                            Rpart[(w1 + 4) * 16 + (tid & 15)]);
    }
    __syncthreads();

    const float i_lo = Rinv[wm + gid];
    const float i_hi = Rinv[wm + gid + 8];
    const size_t obase = (size_t)bz * NPOS * DH;
    #pragma unroll
    for (int nt = 0; nt < 4; ++nt) {
        int d = h * DV + wn + nt * 8 + 2 * t4;
        *(float2*)&ot[obase + (size_t)(r0 + wm + gid) * DH + d] =
            make_float2(acc[nt][0] * i_lo, acc[nt][1] * i_lo);
        *(float2*)&ot[obase + (size_t)(r0 + wm + gid + 8) * DH + d] =
            make_float2(acc[nt][2] * i_hi, acc[nt][3] * i_hi);
    }
}

// ---------------------------------------------------------------------------
// Launch
// ---------------------------------------------------------------------------
extern "C" void kernel_launch(void* const* d_in, const int* in_sizes, int n_in,
                              void* d_out, int out_size)
{
    (void)in_sizes; (void)n_in; (void)out_size;
    const float* x   = (const float*)d_in[0];
    const float* g1  = (const float*)d_in[1];
    const float* b1  = (const float*)d_in[2];
    const float* wq  = (const float*)d_in[3];
    const float* bq  = (const float*)d_in[4];
    const float* wk  = (const float*)d_in[5];
    const float* bk  = (const float*)d_in[6];
    const float* wv  = (const float*)d_in[7];
    const float* bv  = (const float*)d_in[8];
    const float* wp  = (const float*)d_in[9];
    const float* bp  = (const float*)d_in[10];
    const float* g2  = (const float*)d_in[11];
    const float* b2  = (const float*)d_in[12];
    const float* w1  = (const float*)d_in[13];
    const float* bb1 = (const float*)d_in[14];
    const float* w2  = (const float*)d_in[15];
    const float* bb2 = (const float*)d_in[16];
    float* out = (float*)d_out;

    float* base = nullptr;
    cudaGetSymbolAddress((void**)&base, g_buf);
    float* SCb  = base + OFF_SC;
    float* QKVb = base + OFF_QKV;
    float* QKTb = base + OFF_QKT;
    float* OTb  = base + OFF_OT;
    float* X2b  = base + OFF_X2;
    float* Hb   = base + OFF_H;
    float* Wqkv = base + OFF_WQKV;
    float* Bqkv = base + OFF_BQKV;
    float* scl = SCb, * shf = SCb + 256;

    // dynamic smem sizes (As + Bs + scale/shift stage)
    const int SM_B0 = (2 * 64 * 36 + 2 * 128 * 36 + 128) * 4;   // 55808
    const int SM_B1 = (2 * 64 * 36 + 2 * 32 * 136 + 128) * 4;   // 53760
    const int SM_AT6 = AT6_SMEM_FLOATS * 4;                     // 68352
    cudaFuncSetAttribute((const void*)mma2_kernel<64,1,1,0,0>,
                         cudaFuncAttributeMaxDynamicSharedMemorySize, SM_B1);
    cudaFuncSetAttribute((const void*)mma2_kernel<64,1,1,1,0>,
                         cudaFuncAttributeMaxDynamicSharedMemorySize, SM_B1);
    cudaFuncSetAttribute((const void*)mma2_kernel<64,0,0,0,1>,
                         cudaFuncAttributeMaxDynamicSharedMemorySize, SM_B0);
    cudaFuncSetAttribute((const void*)mma2_kernel<64,1,0,0,1>,
                         cudaFuncAttributeMaxDynamicSharedMemorySize, SM_B1);
    cudaFuncSetAttribute((const void*)attn6_kernel,
                         cudaFuncAttributeMaxDynamicSharedMemorySize, SM_AT6);

    // 0) weight concat
    pack_qkv_kernel<<<QKV_M, 256>>>(wq, wk, wv, bq, bk, bv, Wqkv, Bqkv);

    // 1) BN1 stats
    bn_stats_kernel<<<CDIM, 256>>>(x, g1, b1, scl, shf);

    // 2) fused QKV projection; B = x [c][n] with BN1 applied at fragment load
    mma2_kernel<64,1,1,0,0><<<dim3(NPOS/128, QKV_M/64, BATCH), 256, SM_B1>>>(
        Wqkv, x, Bqkv, nullptr, scl, shf, QKVb, QKV_M, CDIM, NPOS);

    // 3) transpose QK rows -> QKt [n][512], attention
    transpose_b_kernel<<<dim3(NPOS/32, 512/32, BATCH), 256>>>(
        QKVb, QKTb, 512, NPOS, (size_t)QKV_M*NPOS, (size_t)512*NPOS);
    attn6_kernel<<<dim3(NPOS/64, NH, BATCH), 256, SM_AT6>>>(QKVb, QKTb, OTb);

    // 4) projection (K=1024) + residual(x) -> X2
    mma2_kernel<64,0,0,0,1><<<dim3(NPOS/128, CDIM/64, BATCH), 256, SM_B0>>>(
        wp, OTb, bp, x, nullptr, nullptr, X2b, CDIM, DH, NPOS);

    // 5) BN2 stats
    bn_stats_kernel<<<CDIM, 256>>>(X2b, g2, b2, scl, shf);

    // 6) MLP1 (tf32 + relu6); B = X2 [c][n] with BN2 applied at fragment load
    mma2_kernel<64,1,1,1,0><<<dim3(NPOS/128, HID/64, BATCH), 256, SM_B1>>>(
        w1, X2b, bb1, nullptr, scl, shf, Hb, HID, CDIM, NPOS);

    // 7) MLP2 (B row-major H, K=1024) + residual(X2) -> out
    mma2_kernel<64,1,0,0,1><<<dim3(NPOS/128, CDIM/64, BATCH), 256, SM_B1>>>(
        w2, Hb, bb2, X2b, nullptr, nullptr, out, CDIM, HID, NPOS);
}